// round 9
// baseline (speedup 1.0000x reference)
#include <cuda_runtime.h>
#include <cuda_bf16.h>
#include <math.h>
#include <stdint.h>

// ---------------------------------------------------------------------------
// Problem constants
// ---------------------------------------------------------------------------
#define BATCH      8
#define T_FRAMES   2048
#define M_TOTAL    (BATCH * T_FRAMES)   // 16384 frames
#define K_DIM      512
#define N_DIM      1026                 // N_FFT + 2
#define N_PAD      1152                 // 9 * 128
#define NBINS      513                  // N_FFT/2 + 1
#define NFFT       1024
#define HOP        256
#define PAD        384                  // (1024-256)/2
#define OUT_FULL   ((T_FRAMES - 1) * HOP + NFFT)  // 525312
#define OUT_LEN    (OUT_FULL - 2 * PAD)           // 524544

// fused ifft+ola chunking
#define OWN_FRAMES 13                   // frames owned per CTA
#define CMP_FRAMES 16                   // computed = owned + 3 halo
#define OWN_SAMP   (OWN_FRAMES * HOP)   // 3328 samples per CTA
#define N_CHUNKS   158                  // ceil(2048/13); covers all output

// ---------------------------------------------------------------------------
// Scratch (device globals: no runtime allocation allowed)
// ---------------------------------------------------------------------------
__device__ float g_h[(size_t)M_TOTAL * N_DIM];        // linear head output (~67 MB)
__device__ __nv_bfloat16 g_xhi[(size_t)M_TOTAL * K_DIM];
__device__ __nv_bfloat16 g_xlo[(size_t)M_TOTAL * K_DIM];
__device__ __nv_bfloat16 g_wthi[(size_t)N_PAD * K_DIM];
__device__ __nv_bfloat16 g_wtlo[(size_t)N_PAD * K_DIM];
// precomputed tables
__device__ float2 g_tw[512];        // e^{+2*pi*i*j/512},  j<512
__device__ float2 g_pretw[512];     // e^{+2*pi*i*k/1024}, k<512  (packing twiddles)
__device__ float  g_win[NFFT];      // hann window
__device__ float  g_env_inv[OUT_FULL];  // 1 / sum win^2

// ---------------------------------------------------------------------------
// baseline-arch PTX helpers (supported on compute_103 WITHOUT 'a')
// ---------------------------------------------------------------------------
__device__ __forceinline__ uint32_t smem_u32(const void* p) {
    return (uint32_t)__cvta_generic_to_shared(p);
}

__device__ __forceinline__ void cp_async16(uint32_t saddr, const void* gptr) {
    asm volatile("cp.async.cg.shared.global [%0], [%1], 16;"
                 :: "r"(saddr), "l"(gptr));
}
#define CP_COMMIT() asm volatile("cp.async.commit_group;" ::: "memory")
#define CP_WAIT0()  asm volatile("cp.async.wait_group 0;" ::: "memory")

#define LDSM_X4(r0, r1, r2, r3, addr) \
    asm volatile("ldmatrix.sync.aligned.m8n8.x4.shared.b16 {%0,%1,%2,%3}, [%4];" \
                 : "=r"(r0), "=r"(r1), "=r"(r2), "=r"(r3) : "r"(addr))

#define MMA16816(c, a0, a1, a2, a3, b0, b1) \
    asm volatile("mma.sync.aligned.m16n8k16.row.col.f32.bf16.bf16.f32 " \
                 "{%0,%1,%2,%3}, {%4,%5,%6,%7}, {%8,%9}, {%0,%1,%2,%3};" \
                 : "+f"((c)[0]), "+f"((c)[1]), "+f"((c)[2]), "+f"((c)[3]) \
                 : "r"(a0), "r"(a1), "r"(a2), "r"(a3), "r"(b0), "r"(b1))

// ---------------------------------------------------------------------------
// complex helpers
// ---------------------------------------------------------------------------
__device__ __forceinline__ float2 cadd(float2 a, float2 b) { return make_float2(a.x + b.x, a.y + b.y); }
__device__ __forceinline__ float2 csub(float2 a, float2 b) { return make_float2(a.x - b.x, a.y - b.y); }
__device__ __forceinline__ float2 cmul(float2 a, float2 b) {
    return make_float2(a.x * b.x - a.y * b.y, a.x * b.y + a.y * b.x);
}
__device__ __forceinline__ float2 cmuli(float2 a) { return make_float2(-a.y, a.x); }  // * i

// inverse 8-point DFT: X[m] = sum_k c[k] e^{+2*pi*i*k*m/8}
__device__ __forceinline__ void ifft8(const float2 c[8], float2 X[8]) {
    const float r = 0.70710678118654752f;
    float2 t0 = cadd(c[0], c[4]), t1 = csub(c[0], c[4]);
    float2 t2 = cadd(c[2], c[6]), t3 = cmuli(csub(c[2], c[6]));
    float2 E0 = cadd(t0, t2), E1 = cadd(t1, t3), E2 = csub(t0, t2), E3 = csub(t1, t3);
    float2 u0 = cadd(c[1], c[5]), u1 = csub(c[1], c[5]);
    float2 u2 = cadd(c[3], c[7]), u3 = cmuli(csub(c[3], c[7]));
    float2 O0 = cadd(u0, u2), O1 = cadd(u1, u3), O2 = csub(u0, u2), O3 = csub(u1, u3);
    float2 W1 = make_float2(r * (O1.x - O1.y), r * (O1.x + O1.y));
    float2 W2 = cmuli(O2);
    float2 W3 = make_float2(-r * (O3.x + O3.y), r * (O3.x - O3.y));
    X[0] = cadd(E0, O0); X[4] = csub(E0, O0);
    X[1] = cadd(E1, W1); X[5] = csub(E1, W1);
    X[2] = cadd(E2, W2); X[6] = csub(E2, W2);
    X[3] = cadd(E3, W3); X[7] = csub(E3, W3);
}

// ---------------------------------------------------------------------------
// Prep: split x (fp32) into bf16 hi/lo
// ---------------------------------------------------------------------------
__global__ void __launch_bounds__(256)
split_x_kernel(const float* __restrict__ x)
{
    size_t i = ((size_t)blockIdx.x * 256 + threadIdx.x) * 8;
    float4 a = *(const float4*)(x + i);
    float4 b = *(const float4*)(x + i + 4);
    float v[8] = {a.x, a.y, a.z, a.w, b.x, b.y, b.z, b.w};
    union { __nv_bfloat16 h[8]; uint4 u; } H, L;
#pragma unroll
    for (int j = 0; j < 8; j++) {
        __nv_bfloat16 hi = __float2bfloat16(v[j]);
        H.h[j] = hi;
        L.h[j] = __float2bfloat16(v[j] - __bfloat162float(hi));
    }
    *(uint4*)&g_xhi[i] = H.u;
    *(uint4*)&g_xlo[i] = L.u;
}

// ---------------------------------------------------------------------------
// Prep: W [K, 1026] -> Wt hi/lo [1152, 512] bf16 (transposed, padded)
// ---------------------------------------------------------------------------
__global__ void __launch_bounds__(256)
prep_w_kernel(const float* __restrict__ W)
{
    int idx = blockIdx.x * 256 + threadIdx.x;
    if (idx >= N_PAD * K_DIM) return;
    int n = idx >> 9;
    int k = idx & 511;
    float v = (n < N_DIM) ? W[(size_t)k * N_DIM + n] : 0.0f;
    __nv_bfloat16 hi = __float2bfloat16(v);
    g_wthi[idx] = hi;
    g_wtlo[idx] = __float2bfloat16(v - __bfloat162float(hi));
}

// ---------------------------------------------------------------------------
// Prep: trig tables + window + envelope reciprocal (merged)
// ---------------------------------------------------------------------------
__global__ void __launch_bounds__(256)
prep_tables_env_kernel()
{
    int i = blockIdx.x * 256 + threadIdx.x;
    float s, c;
    if (i < 512) {                               // e^{2*pi*i*j/512}
        sincospif((float)i * (1.0f / 256.0f), &s, &c);
        g_tw[i] = make_float2(c, s);
    }
    if (i < 512) {                               // e^{2*pi*i*k/1024}
        sincospif((float)i * (1.0f / 512.0f), &s, &c);
        g_pretw[i] = make_float2(c, s);
    }
    if (i < NFFT) {
        g_win[i] = 0.5f * (1.0f - cospif((float)i * (1.0f / 512.0f)));
    }
    if (i < OUT_FULL) {
        int m = i;
        int t_hi = m >> 8;
        if (t_hi > T_FRAMES - 1) t_hi = T_FRAMES - 1;
        int t_lo = (m >= (NFFT - HOP)) ? ((m - (NFFT - HOP)) >> 8) : 0;
        float env = 0.0f;
        for (int t = t_lo; t <= t_hi; t++) {
            int n = m - (t << 8);
            float win = 0.5f * (1.0f - cospif((float)n * (1.0f / 512.0f)));
            env += win * win;
        }
        g_env_inv[m] = (env > 0.0f) ? (1.0f / env) : 0.0f;
    }
}

// ---------------------------------------------------------------------------
// Kernel 1: HMMA GEMM  h = x @ W + b  via 3x-bf16 split on mma.sync.m16n8k16.
// CTA tile 256(M) x 128(N), BK=64, 8 warps (warp tile 64x64), 2-stage cp.async.
// ---------------------------------------------------------------------------
#define A_MAT_BYTES 32768                 // 256 x 64 bf16
#define B_MAT_BYTES 16384                 // 128 x 64 bf16
#define STAGE_BYTES (2 * A_MAT_BYTES + 2 * B_MAT_BYTES)   // 98304
#define GEMM_SMEM   (2 * STAGE_BYTES)     // 196608
#define OFF_AH 0
#define OFF_AL A_MAT_BYTES
#define OFF_BH (2 * A_MAT_BYTES)
#define OFF_BL (2 * A_MAT_BYTES + B_MAT_BYTES)

__device__ __forceinline__ void load_stage(uint32_t sdst,
                                           const __nv_bfloat16* pAh,
                                           const __nv_bfloat16* pAl,
                                           const __nv_bfloat16* pBh,
                                           const __nv_bfloat16* pBl,
                                           int k0, int tid)
{
#pragma unroll
    for (int t = 0; t < 8; t++) {
        int idx = tid + (t << 8);
        int row = idx >> 3;
        int g   = idx & 7;
        uint32_t soff = (row << 7) + ((g ^ (row & 7)) << 4);
        size_t goff = (size_t)row * K_DIM + k0 + (g << 3);
        cp_async16(sdst + OFF_AH + soff, pAh + goff);
        cp_async16(sdst + OFF_AL + soff, pAl + goff);
    }
#pragma unroll
    for (int t = 0; t < 4; t++) {
        int idx = tid + (t << 8);
        int row = idx >> 3;
        int g   = idx & 7;
        uint32_t soff = (row << 7) + ((g ^ (row & 7)) << 4);
        size_t goff = (size_t)row * K_DIM + k0 + (g << 3);
        cp_async16(sdst + OFF_BH + soff, pBh + goff);
        cp_async16(sdst + OFF_BL + soff, pBl + goff);
    }
}

__global__ void __launch_bounds__(256, 1)
gemm_mma_kernel(const float* __restrict__ bias)
{
    extern __shared__ __align__(128) char smem[];
    const int tid  = threadIdx.x;
    const int lane = tid & 31;
    const int warp = tid >> 5;
    const int wm   = (warp >> 1) << 6;   // 0,64,128,192
    const int wn   = (warp & 1) << 6;    // 0,64
    const int bm   = blockIdx.y << 8;    // 256-row tiles
    const int bn   = blockIdx.x << 7;    // 128-col tiles
    const uint32_t sbase = smem_u32(smem);

    const __nv_bfloat16* pAh = g_xhi  + (size_t)bm * K_DIM;
    const __nv_bfloat16* pAl = g_xlo  + (size_t)bm * K_DIM;
    const __nv_bfloat16* pBh = g_wthi + (size_t)bn * K_DIM;
    const __nv_bfloat16* pBl = g_wtlo + (size_t)bn * K_DIM;

    float acc[4][8][4];
#pragma unroll
    for (int i = 0; i < 4; i++)
#pragma unroll
        for (int j = 0; j < 8; j++)
#pragma unroll
            for (int r = 0; r < 4; r++) acc[i][j][r] = 0.0f;

    const int a_row  = wm + (lane & 15);
    const int a_gadd = (lane >> 4);
    const int b_row  = wn + (lane & 7) + ((lane >> 4) << 3);
    const int b_gadd = ((lane >> 3) & 1);

    load_stage(sbase, pAh, pAl, pBh, pBl, 0, tid);
    CP_COMMIT();

    for (int ck = 0; ck < K_DIM / 64; ck++) {
        CP_WAIT0();
        __syncthreads();
        if (ck + 1 < K_DIM / 64)
            load_stage(sbase + (((ck + 1) & 1) ? STAGE_BYTES : 0),
                       pAh, pAl, pBh, pBl, (ck + 1) << 6, tid);
        CP_COMMIT();

        const uint32_t stg = sbase + ((ck & 1) ? STAGE_BYTES : 0);

#pragma unroll
        for (int s16 = 0; s16 < 4; s16++) {
            const int g0 = (s16 << 1);
            uint32_t a[4][4], bh[4][4], bl[4][4];

#pragma unroll
            for (int j2 = 0; j2 < 4; j2++) {
                int row = b_row + (j2 << 4);
                int g   = g0 + b_gadd;
                uint32_t boff = (row << 7) + ((g ^ (row & 7)) << 4);
                LDSM_X4(bh[j2][0], bh[j2][1], bh[j2][2], bh[j2][3],
                        stg + OFF_BH + boff);
                LDSM_X4(bl[j2][0], bl[j2][1], bl[j2][2], bl[j2][3],
                        stg + OFF_BL + boff);
            }
#pragma unroll
            for (int i = 0; i < 4; i++) {
                int row = a_row + (i << 4);
                int g   = g0 + a_gadd;
                uint32_t addr = stg + OFF_AH + (row << 7) + ((g ^ (row & 7)) << 4);
                LDSM_X4(a[i][0], a[i][1], a[i][2], a[i][3], addr);
            }
#pragma unroll
            for (int i = 0; i < 4; i++)
#pragma unroll
                for (int j = 0; j < 8; j++)
                    MMA16816(acc[i][j], a[i][0], a[i][1], a[i][2], a[i][3],
                             bh[j >> 1][(j & 1) << 1], bh[j >> 1][((j & 1) << 1) + 1]);
#pragma unroll
            for (int i = 0; i < 4; i++)
#pragma unroll
                for (int j = 0; j < 8; j++)
                    MMA16816(acc[i][j], a[i][0], a[i][1], a[i][2], a[i][3],
                             bl[j >> 1][(j & 1) << 1], bl[j >> 1][((j & 1) << 1) + 1]);
#pragma unroll
            for (int i = 0; i < 4; i++) {
                int row = a_row + (i << 4);
                int g   = g0 + a_gadd;
                uint32_t addr = stg + OFF_AL + (row << 7) + ((g ^ (row & 7)) << 4);
                LDSM_X4(a[i][0], a[i][1], a[i][2], a[i][3], addr);
            }
#pragma unroll
            for (int i = 0; i < 4; i++)
#pragma unroll
                for (int j = 0; j < 8; j++)
                    MMA16816(acc[i][j], a[i][0], a[i][1], a[i][2], a[i][3],
                             bh[j >> 1][(j & 1) << 1], bh[j >> 1][((j & 1) << 1) + 1]);
        }
    }

    const int r0 = bm + wm + (lane >> 2);
    const int c0 = bn + wn + ((lane & 3) << 1);
#pragma unroll
    for (int j = 0; j < 8; j++) {
        int col = c0 + (j << 3);
        if (col < N_DIM) {
            float bx = bias[col];
            float by = bias[col + 1];
#pragma unroll
            for (int i = 0; i < 4; i++) {
                int row = r0 + (i << 4);
                *(float2*)&g_h[(size_t)row * N_DIM + col] =
                    make_float2(acc[i][j][0] + bx, acc[i][j][1] + by);
                *(float2*)&g_h[(size_t)(row + 8) * N_DIM + col] =
                    make_float2(acc[i][j][2] + bx, acc[i][j][3] + by);
            }
        }
    }
}

// ---------------------------------------------------------------------------
// Kernel 2 (FUSED): per-chunk iFFT (radix-8 register FFT, 4 frames/round,
// 4 rounds = 16 frames: 13 owned + 3 halo) into smem, then overlap-add +
// envelope normalize directly from smem. No g_frames round trip.
// ---------------------------------------------------------------------------
// dynamic smem layout (bytes):
#define SF_FRAMES_B (CMP_FRAMES * NFFT * 4)        // 65536
#define SF_SPEC_B   (4 * 513 * 8)                  // 16416
#define SF_BUF_B    (4 * 540 * 8)                  // 17280
#define SF_TW_B     (512 * 8)                      // 4096
#define FUSED_SMEM  (SF_FRAMES_B + SF_SPEC_B + SF_BUF_B + SF_TW_B)  // 103328

__global__ void __launch_bounds__(256, 2)
ifft_ola_kernel(float* __restrict__ out)
{
    extern __shared__ __align__(16) char dsm[];
    float*  s_frames = (float*)dsm;                                   // [16][1024]
    float2* s_spec   = (float2*)(dsm + SF_FRAMES_B);                  // [4][513]
    float2* s_buf    = (float2*)(dsm + SF_FRAMES_B + SF_SPEC_B);      // [4][540]
    float2* s_tw     = (float2*)(dsm + SF_FRAMES_B + SF_SPEC_B + SF_BUF_B); // [512]

    const int tid = threadIdx.x;
    const int fid = tid >> 6;                 // frame lane within round (0..3)
    const int t   = tid & 63;                 // thread within frame
    const int c   = blockIdx.x;               // chunk 0..157
    const int b   = blockIdx.y;               // batch
    const int s0  = OWN_FRAMES * c - 3;       // first computed frame id (may be <0)

    s_tw[tid]       = g_tw[tid];
    s_tw[tid + 256] = g_tw[tid + 256];

    float2* spec = s_spec + fid * 513;
    float2* buf  = s_buf  + fid * 540;

#pragma unroll 1
    for (int r = 0; r < 4; r++) {
        // frame id for this round (clamped for halo out-of-range; OLA never
        // reads the clamped slots)
        int f  = s0 + (r << 2) + fid;
        int fe = f < 0 ? 0 : (f > T_FRAMES - 1 ? T_FRAMES - 1 : f);
        const float* __restrict__ h = g_h + (size_t)(b * T_FRAMES + fe) * N_DIM;

        // spectrum: S_k = min(exp(h_k),100) * (cos p_k + i sin p_k)
        for (int k = t; k <= 512; k += 64) {
            float mag = fminf(__expf(h[k]), 100.0f);
            float s, cc;
            __sincosf(h[NBINS + k], &s, &cc);
            if (k == 0 || k == 512) s = 0.0f;   // irfft ignores Im of DC/Nyquist
            spec[k] = make_float2(mag * cc, mag * s);
        }
        __syncthreads();

        // ---- pass A: Hermitian pack + IFFT8 over k1 (k2 = t) ----
        {
            float2 cc[8];
#pragma unroll
            for (int k1 = 0; k1 < 8; k1++) {
                int k = (k1 << 6) + t;
                float2 Xk = spec[k];
                float2 Xr = spec[512 - k];
                float Ex = 0.5f * (Xk.x + Xr.x);
                float Ey = 0.5f * (Xk.y - Xr.y);
                float Dx = 0.5f * (Xk.x - Xr.x);
                float Dy = 0.5f * (Xk.y + Xr.y);
                float2 w = g_pretw[k];
                cc[k1] = make_float2(Ex - (w.x * Dy + w.y * Dx),
                                     Ey + (w.x * Dx - w.y * Dy));
            }
            float2 X[8];
            ifft8(cc, X);
#pragma unroll
            for (int n1 = 1; n1 < 8; n1++) X[n1] = cmul(X[n1], s_tw[t * n1]);
            const int base = (t >> 3) * 68 + (t & 7);
#pragma unroll
            for (int n1 = 0; n1 < 8; n1++) buf[base + (n1 << 3)] = X[n1];
        }
        __syncthreads();

        // ---- pass B: IFFT8 over j1, thread = (n1, j2) ----
        {
            const int n1 = t >> 3, j2 = t & 7;
            float2 y[8];
#pragma unroll
            for (int j1 = 0; j1 < 8; j1++) y[j1] = buf[j1 * 68 + (n1 << 3) + j2];
            __syncthreads();
            float2 V[8];
            ifft8(y, V);
#pragma unroll
            for (int m1 = 1; m1 < 8; m1++) V[m1] = cmul(V[m1], s_tw[((j2 * m1) << 3)]);
            const int base = j2 * 66 + (n1 << 3);
#pragma unroll
            for (int m1 = 0; m1 < 8; m1++) buf[base + m1] = V[m1];
        }
        __syncthreads();

        // ---- pass C: IFFT8 over j2; scale + window; store to smem frames ----
        {
            const int n1 = t >> 3, m1 = t & 7;
            float2 d[8];
#pragma unroll
            for (int j2 = 0; j2 < 8; j2++) d[j2] = buf[j2 * 66 + (n1 << 3) + m1];
            float2 X[8];
            ifft8(d, X);
            const float inv = 1.0f / 512.0f;
            float* fr = s_frames + ((r << 2) + fid) * NFFT;
            const int nb = n1 + (m1 << 3);
#pragma unroll
            for (int m2 = 0; m2 < 8; m2++) {
                int n = nb + (m2 << 6);
                float2 w2 = *(const float2*)&g_win[2 * n];
                *(float2*)&fr[2 * n] = make_float2(X[m2].x * inv * w2.x,
                                                   X[m2].y * inv * w2.y);
            }
        }
        __syncthreads();
    }

    // ---- overlap-add from smem frames + envelope normalize ----
    const int mbase = c * OWN_SAMP;
    const size_t obase = (size_t)b * OUT_LEN;
#pragma unroll 1
    for (int i = 0; i < OWN_FRAMES; i++) {
        int m = mbase + (i << 8) + tid;
        if (m < PAD || m >= OUT_FULL - PAD) continue;
        int t_hi = m >> 8;
        if (t_hi > T_FRAMES - 1) t_hi = T_FRAMES - 1;
        int t_lo = (m >= (NFFT - HOP)) ? ((m - (NFFT - HOP)) >> 8) : 0;
        float acc = 0.0f;
#pragma unroll 4
        for (int tt = t_lo; tt <= t_hi; tt++) {
            acc += s_frames[(tt - s0) * NFFT + (m - (tt << 8))];
        }
        out[obase + (m - PAD)] = acc * g_env_inv[m];
    }
}

// ---------------------------------------------------------------------------
// Launch
// ---------------------------------------------------------------------------
extern "C" void kernel_launch(void* const* d_in, const int* in_sizes, int n_in,
                              void* d_out, int out_size)
{
    const float* x    = (const float*)d_in[0];   // [8, 2048, 512]
    const float* W    = (const float*)d_in[1];   // [512, 1026]
    const float* bias = (const float*)d_in[2];   // [1026]
    float* out = (float*)d_out;                  // [8, 524544]

    cudaFuncSetAttribute(gemm_mma_kernel,
                         cudaFuncAttributeMaxDynamicSharedMemorySize,
                         GEMM_SMEM);
    cudaFuncSetAttribute(ifft_ola_kernel,
                         cudaFuncAttributeMaxDynamicSharedMemorySize,
                         FUSED_SMEM);

    // 0) prep: bf16 splits + tables/window/envelope
    split_x_kernel<<<(M_TOTAL * K_DIM) / (256 * 8), 256>>>(x);
    prep_w_kernel<<<(N_PAD * K_DIM + 255) / 256, 256>>>(W);
    prep_tables_env_kernel<<<(OUT_FULL + 255) / 256, 256>>>();

    // 1) tensor-core (HMMA) GEMM -> g_h
    dim3 g1(N_PAD / 128, M_TOTAL / 256);   // (9, 64)
    gemm_mma_kernel<<<g1, 256, GEMM_SMEM>>>(bias);

    // 2) fused: spectrum -> radix-8 register irfft -> window -> OLA -> out
    dim3 g2(N_CHUNKS, BATCH);              // (158, 8)
    ifft_ola_kernel<<<g2, 256, FUSED_SMEM>>>(out);
}

// round 10
// speedup vs baseline: 1.0439x; 1.0439x over previous
#include <cuda_runtime.h>
#include <cuda_bf16.h>
#include <math.h>
#include <stdint.h>

// ---------------------------------------------------------------------------
// Problem constants
// ---------------------------------------------------------------------------
#define BATCH      8
#define T_FRAMES   2048
#define M_TOTAL    (BATCH * T_FRAMES)   // 16384 frames
#define K_DIM      512
#define N_DIM      1026                 // N_FFT + 2
#define N_PAD      1152                 // 9 * 128
#define NBINS      513                  // N_FFT/2 + 1
#define NFFT       1024
#define HOP        256
#define PAD        384                  // (1024-256)/2
#define OUT_FULL   ((T_FRAMES - 1) * HOP + NFFT)  // 525312
#define OUT_LEN    (OUT_FULL - 2 * PAD)           // 524544

// ---------------------------------------------------------------------------
// Scratch (device globals: no runtime allocation allowed)
// ---------------------------------------------------------------------------
__device__ float g_h[(size_t)M_TOTAL * N_DIM];        // linear head output (~67 MB)
__device__ float g_frames[(size_t)M_TOTAL * NFFT];    // windowed iFFT frames (~67 MB)
__device__ __nv_bfloat16 g_xhi[(size_t)M_TOTAL * K_DIM];
__device__ __nv_bfloat16 g_xlo[(size_t)M_TOTAL * K_DIM];
__device__ __nv_bfloat16 g_wthi[(size_t)N_PAD * K_DIM];
__device__ __nv_bfloat16 g_wtlo[(size_t)N_PAD * K_DIM];
// precomputed tables
__device__ float2 g_tw[512];        // e^{+2*pi*i*j/512},  j<512
__device__ float2 g_pretw[512];     // e^{+2*pi*i*k/1024}, k<512  (packing twiddles)
__device__ float  g_win[NFFT];      // hann window
__device__ float  g_env_inv[OUT_FULL];  // 1 / sum win^2

// ---------------------------------------------------------------------------
// baseline-arch PTX helpers (supported on compute_103 WITHOUT 'a')
// ---------------------------------------------------------------------------
__device__ __forceinline__ uint32_t smem_u32(const void* p) {
    return (uint32_t)__cvta_generic_to_shared(p);
}

__device__ __forceinline__ void cp_async16(uint32_t saddr, const void* gptr) {
    asm volatile("cp.async.cg.shared.global [%0], [%1], 16;"
                 :: "r"(saddr), "l"(gptr));
}
#define CP_COMMIT() asm volatile("cp.async.commit_group;" ::: "memory")
#define CP_WAIT2()  asm volatile("cp.async.wait_group 2;" ::: "memory")

#define LDSM_X4(r0, r1, r2, r3, addr) \
    asm volatile("ldmatrix.sync.aligned.m8n8.x4.shared.b16 {%0,%1,%2,%3}, [%4];" \
                 : "=r"(r0), "=r"(r1), "=r"(r2), "=r"(r3) : "r"(addr))

#define MMA16816(c, a0, a1, a2, a3, b0, b1) \
    asm volatile("mma.sync.aligned.m16n8k16.row.col.f32.bf16.bf16.f32 " \
                 "{%0,%1,%2,%3}, {%4,%5,%6,%7}, {%8,%9}, {%0,%1,%2,%3};" \
                 : "+f"((c)[0]), "+f"((c)[1]), "+f"((c)[2]), "+f"((c)[3]) \
                 : "r"(a0), "r"(a1), "r"(a2), "r"(a3), "r"(b0), "r"(b1))

// ---------------------------------------------------------------------------
// complex helpers
// ---------------------------------------------------------------------------
__device__ __forceinline__ float2 cadd(float2 a, float2 b) { return make_float2(a.x + b.x, a.y + b.y); }
__device__ __forceinline__ float2 csub(float2 a, float2 b) { return make_float2(a.x - b.x, a.y - b.y); }
__device__ __forceinline__ float2 cmul(float2 a, float2 b) {
    return make_float2(a.x * b.x - a.y * b.y, a.x * b.y + a.y * b.x);
}
__device__ __forceinline__ float2 cmuli(float2 a) { return make_float2(-a.y, a.x); }  // * i

// inverse 8-point DFT: X[m] = sum_k c[k] e^{+2*pi*i*k*m/8}
__device__ __forceinline__ void ifft8(const float2 c[8], float2 X[8]) {
    const float r = 0.70710678118654752f;
    float2 t0 = cadd(c[0], c[4]), t1 = csub(c[0], c[4]);
    float2 t2 = cadd(c[2], c[6]), t3 = cmuli(csub(c[2], c[6]));
    float2 E0 = cadd(t0, t2), E1 = cadd(t1, t3), E2 = csub(t0, t2), E3 = csub(t1, t3);
    float2 u0 = cadd(c[1], c[5]), u1 = csub(c[1], c[5]);
    float2 u2 = cadd(c[3], c[7]), u3 = cmuli(csub(c[3], c[7]));
    float2 O0 = cadd(u0, u2), O1 = cadd(u1, u3), O2 = csub(u0, u2), O3 = csub(u1, u3);
    float2 W1 = make_float2(r * (O1.x - O1.y), r * (O1.x + O1.y));
    float2 W2 = cmuli(O2);
    float2 W3 = make_float2(-r * (O3.x + O3.y), r * (O3.x - O3.y));
    X[0] = cadd(E0, O0); X[4] = csub(E0, O0);
    X[1] = cadd(E1, W1); X[5] = csub(E1, W1);
    X[2] = cadd(E2, W2); X[6] = csub(E2, W2);
    X[3] = cadd(E3, W3); X[7] = csub(E3, W3);
}

// ---------------------------------------------------------------------------
// Prep: split x (fp32) into bf16 hi/lo
// ---------------------------------------------------------------------------
__global__ void __launch_bounds__(256)
split_x_kernel(const float* __restrict__ x)
{
    size_t i = ((size_t)blockIdx.x * 256 + threadIdx.x) * 8;
    float4 a = *(const float4*)(x + i);
    float4 b = *(const float4*)(x + i + 4);
    float v[8] = {a.x, a.y, a.z, a.w, b.x, b.y, b.z, b.w};
    union { __nv_bfloat16 h[8]; uint4 u; } H, L;
#pragma unroll
    for (int j = 0; j < 8; j++) {
        __nv_bfloat16 hi = __float2bfloat16(v[j]);
        H.h[j] = hi;
        L.h[j] = __float2bfloat16(v[j] - __bfloat162float(hi));
    }
    *(uint4*)&g_xhi[i] = H.u;
    *(uint4*)&g_xlo[i] = L.u;
}

// ---------------------------------------------------------------------------
// Prep: W [K, 1026] -> Wt hi/lo [1152, 512] bf16 (transposed, padded)
// ---------------------------------------------------------------------------
__global__ void __launch_bounds__(256)
prep_w_kernel(const float* __restrict__ W)
{
    int idx = blockIdx.x * 256 + threadIdx.x;
    if (idx >= N_PAD * K_DIM) return;
    int n = idx >> 9;
    int k = idx & 511;
    float v = (n < N_DIM) ? W[(size_t)k * N_DIM + n] : 0.0f;
    __nv_bfloat16 hi = __float2bfloat16(v);
    g_wthi[idx] = hi;
    g_wtlo[idx] = __float2bfloat16(v - __bfloat162float(hi));
}

// ---------------------------------------------------------------------------
// Prep: trig tables + window + envelope reciprocal (merged)
// ---------------------------------------------------------------------------
__global__ void __launch_bounds__(256)
prep_tables_env_kernel()
{
    int i = blockIdx.x * 256 + threadIdx.x;
    float s, c;
    if (i < 512) {                               // e^{2*pi*i*j/512}
        sincospif((float)i * (1.0f / 256.0f), &s, &c);
        g_tw[i] = make_float2(c, s);
    }
    if (i < 512) {                               // e^{2*pi*i*k/1024}
        sincospif((float)i * (1.0f / 512.0f), &s, &c);
        g_pretw[i] = make_float2(c, s);
    }
    if (i < NFFT) {
        g_win[i] = 0.5f * (1.0f - cospif((float)i * (1.0f / 512.0f)));
    }
    if (i < OUT_FULL) {
        int m = i;
        int t_hi = m >> 8;
        if (t_hi > T_FRAMES - 1) t_hi = T_FRAMES - 1;
        int t_lo = (m >= (NFFT - HOP)) ? ((m - (NFFT - HOP)) >> 8) : 0;
        float env = 0.0f;
        for (int t = t_lo; t <= t_hi; t++) {
            int n = m - (t << 8);
            float win = 0.5f * (1.0f - cospif((float)n * (1.0f / 512.0f)));
            env += win * win;
        }
        g_env_inv[m] = (env > 0.0f) ? (1.0f / env) : 0.0f;
    }
}

// ---------------------------------------------------------------------------
// Kernel 1: HMMA GEMM  h = x @ W + b  via 3x-bf16 split on mma.sync.m16n8k16.
// CTA tile 256(M) x 128(N), BK=32, 4-stage cp.async pipeline (wait_group 2),
// 8 warps (warp tile 64x64). 64B rows with xor swizzle slot = g ^ ((row>>1)&3)
// -> conflict-free cp.async stores AND ldmatrix reads.
// ---------------------------------------------------------------------------
#define A_MAT_BYTES 16384                 // 256 rows x 64 B
#define B_MAT_BYTES 8192                  // 128 rows x 64 B
#define STAGE_BYTES (2 * A_MAT_BYTES + 2 * B_MAT_BYTES)   // 49152
#define N_STAGES    4
#define GEMM_SMEM   (N_STAGES * STAGE_BYTES)              // 196608
#define N_CHUNKS_K  (K_DIM / 32)          // 16
#define OFF_AH 0
#define OFF_AL A_MAT_BYTES
#define OFF_BH (2 * A_MAT_BYTES)
#define OFF_BL (2 * A_MAT_BYTES + B_MAT_BYTES)

// byte offset of (row, 16B-granule g in 0..3) within a matrix tile
#define SWZ(row, g) (((row) << 6) + ((((g) ^ (((row) >> 1) & 3))) << 4))

__device__ __forceinline__ void load_stage(uint32_t sdst,
                                           const __nv_bfloat16* pAh,
                                           const __nv_bfloat16* pAl,
                                           const __nv_bfloat16* pBh,
                                           const __nv_bfloat16* pBl,
                                           int k0, int tid)
{
    // A matrices: 256 rows x 4 granules = 1024 transfers (4 iters)
#pragma unroll
    for (int t = 0; t < 4; t++) {
        int idx = tid + (t << 8);
        int row = idx >> 2;
        int g   = idx & 3;
        uint32_t soff = SWZ(row, g);
        size_t goff = (size_t)row * K_DIM + k0 + (g << 3);
        cp_async16(sdst + OFF_AH + soff, pAh + goff);
        cp_async16(sdst + OFF_AL + soff, pAl + goff);
    }
    // B matrices: 128 rows x 4 granules = 512 transfers (2 iters)
#pragma unroll
    for (int t = 0; t < 2; t++) {
        int idx = tid + (t << 8);
        int row = idx >> 2;
        int g   = idx & 3;
        uint32_t soff = SWZ(row, g);
        size_t goff = (size_t)row * K_DIM + k0 + (g << 3);
        cp_async16(sdst + OFF_BH + soff, pBh + goff);
        cp_async16(sdst + OFF_BL + soff, pBl + goff);
    }
}

__global__ void __launch_bounds__(256, 1)
gemm_mma_kernel(const float* __restrict__ bias)
{
    extern __shared__ __align__(128) char smem[];
    const int tid  = threadIdx.x;
    const int lane = tid & 31;
    const int warp = tid >> 5;
    const int wm   = (warp >> 1) << 6;   // 0,64,128,192
    const int wn   = (warp & 1) << 6;    // 0,64
    const int bm   = blockIdx.y << 8;    // 256-row tiles
    const int bn   = blockIdx.x << 7;    // 128-col tiles
    const uint32_t sbase = smem_u32(smem);

    const __nv_bfloat16* pAh = g_xhi  + (size_t)bm * K_DIM;
    const __nv_bfloat16* pAl = g_xlo  + (size_t)bm * K_DIM;
    const __nv_bfloat16* pBh = g_wthi + (size_t)bn * K_DIM;
    const __nv_bfloat16* pBl = g_wtlo + (size_t)bn * K_DIM;

    float acc[4][8][4];
#pragma unroll
    for (int i = 0; i < 4; i++)
#pragma unroll
        for (int j = 0; j < 8; j++)
#pragma unroll
            for (int r = 0; r < 4; r++) acc[i][j][r] = 0.0f;

    const int a_row  = wm + (lane & 15);
    const int a_gadd = (lane >> 4);          // 0/1
    const int b_row  = wn + (lane & 7) + ((lane >> 4) << 3);
    const int b_gadd = ((lane >> 3) & 1);

    // prologue: 3 stages in flight
    load_stage(sbase + 0 * STAGE_BYTES, pAh, pAl, pBh, pBl,  0, tid); CP_COMMIT();
    load_stage(sbase + 1 * STAGE_BYTES, pAh, pAl, pBh, pBl, 32, tid); CP_COMMIT();
    load_stage(sbase + 2 * STAGE_BYTES, pAh, pAl, pBh, pBl, 64, tid); CP_COMMIT();

    for (int ck = 0; ck < N_CHUNKS_K; ck++) {
        CP_WAIT2();                        // stage ck landed (<=2 still flying)
        __syncthreads();
        if (ck + 3 < N_CHUNKS_K)
            load_stage(sbase + ((ck + 3) & 3) * STAGE_BYTES,
                       pAh, pAl, pBh, pBl, (ck + 3) << 5, tid);
        CP_COMMIT();                       // commit (possibly empty) group

        const uint32_t stg = sbase + (ck & 3) * STAGE_BYTES;

#pragma unroll
        for (int s16 = 0; s16 < 2; s16++) {
            const int g0 = (s16 << 1);
            uint32_t a[4][4], bh[4][4], bl[4][4];

            // B(hi), B(lo): 4+4 ldmatrix.x4 covering 64 cols
#pragma unroll
            for (int j2 = 0; j2 < 4; j2++) {
                int row = b_row + (j2 << 4);
                int g   = g0 + b_gadd;
                uint32_t boff = SWZ(row, g);
                LDSM_X4(bh[j2][0], bh[j2][1], bh[j2][2], bh[j2][3],
                        stg + OFF_BH + boff);
                LDSM_X4(bl[j2][0], bl[j2][1], bl[j2][2], bl[j2][3],
                        stg + OFF_BL + boff);
            }
            // A(hi)
#pragma unroll
            for (int i = 0; i < 4; i++) {
                int row = a_row + (i << 4);
                int g   = g0 + a_gadd;
                uint32_t addr = stg + OFF_AH + SWZ(row, g);
                LDSM_X4(a[i][0], a[i][1], a[i][2], a[i][3], addr);
            }
            // pass 1: Ah x Bh
#pragma unroll
            for (int i = 0; i < 4; i++)
#pragma unroll
                for (int j = 0; j < 8; j++)
                    MMA16816(acc[i][j], a[i][0], a[i][1], a[i][2], a[i][3],
                             bh[j >> 1][(j & 1) << 1], bh[j >> 1][((j & 1) << 1) + 1]);
            // pass 2: Ah x Bl
#pragma unroll
            for (int i = 0; i < 4; i++)
#pragma unroll
                for (int j = 0; j < 8; j++)
                    MMA16816(acc[i][j], a[i][0], a[i][1], a[i][2], a[i][3],
                             bl[j >> 1][(j & 1) << 1], bl[j >> 1][((j & 1) << 1) + 1]);
            // A(lo) (reuse regs)
#pragma unroll
            for (int i = 0; i < 4; i++) {
                int row = a_row + (i << 4);
                int g   = g0 + a_gadd;
                uint32_t addr = stg + OFF_AL + SWZ(row, g);
                LDSM_X4(a[i][0], a[i][1], a[i][2], a[i][3], addr);
            }
            // pass 3: Al x Bh
#pragma unroll
            for (int i = 0; i < 4; i++)
#pragma unroll
                for (int j = 0; j < 8; j++)
                    MMA16816(acc[i][j], a[i][0], a[i][1], a[i][2], a[i][3],
                             bh[j >> 1][(j & 1) << 1], bh[j >> 1][((j & 1) << 1) + 1]);
        }
    }

    // epilogue: bias + direct float2 stores
    const int r0 = bm + wm + (lane >> 2);
    const int c0 = bn + wn + ((lane & 3) << 1);
#pragma unroll
    for (int j = 0; j < 8; j++) {
        int col = c0 + (j << 3);
        if (col < N_DIM) {
            float bx = bias[col];
            float by = bias[col + 1];
#pragma unroll
            for (int i = 0; i < 4; i++) {
                int row = r0 + (i << 4);
                *(float2*)&g_h[(size_t)row * N_DIM + col] =
                    make_float2(acc[i][j][0] + bx, acc[i][j][1] + by);
                *(float2*)&g_h[(size_t)(row + 8) * N_DIM + col] =
                    make_float2(acc[i][j][2] + bx, acc[i][j][3] + by);
            }
        }
    }
}

// ---------------------------------------------------------------------------
// Kernel 2: spectrum -> 512-pt inverse FFT as 3x radix-8 register passes
// (2 smem transposes, 64 threads/frame, 4 frames/block) -> window -> frames.
// ---------------------------------------------------------------------------
__global__ void __launch_bounds__(256)
ifft_kernel()
{
    __shared__ float2 s_spec[4][513];   // packed spectrum per frame
    __shared__ float2 s_buf[4][540];    // transpose buffer per frame
    __shared__ float2 s_tw[512];        // e^{2*pi*i*j/512}

    const int tid = threadIdx.x;
    const int fid = tid >> 6;                      // frame within block
    const int t   = tid & 63;                      // thread within frame
    const int f   = (blockIdx.x << 2) + fid;       // global frame id
    const float* __restrict__ h = g_h + (size_t)f * N_DIM;

    s_tw[tid]       = g_tw[tid];
    s_tw[tid + 256] = g_tw[tid + 256];

    // spectrum: S_k = min(exp(h_k),100) * (cos p_k + i sin p_k)
    for (int k = t; k <= 512; k += 64) {
        float mag = fminf(__expf(h[k]), 100.0f);
        float s, c;
        __sincosf(h[NBINS + k], &s, &c);
        if (k == 0 || k == 512) s = 0.0f;          // irfft ignores Im of DC/Nyquist
        s_spec[fid][k] = make_float2(mag * c, mag * s);
    }
    __syncthreads();

    // ---- pass A: pack + IFFT8 over k1 (k2 = t) ----
    {
        float2 c[8];
#pragma unroll
        for (int k1 = 0; k1 < 8; k1++) {
            int k = (k1 << 6) + t;
            float2 Xk = s_spec[fid][k];
            float2 Xr = s_spec[fid][512 - k];
            float Ex = 0.5f * (Xk.x + Xr.x);
            float Ey = 0.5f * (Xk.y - Xr.y);
            float Dx = 0.5f * (Xk.x - Xr.x);
            float Dy = 0.5f * (Xk.y + Xr.y);
            float2 w = g_pretw[k];
            c[k1] = make_float2(Ex - (w.x * Dy + w.y * Dx),
                                Ey + (w.x * Dx - w.y * Dy));
        }
        float2 X[8];
        ifft8(c, X);
#pragma unroll
        for (int n1 = 1; n1 < 8; n1++) X[n1] = cmul(X[n1], s_tw[t * n1]);
        const int base = (t >> 3) * 68 + (t & 7);
#pragma unroll
        for (int n1 = 0; n1 < 8; n1++) s_buf[fid][base + (n1 << 3)] = X[n1];
    }
    __syncthreads();

    // ---- pass B: IFFT8 over j1, thread = (n1, j2) ----
    {
        const int n1 = t >> 3, j2 = t & 7;
        float2 y[8];
#pragma unroll
        for (int j1 = 0; j1 < 8; j1++) y[j1] = s_buf[fid][j1 * 68 + (n1 << 3) + j2];
        __syncthreads();                          // reads done before in-place writes
        float2 V[8];
        ifft8(y, V);
#pragma unroll
        for (int m1 = 1; m1 < 8; m1++) V[m1] = cmul(V[m1], s_tw[((j2 * m1) << 3)]);
        const int base = j2 * 66 + (n1 << 3);
#pragma unroll
        for (int m1 = 0; m1 < 8; m1++) s_buf[fid][base + m1] = V[m1];
    }
    __syncthreads();

    // ---- pass C: IFFT8 over j2, thread = (n1, m1); scale + window + store ----
    {
        const int n1 = t >> 3, m1 = t & 7;
        float2 d[8];
#pragma unroll
        for (int j2 = 0; j2 < 8; j2++) d[j2] = s_buf[fid][j2 * 66 + (n1 << 3) + m1];
        float2 X[8];
        ifft8(d, X);
        const float inv = 1.0f / 512.0f;
        float* __restrict__ fr = g_frames + (size_t)f * NFFT;
        const int nb = n1 + (m1 << 3);
#pragma unroll
        for (int m2 = 0; m2 < 8; m2++) {
            int n = nb + (m2 << 6);
            float2 w2 = *(const float2*)&g_win[2 * n];
            *(float2*)&fr[2 * n] = make_float2(X[m2].x * inv * w2.x,
                                               X[m2].y * inv * w2.y);
        }
    }
}

// ---------------------------------------------------------------------------
// Kernel 3: overlap-add, 4 outputs/thread, float4 loads, precomputed 1/env.
// ---------------------------------------------------------------------------
__global__ void __launch_bounds__(256)
ola_kernel(float* __restrict__ out)
{
    int g = blockIdx.x * blockDim.x + threadIdx.x;       // group id
    if (g >= (BATCH * OUT_LEN) / 4) return;
    int b   = g / (OUT_LEN / 4);
    int mo0 = (g - b * (OUT_LEN / 4)) << 2;
    int m0  = mo0 + PAD;

    int t_hi = m0 >> 8;
    if (t_hi > T_FRAMES - 1) t_hi = T_FRAMES - 1;
    int t_lo = (m0 >= (NFFT - HOP)) ? ((m0 - (NFFT - HOP)) >> 8) : 0;

    float4 acc = make_float4(0.0f, 0.0f, 0.0f, 0.0f);
    const float* __restrict__ base = g_frames + (size_t)b * T_FRAMES * NFFT;
#pragma unroll 4
    for (int t = t_lo; t <= t_hi; t++) {
        float4 v = *(const float4*)(base + (size_t)t * NFFT + (m0 - (t << 8)));
        acc.x += v.x; acc.y += v.y; acc.z += v.z; acc.w += v.w;
    }
    float4 e = *(const float4*)&g_env_inv[m0];
    *(float4*)&out[(size_t)b * OUT_LEN + mo0] =
        make_float4(acc.x * e.x, acc.y * e.y, acc.z * e.z, acc.w * e.w);
}

// ---------------------------------------------------------------------------
// Launch
// ---------------------------------------------------------------------------
extern "C" void kernel_launch(void* const* d_in, const int* in_sizes, int n_in,
                              void* d_out, int out_size)
{
    const float* x    = (const float*)d_in[0];   // [8, 2048, 512]
    const float* W    = (const float*)d_in[1];   // [512, 1026]
    const float* bias = (const float*)d_in[2];   // [1026]
    float* out = (float*)d_out;                  // [8, 524544]

    cudaFuncSetAttribute(gemm_mma_kernel,
                         cudaFuncAttributeMaxDynamicSharedMemorySize,
                         GEMM_SMEM);

    // 0) prep: bf16 splits + tables/window/envelope
    split_x_kernel<<<(M_TOTAL * K_DIM) / (256 * 8), 256>>>(x);
    prep_w_kernel<<<(N_PAD * K_DIM + 255) / 256, 256>>>(W);
    prep_tables_env_kernel<<<(OUT_FULL + 255) / 256, 256>>>();

    // 1) tensor-core (HMMA) GEMM -> g_h
    dim3 g1(N_PAD / 128, M_TOTAL / 256);   // (9, 64)
    gemm_mma_kernel<<<g1, 256, GEMM_SMEM>>>(bias);

    // 2) spectrum -> radix-8 register irfft -> window -> g_frames
    ifft_kernel<<<M_TOTAL / 4, 256>>>();

    // 3) overlap-add * 1/env -> out (4 outputs per thread)
    int groups = (BATCH * OUT_LEN) / 4;
    ola_kernel<<<(groups + 255) / 256, 256>>>(out);
}

// round 11
// speedup vs baseline: 1.0782x; 1.0329x over previous
#include <cuda_runtime.h>
#include <cuda_bf16.h>
#include <math.h>
#include <stdint.h>

// ---------------------------------------------------------------------------
// Problem constants
// ---------------------------------------------------------------------------
#define BATCH      8
#define T_FRAMES   2048
#define M_TOTAL    (BATCH * T_FRAMES)   // 16384 frames
#define K_DIM      512
#define N_DIM      1026                 // N_FFT + 2
#define N_PAD      1152                 // 9 * 128
#define NBINS      513                  // N_FFT/2 + 1
#define NFFT       1024
#define HOP        256
#define PAD        384                  // (1024-256)/2
#define OUT_FULL   ((T_FRAMES - 1) * HOP + NFFT)  // 525312
#define OUT_LEN    (OUT_FULL - 2 * PAD)           // 524544

// ---------------------------------------------------------------------------
// Scratch (device globals: no runtime allocation allowed)
// ---------------------------------------------------------------------------
__device__ float g_h[(size_t)M_TOTAL * N_DIM];        // linear head output (~67 MB)
__device__ float g_frames[(size_t)M_TOTAL * NFFT];    // windowed iFFT frames (~67 MB)
__device__ __nv_bfloat16 g_xhi[(size_t)M_TOTAL * K_DIM];
__device__ __nv_bfloat16 g_xlo[(size_t)M_TOTAL * K_DIM];
__device__ __nv_bfloat16 g_wthi[(size_t)N_PAD * K_DIM];
__device__ __nv_bfloat16 g_wtlo[(size_t)N_PAD * K_DIM];
// precomputed tables
__device__ float2 g_tw[512];        // e^{+2*pi*i*j/512},  j<512
__device__ float2 g_pretw[512];     // e^{+2*pi*i*k/1024}, k<512  (packing twiddles)
__device__ float  g_win[NFFT];      // hann window
__device__ float  g_env_inv[OUT_FULL];  // 1 / sum win^2

// ---------------------------------------------------------------------------
// baseline-arch PTX helpers (supported on compute_103 WITHOUT 'a')
// ---------------------------------------------------------------------------
__device__ __forceinline__ uint32_t smem_u32(const void* p) {
    return (uint32_t)__cvta_generic_to_shared(p);
}

__device__ __forceinline__ void cp_async16(uint32_t saddr, const void* gptr) {
    asm volatile("cp.async.cg.shared.global [%0], [%1], 16;"
                 :: "r"(saddr), "l"(gptr));
}
#define CP_COMMIT() asm volatile("cp.async.commit_group;" ::: "memory")
#define CP_WAIT1()  asm volatile("cp.async.wait_group 1;" ::: "memory")

#define LDSM_X4(r0, r1, r2, r3, addr) \
    asm volatile("ldmatrix.sync.aligned.m8n8.x4.shared.b16 {%0,%1,%2,%3}, [%4];" \
                 : "=r"(r0), "=r"(r1), "=r"(r2), "=r"(r3) : "r"(addr))

#define MMA16816(c, a0, a1, a2, a3, b0, b1) \
    asm volatile("mma.sync.aligned.m16n8k16.row.col.f32.bf16.bf16.f32 " \
                 "{%0,%1,%2,%3}, {%4,%5,%6,%7}, {%8,%9}, {%0,%1,%2,%3};" \
                 : "+f"((c)[0]), "+f"((c)[1]), "+f"((c)[2]), "+f"((c)[3]) \
                 : "r"(a0), "r"(a1), "r"(a2), "r"(a3), "r"(b0), "r"(b1))

// ---------------------------------------------------------------------------
// complex helpers
// ---------------------------------------------------------------------------
__device__ __forceinline__ float2 cadd(float2 a, float2 b) { return make_float2(a.x + b.x, a.y + b.y); }
__device__ __forceinline__ float2 csub(float2 a, float2 b) { return make_float2(a.x - b.x, a.y - b.y); }
__device__ __forceinline__ float2 cmul(float2 a, float2 b) {
    return make_float2(a.x * b.x - a.y * b.y, a.x * b.y + a.y * b.x);
}
__device__ __forceinline__ float2 cmuli(float2 a) { return make_float2(-a.y, a.x); }  // * i

// inverse 8-point DFT: X[m] = sum_k c[k] e^{+2*pi*i*k*m/8}
__device__ __forceinline__ void ifft8(const float2 c[8], float2 X[8]) {
    const float r = 0.70710678118654752f;
    float2 t0 = cadd(c[0], c[4]), t1 = csub(c[0], c[4]);
    float2 t2 = cadd(c[2], c[6]), t3 = cmuli(csub(c[2], c[6]));
    float2 E0 = cadd(t0, t2), E1 = cadd(t1, t3), E2 = csub(t0, t2), E3 = csub(t1, t3);
    float2 u0 = cadd(c[1], c[5]), u1 = csub(c[1], c[5]);
    float2 u2 = cadd(c[3], c[7]), u3 = cmuli(csub(c[3], c[7]));
    float2 O0 = cadd(u0, u2), O1 = cadd(u1, u3), O2 = csub(u0, u2), O3 = csub(u1, u3);
    float2 W1 = make_float2(r * (O1.x - O1.y), r * (O1.x + O1.y));
    float2 W2 = cmuli(O2);
    float2 W3 = make_float2(-r * (O3.x + O3.y), r * (O3.x - O3.y));
    X[0] = cadd(E0, O0); X[4] = csub(E0, O0);
    X[1] = cadd(E1, W1); X[5] = csub(E1, W1);
    X[2] = cadd(E2, W2); X[6] = csub(E2, W2);
    X[3] = cadd(E3, W3); X[7] = csub(E3, W3);
}

// ---------------------------------------------------------------------------
// Prep: split x (fp32) into bf16 hi/lo
// ---------------------------------------------------------------------------
__global__ void __launch_bounds__(256)
split_x_kernel(const float* __restrict__ x)
{
    size_t i = ((size_t)blockIdx.x * 256 + threadIdx.x) * 8;
    float4 a = *(const float4*)(x + i);
    float4 b = *(const float4*)(x + i + 4);
    float v[8] = {a.x, a.y, a.z, a.w, b.x, b.y, b.z, b.w};
    union { __nv_bfloat16 h[8]; uint4 u; } H, L;
#pragma unroll
    for (int j = 0; j < 8; j++) {
        __nv_bfloat16 hi = __float2bfloat16(v[j]);
        H.h[j] = hi;
        L.h[j] = __float2bfloat16(v[j] - __bfloat162float(hi));
    }
    *(uint4*)&g_xhi[i] = H.u;
    *(uint4*)&g_xlo[i] = L.u;
}

// ---------------------------------------------------------------------------
// Prep: W [K, 1026] -> Wt hi/lo [1152, 512] bf16 (transposed, padded)
// ---------------------------------------------------------------------------
__global__ void __launch_bounds__(256)
prep_w_kernel(const float* __restrict__ W)
{
    int idx = blockIdx.x * 256 + threadIdx.x;
    if (idx >= N_PAD * K_DIM) return;
    int n = idx >> 9;
    int k = idx & 511;
    float v = (n < N_DIM) ? W[(size_t)k * N_DIM + n] : 0.0f;
    __nv_bfloat16 hi = __float2bfloat16(v);
    g_wthi[idx] = hi;
    g_wtlo[idx] = __float2bfloat16(v - __bfloat162float(hi));
}

// ---------------------------------------------------------------------------
// Prep: trig tables + window + envelope reciprocal (merged)
// ---------------------------------------------------------------------------
__global__ void __launch_bounds__(256)
prep_tables_env_kernel()
{
    int i = blockIdx.x * 256 + threadIdx.x;
    float s, c;
    if (i < 512) {                               // e^{2*pi*i*j/512}
        sincospif((float)i * (1.0f / 256.0f), &s, &c);
        g_tw[i] = make_float2(c, s);
    }
    if (i < 512) {                               // e^{2*pi*i*k/1024}
        sincospif((float)i * (1.0f / 512.0f), &s, &c);
        g_pretw[i] = make_float2(c, s);
    }
    if (i < NFFT) {
        g_win[i] = 0.5f * (1.0f - cospif((float)i * (1.0f / 512.0f)));
    }
    if (i < OUT_FULL) {
        int m = i;
        int t_hi = m >> 8;
        if (t_hi > T_FRAMES - 1) t_hi = T_FRAMES - 1;
        int t_lo = (m >= (NFFT - HOP)) ? ((m - (NFFT - HOP)) >> 8) : 0;
        float env = 0.0f;
        for (int t = t_lo; t <= t_hi; t++) {
            int n = m - (t << 8);
            float win = 0.5f * (1.0f - cospif((float)n * (1.0f / 512.0f)));
            env += win * win;
        }
        g_env_inv[m] = (env > 0.0f) ? (1.0f / env) : 0.0f;
    }
}

// ---------------------------------------------------------------------------
// Kernel 1: HMMA GEMM  h = x @ W + b  via 3x-bf16 split on mma.sync.m16n8k16.
// CTA tile 128(M) x 128(N), BK=32, 3-stage cp.async pipeline, 8 warps
// (warp tile 64x32), 2 CTAs/SM (96 KB smem, <=128 regs). 64B rows with xor
// swizzle slot = g ^ ((row>>1)&3): conflict-free cp.async + ldmatrix.
// ---------------------------------------------------------------------------
#define MAT_BYTES   8192                  // 128 rows x 64 B
#define STAGE_BYTES (4 * MAT_BYTES)       // 32768 (Ah, Al, Bh, Bl)
#define N_STAGES    3
#define GEMM_SMEM   (N_STAGES * STAGE_BYTES)   // 98304
#define N_CHUNKS_K  (K_DIM / 32)          // 16
#define OFF_AH 0
#define OFF_AL MAT_BYTES
#define OFF_BH (2 * MAT_BYTES)
#define OFF_BL (3 * MAT_BYTES)

// byte offset of (row, 16B-granule g in 0..3) within a 64B-row matrix tile
#define SWZ(row, g) (((row) << 6) + ((((g) ^ (((row) >> 1) & 3))) << 4))

__device__ __forceinline__ void load_stage(uint32_t sdst,
                                           const __nv_bfloat16* pAh,
                                           const __nv_bfloat16* pAl,
                                           const __nv_bfloat16* pBh,
                                           const __nv_bfloat16* pBl,
                                           int k0, int tid)
{
    // each matrix: 128 rows x 4 granules = 512 transfers (2 iters of 256)
#pragma unroll
    for (int t = 0; t < 2; t++) {
        int idx = tid + (t << 8);
        int row = idx >> 2;
        int g   = idx & 3;
        uint32_t soff = SWZ(row, g);
        size_t goff = (size_t)row * K_DIM + k0 + (g << 3);
        cp_async16(sdst + OFF_AH + soff, pAh + goff);
        cp_async16(sdst + OFF_AL + soff, pAl + goff);
        cp_async16(sdst + OFF_BH + soff, pBh + goff);
        cp_async16(sdst + OFF_BL + soff, pBl + goff);
    }
}

__global__ void __launch_bounds__(256, 2)
gemm_mma_kernel(const float* __restrict__ bias)
{
    extern __shared__ __align__(128) char smem[];
    const int tid  = threadIdx.x;
    const int lane = tid & 31;
    const int warp = tid >> 5;
    const int wm   = (warp >> 2) << 6;   // 0 / 64
    const int wn   = (warp & 3) << 5;    // 0,32,64,96
    const int bm   = blockIdx.y << 7;    // 128-row tiles
    const int bn   = blockIdx.x << 7;    // 128-col tiles
    const uint32_t sbase = smem_u32(smem);

    const __nv_bfloat16* pAh = g_xhi  + (size_t)bm * K_DIM;
    const __nv_bfloat16* pAl = g_xlo  + (size_t)bm * K_DIM;
    const __nv_bfloat16* pBh = g_wthi + (size_t)bn * K_DIM;
    const __nv_bfloat16* pBl = g_wtlo + (size_t)bn * K_DIM;

    float acc[4][4][4];
#pragma unroll
    for (int i = 0; i < 4; i++)
#pragma unroll
        for (int j = 0; j < 4; j++)
#pragma unroll
            for (int r = 0; r < 4; r++) acc[i][j][r] = 0.0f;

    const int a_row  = wm + (lane & 15);
    const int a_gadd = (lane >> 4);          // 0/1
    const int b_row  = wn + (lane & 7) + ((lane >> 4) << 3);
    const int b_gadd = ((lane >> 3) & 1);

    // prologue: 2 stages in flight
    load_stage(sbase + 0 * STAGE_BYTES, pAh, pAl, pBh, pBl,  0, tid); CP_COMMIT();
    load_stage(sbase + 1 * STAGE_BYTES, pAh, pAl, pBh, pBl, 32, tid); CP_COMMIT();

    int buf = 0;
    for (int ck = 0; ck < N_CHUNKS_K; ck++) {
        CP_WAIT1();                        // stage ck landed (1 still flying)
        __syncthreads();
        if (ck + 2 < N_CHUNKS_K) {
            int nb = buf + 2; if (nb >= N_STAGES) nb -= N_STAGES;
            load_stage(sbase + nb * STAGE_BYTES,
                       pAh, pAl, pBh, pBl, (ck + 2) << 5, tid);
        }
        CP_COMMIT();                       // commit (possibly empty) group

        const uint32_t stg = sbase + buf * STAGE_BYTES;
        if (++buf == N_STAGES) buf = 0;

#pragma unroll
        for (int s16 = 0; s16 < 2; s16++) {
            const int g0 = (s16 << 1);
            uint32_t a[4][4], bh[2][4], bl[2][4];

            // B(hi), B(lo): 2+2 ldmatrix.x4 covering 32 cols
#pragma unroll
            for (int j2 = 0; j2 < 2; j2++) {
                int row = b_row + (j2 << 4);
                int g   = g0 + b_gadd;
                uint32_t boff = SWZ(row, g);
                LDSM_X4(bh[j2][0], bh[j2][1], bh[j2][2], bh[j2][3],
                        stg + OFF_BH + boff);
                LDSM_X4(bl[j2][0], bl[j2][1], bl[j2][2], bl[j2][3],
                        stg + OFF_BL + boff);
            }
            // A(hi)
#pragma unroll
            for (int i = 0; i < 4; i++) {
                int row = a_row + (i << 4);
                int g   = g0 + a_gadd;
                uint32_t addr = stg + OFF_AH + SWZ(row, g);
                LDSM_X4(a[i][0], a[i][1], a[i][2], a[i][3], addr);
            }
            // pass 1: Ah x Bh
#pragma unroll
            for (int i = 0; i < 4; i++)
#pragma unroll
                for (int j = 0; j < 4; j++)
                    MMA16816(acc[i][j], a[i][0], a[i][1], a[i][2], a[i][3],
                             bh[j >> 1][(j & 1) << 1], bh[j >> 1][((j & 1) << 1) + 1]);
            // pass 2: Ah x Bl
#pragma unroll
            for (int i = 0; i < 4; i++)
#pragma unroll
                for (int j = 0; j < 4; j++)
                    MMA16816(acc[i][j], a[i][0], a[i][1], a[i][2], a[i][3],
                             bl[j >> 1][(j & 1) << 1], bl[j >> 1][((j & 1) << 1) + 1]);
            // A(lo) (reuse regs)
#pragma unroll
            for (int i = 0; i < 4; i++) {
                int row = a_row + (i << 4);
                int g   = g0 + a_gadd;
                uint32_t addr = stg + OFF_AL + SWZ(row, g);
                LDSM_X4(a[i][0], a[i][1], a[i][2], a[i][3], addr);
            }
            // pass 3: Al x Bh
#pragma unroll
            for (int i = 0; i < 4; i++)
#pragma unroll
                for (int j = 0; j < 4; j++)
                    MMA16816(acc[i][j], a[i][0], a[i][1], a[i][2], a[i][3],
                             bh[j >> 1][(j & 1) << 1], bh[j >> 1][((j & 1) << 1) + 1]);
        }
    }

    // epilogue: bias + direct float2 stores
    const int r0 = bm + wm + (lane >> 2);
    const int c0 = bn + wn + ((lane & 3) << 1);
#pragma unroll
    for (int j = 0; j < 4; j++) {
        int col = c0 + (j << 3);
        if (col < N_DIM) {
            float bx = bias[col];
            float by = bias[col + 1];
#pragma unroll
            for (int i = 0; i < 4; i++) {
                int row = r0 + (i << 4);
                *(float2*)&g_h[(size_t)row * N_DIM + col] =
                    make_float2(acc[i][j][0] + bx, acc[i][j][1] + by);
                *(float2*)&g_h[(size_t)(row + 8) * N_DIM + col] =
                    make_float2(acc[i][j][2] + bx, acc[i][j][3] + by);
            }
        }
    }
}

// ---------------------------------------------------------------------------
// Kernel 2: spectrum -> 512-pt inverse FFT as 3x radix-8 register passes
// (2 smem transposes, 64 threads/frame, 4 frames/block) -> window -> frames.
// ---------------------------------------------------------------------------
__global__ void __launch_bounds__(256)
ifft_kernel()
{
    __shared__ float2 s_spec[4][513];   // packed spectrum per frame
    __shared__ float2 s_buf[4][540];    // transpose buffer per frame
    __shared__ float2 s_tw[512];        // e^{2*pi*i*j/512}

    const int tid = threadIdx.x;
    const int fid = tid >> 6;                      // frame within block
    const int t   = tid & 63;                      // thread within frame
    const int f   = (blockIdx.x << 2) + fid;       // global frame id
    const float* __restrict__ h = g_h + (size_t)f * N_DIM;

    s_tw[tid]       = g_tw[tid];
    s_tw[tid + 256] = g_tw[tid + 256];

    // spectrum: S_k = min(exp(h_k),100) * (cos p_k + i sin p_k)
    for (int k = t; k <= 512; k += 64) {
        float mag = fminf(__expf(h[k]), 100.0f);
        float s, c;
        __sincosf(h[NBINS + k], &s, &c);
        if (k == 0 || k == 512) s = 0.0f;          // irfft ignores Im of DC/Nyquist
        s_spec[fid][k] = make_float2(mag * c, mag * s);
    }
    __syncthreads();

    // ---- pass A: pack + IFFT8 over k1 (k2 = t) ----
    {
        float2 c[8];
#pragma unroll
        for (int k1 = 0; k1 < 8; k1++) {
            int k = (k1 << 6) + t;
            float2 Xk = s_spec[fid][k];
            float2 Xr = s_spec[fid][512 - k];
            float Ex = 0.5f * (Xk.x + Xr.x);
            float Ey = 0.5f * (Xk.y - Xr.y);
            float Dx = 0.5f * (Xk.x - Xr.x);
            float Dy = 0.5f * (Xk.y + Xr.y);
            float2 w = g_pretw[k];
            c[k1] = make_float2(Ex - (w.x * Dy + w.y * Dx),
                                Ey + (w.x * Dx - w.y * Dy));
        }
        float2 X[8];
        ifft8(c, X);
#pragma unroll
        for (int n1 = 1; n1 < 8; n1++) X[n1] = cmul(X[n1], s_tw[t * n1]);
        const int base = (t >> 3) * 68 + (t & 7);
#pragma unroll
        for (int n1 = 0; n1 < 8; n1++) s_buf[fid][base + (n1 << 3)] = X[n1];
    }
    __syncthreads();

    // ---- pass B: IFFT8 over j1, thread = (n1, j2) ----
    {
        const int n1 = t >> 3, j2 = t & 7;
        float2 y[8];
#pragma unroll
        for (int j1 = 0; j1 < 8; j1++) y[j1] = s_buf[fid][j1 * 68 + (n1 << 3) + j2];
        __syncthreads();                          // reads done before in-place writes
        float2 V[8];
        ifft8(y, V);
#pragma unroll
        for (int m1 = 1; m1 < 8; m1++) V[m1] = cmul(V[m1], s_tw[((j2 * m1) << 3)]);
        const int base = j2 * 66 + (n1 << 3);
#pragma unroll
        for (int m1 = 0; m1 < 8; m1++) s_buf[fid][base + m1] = V[m1];
    }
    __syncthreads();

    // ---- pass C: IFFT8 over j2, thread = (n1, m1); scale + window + store ----
    {
        const int n1 = t >> 3, m1 = t & 7;
        float2 d[8];
#pragma unroll
        for (int j2 = 0; j2 < 8; j2++) d[j2] = s_buf[fid][j2 * 66 + (n1 << 3) + m1];
        float2 X[8];
        ifft8(d, X);
        const float inv = 1.0f / 512.0f;
        float* __restrict__ fr = g_frames + (size_t)f * NFFT;
        const int nb = n1 + (m1 << 3);
#pragma unroll
        for (int m2 = 0; m2 < 8; m2++) {
            int n = nb + (m2 << 6);
            float2 w2 = *(const float2*)&g_win[2 * n];
            *(float2*)&fr[2 * n] = make_float2(X[m2].x * inv * w2.x,
                                               X[m2].y * inv * w2.y);
        }
    }
}

// ---------------------------------------------------------------------------
// Kernel 3: overlap-add, 4 outputs/thread, float4 loads, precomputed 1/env.
// ---------------------------------------------------------------------------
__global__ void __launch_bounds__(256)
ola_kernel(float* __restrict__ out)
{
    int g = blockIdx.x * blockDim.x + threadIdx.x;       // group id
    if (g >= (BATCH * OUT_LEN) / 4) return;
    int b   = g / (OUT_LEN / 4);
    int mo0 = (g - b * (OUT_LEN / 4)) << 2;
    int m0  = mo0 + PAD;

    int t_hi = m0 >> 8;
    if (t_hi > T_FRAMES - 1) t_hi = T_FRAMES - 1;
    int t_lo = (m0 >= (NFFT - HOP)) ? ((m0 - (NFFT - HOP)) >> 8) : 0;

    float4 acc = make_float4(0.0f, 0.0f, 0.0f, 0.0f);
    const float* __restrict__ base = g_frames + (size_t)b * T_FRAMES * NFFT;
#pragma unroll 4
    for (int t = t_lo; t <= t_hi; t++) {
        float4 v = *(const float4*)(base + (size_t)t * NFFT + (m0 - (t << 8)));
        acc.x += v.x; acc.y += v.y; acc.z += v.z; acc.w += v.w;
    }
    float4 e = *(const float4*)&g_env_inv[m0];
    *(float4*)&out[(size_t)b * OUT_LEN + mo0] =
        make_float4(acc.x * e.x, acc.y * e.y, acc.z * e.z, acc.w * e.w);
}

// ---------------------------------------------------------------------------
// Launch
// ---------------------------------------------------------------------------
extern "C" void kernel_launch(void* const* d_in, const int* in_sizes, int n_in,
                              void* d_out, int out_size)
{
    const float* x    = (const float*)d_in[0];   // [8, 2048, 512]
    const float* W    = (const float*)d_in[1];   // [512, 1026]
    const float* bias = (const float*)d_in[2];   // [1026]
    float* out = (float*)d_out;                  // [8, 524544]

    cudaFuncSetAttribute(gemm_mma_kernel,
                         cudaFuncAttributeMaxDynamicSharedMemorySize,
                         GEMM_SMEM);

    // 0) prep: bf16 splits + tables/window/envelope
    split_x_kernel<<<(M_TOTAL * K_DIM) / (256 * 8), 256>>>(x);
    prep_w_kernel<<<(N_PAD * K_DIM + 255) / 256, 256>>>(W);
    prep_tables_env_kernel<<<(OUT_FULL + 255) / 256, 256>>>();

    // 1) tensor-core (HMMA) GEMM -> g_h  (2 CTAs/SM)
    dim3 g1(N_PAD / 128, M_TOTAL / 128);   // (9, 128)
    gemm_mma_kernel<<<g1, 256, GEMM_SMEM>>>(bias);

    // 2) spectrum -> radix-8 register irfft -> window -> g_frames
    ifft_kernel<<<M_TOTAL / 4, 256>>>();

    // 3) overlap-add * 1/env -> out (4 outputs per thread)
    int groups = (BATCH * OUT_LEN) / 4;
    ola_kernel<<<(groups + 255) / 256, 256>>>(out);
}

// round 12
// speedup vs baseline: 1.1320x; 1.0499x over previous
#include <cuda_runtime.h>
#include <cuda_bf16.h>
#include <math.h>
#include <stdint.h>

// ---------------------------------------------------------------------------
// Problem constants
// ---------------------------------------------------------------------------
#define BATCH      8
#define T_FRAMES   2048
#define M_TOTAL    (BATCH * T_FRAMES)   // 16384 frames
#define K_DIM      512
#define N_DIM      1026                 // N_FFT + 2
#define N_MAIN     1024                 // 8 x 128 tiles via tensor cores
#define NBINS      513                  // N_FFT/2 + 1
#define NFFT       1024
#define HOP        256
#define PAD        384                  // (1024-256)/2
#define OUT_FULL   ((T_FRAMES - 1) * HOP + NFFT)  // 525312
#define OUT_LEN    (OUT_FULL - 2 * PAD)           // 524544

// ---------------------------------------------------------------------------
// Scratch (device globals: no runtime allocation allowed)
// ---------------------------------------------------------------------------
__device__ float g_h[(size_t)M_TOTAL * N_DIM];        // linear head output (~67 MB)
__device__ float g_frames[(size_t)M_TOTAL * NFFT];    // windowed iFFT frames (~67 MB)
__device__ __nv_bfloat16 g_xhi[(size_t)M_TOTAL * K_DIM];
__device__ __nv_bfloat16 g_xlo[(size_t)M_TOTAL * K_DIM];
__device__ __nv_bfloat16 g_wthi[(size_t)N_MAIN * K_DIM];
__device__ __nv_bfloat16 g_wtlo[(size_t)N_MAIN * K_DIM];
__device__ float g_wtail[2 * K_DIM];    // fp32 W columns 1024,1025 (transposed)
// precomputed tables
__device__ float2 g_tw[512];        // e^{+2*pi*i*j/512},  j<512
__device__ float2 g_pretw[512];     // e^{+2*pi*i*k/1024}, k<512  (packing twiddles)
__device__ float  g_win[NFFT];      // hann window
__device__ float  g_env_inv[OUT_FULL];  // 1 / sum win^2

// ---------------------------------------------------------------------------
// baseline-arch PTX helpers (supported on compute_103 WITHOUT 'a')
// ---------------------------------------------------------------------------
__device__ __forceinline__ uint32_t smem_u32(const void* p) {
    return (uint32_t)__cvta_generic_to_shared(p);
}

__device__ __forceinline__ void cp_async16(uint32_t saddr, const void* gptr) {
    asm volatile("cp.async.cg.shared.global [%0], [%1], 16;"
                 :: "r"(saddr), "l"(gptr));
}
#define CP_COMMIT() asm volatile("cp.async.commit_group;" ::: "memory")
#define CP_WAIT1()  asm volatile("cp.async.wait_group 1;" ::: "memory")

#define LDSM_X4(r0, r1, r2, r3, addr) \
    asm volatile("ldmatrix.sync.aligned.m8n8.x4.shared.b16 {%0,%1,%2,%3}, [%4];" \
                 : "=r"(r0), "=r"(r1), "=r"(r2), "=r"(r3) : "r"(addr))

#define MMA16816(c, a0, a1, a2, a3, b0, b1) \
    asm volatile("mma.sync.aligned.m16n8k16.row.col.f32.bf16.bf16.f32 " \
                 "{%0,%1,%2,%3}, {%4,%5,%6,%7}, {%8,%9}, {%0,%1,%2,%3};" \
                 : "+f"((c)[0]), "+f"((c)[1]), "+f"((c)[2]), "+f"((c)[3]) \
                 : "r"(a0), "r"(a1), "r"(a2), "r"(a3), "r"(b0), "r"(b1))

// ---------------------------------------------------------------------------
// complex helpers
// ---------------------------------------------------------------------------
__device__ __forceinline__ float2 cadd(float2 a, float2 b) { return make_float2(a.x + b.x, a.y + b.y); }
__device__ __forceinline__ float2 csub(float2 a, float2 b) { return make_float2(a.x - b.x, a.y - b.y); }
__device__ __forceinline__ float2 cmul(float2 a, float2 b) {
    return make_float2(a.x * b.x - a.y * b.y, a.x * b.y + a.y * b.x);
}
__device__ __forceinline__ float2 cmuli(float2 a) { return make_float2(-a.y, a.x); }  // * i

// inverse 8-point DFT: X[m] = sum_k c[k] e^{+2*pi*i*k*m/8}
__device__ __forceinline__ void ifft8(const float2 c[8], float2 X[8]) {
    const float r = 0.70710678118654752f;
    float2 t0 = cadd(c[0], c[4]), t1 = csub(c[0], c[4]);
    float2 t2 = cadd(c[2], c[6]), t3 = cmuli(csub(c[2], c[6]));
    float2 E0 = cadd(t0, t2), E1 = cadd(t1, t3), E2 = csub(t0, t2), E3 = csub(t1, t3);
    float2 u0 = cadd(c[1], c[5]), u1 = csub(c[1], c[5]);
    float2 u2 = cadd(c[3], c[7]), u3 = cmuli(csub(c[3], c[7]));
    float2 O0 = cadd(u0, u2), O1 = cadd(u1, u3), O2 = csub(u0, u2), O3 = csub(u1, u3);
    float2 W1 = make_float2(r * (O1.x - O1.y), r * (O1.x + O1.y));
    float2 W2 = cmuli(O2);
    float2 W3 = make_float2(-r * (O3.x + O3.y), r * (O3.x - O3.y));
    X[0] = cadd(E0, O0); X[4] = csub(E0, O0);
    X[1] = cadd(E1, W1); X[5] = csub(E1, W1);
    X[2] = cadd(E2, W2); X[6] = csub(E2, W2);
    X[3] = cadd(E3, W3); X[7] = csub(E3, W3);
}

// ---------------------------------------------------------------------------
// Prep: split x (fp32) into bf16 hi/lo
// ---------------------------------------------------------------------------
__global__ void __launch_bounds__(256)
split_x_kernel(const float* __restrict__ x)
{
    size_t i = ((size_t)blockIdx.x * 256 + threadIdx.x) * 8;
    float4 a = *(const float4*)(x + i);
    float4 b = *(const float4*)(x + i + 4);
    float v[8] = {a.x, a.y, a.z, a.w, b.x, b.y, b.z, b.w};
    union { __nv_bfloat16 h[8]; uint4 u; } H, L;
#pragma unroll
    for (int j = 0; j < 8; j++) {
        __nv_bfloat16 hi = __float2bfloat16(v[j]);
        H.h[j] = hi;
        L.h[j] = __float2bfloat16(v[j] - __bfloat162float(hi));
    }
    *(uint4*)&g_xhi[i] = H.u;
    *(uint4*)&g_xlo[i] = L.u;
}

// ---------------------------------------------------------------------------
// Prep: W [K, 1026] -> Wt hi/lo [1024, 512] bf16 + fp32 tail cols (1024,1025)
// ---------------------------------------------------------------------------
__global__ void __launch_bounds__(256)
prep_w_kernel(const float* __restrict__ W)
{
    int idx = blockIdx.x * 256 + threadIdx.x;       // over N_MAIN * K_DIM
    int n = idx >> 9;          // 0..1023
    int k = idx & 511;
    float v = W[(size_t)k * N_DIM + n];
    __nv_bfloat16 hi = __float2bfloat16(v);
    g_wthi[idx] = hi;
    g_wtlo[idx] = __float2bfloat16(v - __bfloat162float(hi));
    // tail columns: block 0 extracts W[:,1024:1026] transposed, fp32
    if (blockIdx.x == 0) {
        int tid = threadIdx.x;
        for (int i = tid; i < 2 * K_DIM; i += 256) {
            int j  = i >> 9;           // 0/1
            int kk = i & 511;
            g_wtail[i] = W[(size_t)kk * N_DIM + 1024 + j];
        }
    }
}

// ---------------------------------------------------------------------------
// Prep: trig tables + window + envelope reciprocal (merged)
// ---------------------------------------------------------------------------
__global__ void __launch_bounds__(256)
prep_tables_env_kernel()
{
    int i = blockIdx.x * 256 + threadIdx.x;
    float s, c;
    if (i < 512) {                               // e^{2*pi*i*j/512}
        sincospif((float)i * (1.0f / 256.0f), &s, &c);
        g_tw[i] = make_float2(c, s);
    }
    if (i < 512) {                               // e^{2*pi*i*k/1024}
        sincospif((float)i * (1.0f / 512.0f), &s, &c);
        g_pretw[i] = make_float2(c, s);
    }
    if (i < NFFT) {
        g_win[i] = 0.5f * (1.0f - cospif((float)i * (1.0f / 512.0f)));
    }
    if (i < OUT_FULL) {
        int m = i;
        int t_hi = m >> 8;
        if (t_hi > T_FRAMES - 1) t_hi = T_FRAMES - 1;
        int t_lo = (m >= (NFFT - HOP)) ? ((m - (NFFT - HOP)) >> 8) : 0;
        float env = 0.0f;
        for (int t = t_lo; t <= t_hi; t++) {
            int n = m - (t << 8);
            float win = 0.5f * (1.0f - cospif((float)n * (1.0f / 512.0f)));
            env += win * win;
        }
        g_env_inv[m] = (env > 0.0f) ? (1.0f / env) : 0.0f;
    }
}

// ---------------------------------------------------------------------------
// Kernel 1a: HMMA GEMM  h[:, :1024] = x @ W[:, :1024] + b  (3x-bf16 split).
// CTA tile 128x128, BK=32, 3-stage cp.async, 8 warps (64x32), 2 CTAs/SM.
// ---------------------------------------------------------------------------
#define MAT_BYTES   8192                  // 128 rows x 64 B
#define STAGE_BYTES (4 * MAT_BYTES)       // 32768 (Ah, Al, Bh, Bl)
#define N_STAGES    3
#define GEMM_SMEM   (N_STAGES * STAGE_BYTES)   // 98304
#define N_CHUNKS_K  (K_DIM / 32)          // 16
#define OFF_AH 0
#define OFF_AL MAT_BYTES
#define OFF_BH (2 * MAT_BYTES)
#define OFF_BL (3 * MAT_BYTES)

// byte offset of (row, 16B-granule g in 0..3) within a 64B-row matrix tile
#define SWZ(row, g) (((row) << 6) + ((((g) ^ (((row) >> 1) & 3))) << 4))

__device__ __forceinline__ void load_stage(uint32_t sdst,
                                           const __nv_bfloat16* pAh,
                                           const __nv_bfloat16* pAl,
                                           const __nv_bfloat16* pBh,
                                           const __nv_bfloat16* pBl,
                                           int k0, int tid)
{
#pragma unroll
    for (int t = 0; t < 2; t++) {
        int idx = tid + (t << 8);
        int row = idx >> 2;
        int g   = idx & 3;
        uint32_t soff = SWZ(row, g);
        size_t goff = (size_t)row * K_DIM + k0 + (g << 3);
        cp_async16(sdst + OFF_AH + soff, pAh + goff);
        cp_async16(sdst + OFF_AL + soff, pAl + goff);
        cp_async16(sdst + OFF_BH + soff, pBh + goff);
        cp_async16(sdst + OFF_BL + soff, pBl + goff);
    }
}

__global__ void __launch_bounds__(256, 2)
gemm_mma_kernel(const float* __restrict__ bias)
{
    extern __shared__ __align__(128) char smem[];
    const int tid  = threadIdx.x;
    const int lane = tid & 31;
    const int warp = tid >> 5;
    const int wm   = (warp >> 2) << 6;   // 0 / 64
    const int wn   = (warp & 3) << 5;    // 0,32,64,96
    const int bm   = blockIdx.y << 7;    // 128-row tiles
    const int bn   = blockIdx.x << 7;    // 128-col tiles
    const uint32_t sbase = smem_u32(smem);

    const __nv_bfloat16* pAh = g_xhi  + (size_t)bm * K_DIM;
    const __nv_bfloat16* pAl = g_xlo  + (size_t)bm * K_DIM;
    const __nv_bfloat16* pBh = g_wthi + (size_t)bn * K_DIM;
    const __nv_bfloat16* pBl = g_wtlo + (size_t)bn * K_DIM;

    float acc[4][4][4];
#pragma unroll
    for (int i = 0; i < 4; i++)
#pragma unroll
        for (int j = 0; j < 4; j++)
#pragma unroll
            for (int r = 0; r < 4; r++) acc[i][j][r] = 0.0f;

    const int a_row  = wm + (lane & 15);
    const int a_gadd = (lane >> 4);          // 0/1
    const int b_row  = wn + (lane & 7) + ((lane >> 4) << 3);
    const int b_gadd = ((lane >> 3) & 1);

    // prologue: 2 stages in flight
    load_stage(sbase + 0 * STAGE_BYTES, pAh, pAl, pBh, pBl,  0, tid); CP_COMMIT();
    load_stage(sbase + 1 * STAGE_BYTES, pAh, pAl, pBh, pBl, 32, tid); CP_COMMIT();

    int buf = 0;
    for (int ck = 0; ck < N_CHUNKS_K; ck++) {
        CP_WAIT1();                        // stage ck landed (1 still flying)
        __syncthreads();
        if (ck + 2 < N_CHUNKS_K) {
            int nb = buf + 2; if (nb >= N_STAGES) nb -= N_STAGES;
            load_stage(sbase + nb * STAGE_BYTES,
                       pAh, pAl, pBh, pBl, (ck + 2) << 5, tid);
        }
        CP_COMMIT();                       // commit (possibly empty) group

        const uint32_t stg = sbase + buf * STAGE_BYTES;
        if (++buf == N_STAGES) buf = 0;

#pragma unroll
        for (int s16 = 0; s16 < 2; s16++) {
            const int g0 = (s16 << 1);
            uint32_t a[4][4], bh[2][4], bl[2][4];

            // B(hi), B(lo): 2+2 ldmatrix.x4 covering 32 cols
#pragma unroll
            for (int j2 = 0; j2 < 2; j2++) {
                int row = b_row + (j2 << 4);
                int g   = g0 + b_gadd;
                uint32_t boff = SWZ(row, g);
                LDSM_X4(bh[j2][0], bh[j2][1], bh[j2][2], bh[j2][3],
                        stg + OFF_BH + boff);
                LDSM_X4(bl[j2][0], bl[j2][1], bl[j2][2], bl[j2][3],
                        stg + OFF_BL + boff);
            }
            // A(hi)
#pragma unroll
            for (int i = 0; i < 4; i++) {
                int row = a_row + (i << 4);
                int g   = g0 + a_gadd;
                uint32_t addr = stg + OFF_AH + SWZ(row, g);
                LDSM_X4(a[i][0], a[i][1], a[i][2], a[i][3], addr);
            }
            // pass 1: Ah x Bh
#pragma unroll
            for (int i = 0; i < 4; i++)
#pragma unroll
                for (int j = 0; j < 4; j++)
                    MMA16816(acc[i][j], a[i][0], a[i][1], a[i][2], a[i][3],
                             bh[j >> 1][(j & 1) << 1], bh[j >> 1][((j & 1) << 1) + 1]);
            // pass 2: Ah x Bl
#pragma unroll
            for (int i = 0; i < 4; i++)
#pragma unroll
                for (int j = 0; j < 4; j++)
                    MMA16816(acc[i][j], a[i][0], a[i][1], a[i][2], a[i][3],
                             bl[j >> 1][(j & 1) << 1], bl[j >> 1][((j & 1) << 1) + 1]);
            // A(lo) (reuse regs)
#pragma unroll
            for (int i = 0; i < 4; i++) {
                int row = a_row + (i << 4);
                int g   = g0 + a_gadd;
                uint32_t addr = stg + OFF_AL + SWZ(row, g);
                LDSM_X4(a[i][0], a[i][1], a[i][2], a[i][3], addr);
            }
            // pass 3: Al x Bh
#pragma unroll
            for (int i = 0; i < 4; i++)
#pragma unroll
                for (int j = 0; j < 4; j++)
                    MMA16816(acc[i][j], a[i][0], a[i][1], a[i][2], a[i][3],
                             bh[j >> 1][(j & 1) << 1], bh[j >> 1][((j & 1) << 1) + 1]);
        }
    }

    // epilogue: bias + direct float2 stores (all cols < 1024 < N_DIM: no guard)
    const int r0 = bm + wm + (lane >> 2);
    const int c0 = bn + wn + ((lane & 3) << 1);
#pragma unroll
    for (int j = 0; j < 4; j++) {
        int col = c0 + (j << 3);
        float bx = bias[col];
        float by = bias[col + 1];
#pragma unroll
        for (int i = 0; i < 4; i++) {
            int row = r0 + (i << 4);
            *(float2*)&g_h[(size_t)row * N_DIM + col] =
                make_float2(acc[i][j][0] + bx, acc[i][j][1] + by);
            *(float2*)&g_h[(size_t)(row + 8) * N_DIM + col] =
                make_float2(acc[i][j][2] + bx, acc[i][j][3] + by);
        }
    }
}

// ---------------------------------------------------------------------------
// Kernel 1b: fp32 GEMV for tail columns 1024..1025 (one warp per row).
// ---------------------------------------------------------------------------
__global__ void __launch_bounds__(256)
gemv_tail_kernel(const float* __restrict__ x, const float* __restrict__ bias)
{
    __shared__ float w0[K_DIM], w1[K_DIM];
    const int tid  = threadIdx.x;
    const int warp = tid >> 5;
    const int lane = tid & 31;

    for (int i = tid; i < K_DIM; i += 256) {
        w0[i] = g_wtail[i];
        w1[i] = g_wtail[K_DIM + i];
    }
    __syncthreads();

    const int m = (blockIdx.x << 3) + warp;
    const float* __restrict__ xr = x + (size_t)m * K_DIM;
    float a0 = 0.0f, a1 = 0.0f;
#pragma unroll
    for (int p = 0; p < 4; p++) {
        int k = (p << 7) + (lane << 2);
        float4 v = *(const float4*)&xr[k];
        a0 += v.x * w0[k] + v.y * w0[k + 1] + v.z * w0[k + 2] + v.w * w0[k + 3];
        a1 += v.x * w1[k] + v.y * w1[k + 1] + v.z * w1[k + 2] + v.w * w1[k + 3];
    }
#pragma unroll
    for (int off = 16; off > 0; off >>= 1) {
        a0 += __shfl_down_sync(0xFFFFFFFFu, a0, off);
        a1 += __shfl_down_sync(0xFFFFFFFFu, a1, off);
    }
    if (lane == 0) {
        g_h[(size_t)m * N_DIM + 1024] = a0 + bias[1024];
        g_h[(size_t)m * N_DIM + 1025] = a1 + bias[1025];
    }
}

// ---------------------------------------------------------------------------
// Kernel 2: spectrum -> 512-pt inverse FFT as 3x radix-8 register passes
// (2 smem transposes, 64 threads/frame, 4 frames/block) -> window -> frames.
// ---------------------------------------------------------------------------
__global__ void __launch_bounds__(256)
ifft_kernel()
{
    __shared__ float2 s_spec[4][513];   // packed spectrum per frame
    __shared__ float2 s_buf[4][540];    // transpose buffer per frame
    __shared__ float2 s_tw[512];        // e^{2*pi*i*j/512}

    const int tid = threadIdx.x;
    const int fid = tid >> 6;                      // frame within block
    const int t   = tid & 63;                      // thread within frame
    const int f   = (blockIdx.x << 2) + fid;       // global frame id
    const float* __restrict__ h = g_h + (size_t)f * N_DIM;

    s_tw[tid]       = g_tw[tid];
    s_tw[tid + 256] = g_tw[tid + 256];

    // spectrum: S_k = min(exp(h_k),100) * (cos p_k + i sin p_k)
    for (int k = t; k <= 512; k += 64) {
        float mag = fminf(__expf(h[k]), 100.0f);
        float s, c;
        __sincosf(h[NBINS + k], &s, &c);
        if (k == 0 || k == 512) s = 0.0f;          // irfft ignores Im of DC/Nyquist
        s_spec[fid][k] = make_float2(mag * c, mag * s);
    }
    __syncthreads();

    // ---- pass A: pack + IFFT8 over k1 (k2 = t) ----
    {
        float2 c[8];
#pragma unroll
        for (int k1 = 0; k1 < 8; k1++) {
            int k = (k1 << 6) + t;
            float2 Xk = s_spec[fid][k];
            float2 Xr = s_spec[fid][512 - k];
            float Ex = 0.5f * (Xk.x + Xr.x);
            float Ey = 0.5f * (Xk.y - Xr.y);
            float Dx = 0.5f * (Xk.x - Xr.x);
            float Dy = 0.5f * (Xk.y + Xr.y);
            float2 w = g_pretw[k];
            c[k1] = make_float2(Ex - (w.x * Dy + w.y * Dx),
                                Ey + (w.x * Dx - w.y * Dy));
        }
        float2 X[8];
        ifft8(c, X);
#pragma unroll
        for (int n1 = 1; n1 < 8; n1++) X[n1] = cmul(X[n1], s_tw[t * n1]);
        const int base = (t >> 3) * 68 + (t & 7);
#pragma unroll
        for (int n1 = 0; n1 < 8; n1++) s_buf[fid][base + (n1 << 3)] = X[n1];
    }
    __syncthreads();

    // ---- pass B: IFFT8 over j1, thread = (n1, j2) ----
    {
        const int n1 = t >> 3, j2 = t & 7;
        float2 y[8];
#pragma unroll
        for (int j1 = 0; j1 < 8; j1++) y[j1] = s_buf[fid][j1 * 68 + (n1 << 3) + j2];
        __syncthreads();                          // reads done before in-place writes
        float2 V[8];
        ifft8(y, V);
#pragma unroll
        for (int m1 = 1; m1 < 8; m1++) V[m1] = cmul(V[m1], s_tw[((j2 * m1) << 3)]);
        const int base = j2 * 66 + (n1 << 3);
#pragma unroll
        for (int m1 = 0; m1 < 8; m1++) s_buf[fid][base + m1] = V[m1];
    }
    __syncthreads();

    // ---- pass C: IFFT8 over j2, thread = (n1, m1); scale + window + store ----
    {
        const int n1 = t >> 3, m1 = t & 7;
        float2 d[8];
#pragma unroll
        for (int j2 = 0; j2 < 8; j2++) d[j2] = s_buf[fid][j2 * 66 + (n1 << 3) + m1];
        float2 X[8];
        ifft8(d, X);
        const float inv = 1.0f / 512.0f;
        float* __restrict__ fr = g_frames + (size_t)f * NFFT;
        const int nb = n1 + (m1 << 3);
#pragma unroll
        for (int m2 = 0; m2 < 8; m2++) {
            int n = nb + (m2 << 6);
            float2 w2 = *(const float2*)&g_win[2 * n];
            *(float2*)&fr[2 * n] = make_float2(X[m2].x * inv * w2.x,
                                               X[m2].y * inv * w2.y);
        }
    }
}

// ---------------------------------------------------------------------------
// Kernel 3: overlap-add, 4 outputs/thread, float4 loads, precomputed 1/env.
// Interior samples always have exactly 4 taps -> unrolled fast path.
// ---------------------------------------------------------------------------
__global__ void __launch_bounds__(256)
ola_kernel(float* __restrict__ out)
{
    int g = blockIdx.x * blockDim.x + threadIdx.x;       // group id
    if (g >= (BATCH * OUT_LEN) / 4) return;
    int b   = g / (OUT_LEN / 4);
    int mo0 = (g - b * (OUT_LEN / 4)) << 2;
    int m0  = mo0 + PAD;

    int t_hi = m0 >> 8;
    if (t_hi > T_FRAMES - 1) t_hi = T_FRAMES - 1;
    int t_lo = (m0 >= (NFFT - HOP)) ? ((m0 - (NFFT - HOP)) >> 8) : 0;

    float4 acc = make_float4(0.0f, 0.0f, 0.0f, 0.0f);
    const float* __restrict__ base = g_frames + (size_t)b * T_FRAMES * NFFT;
    if (t_hi - t_lo == 3) {
#pragma unroll
        for (int d = 0; d < 4; d++) {
            int t = t_lo + d;
            float4 v = *(const float4*)(base + (size_t)t * NFFT + (m0 - (t << 8)));
            acc.x += v.x; acc.y += v.y; acc.z += v.z; acc.w += v.w;
        }
    } else {
        for (int t = t_lo; t <= t_hi; t++) {
            float4 v = *(const float4*)(base + (size_t)t * NFFT + (m0 - (t << 8)));
            acc.x += v.x; acc.y += v.y; acc.z += v.z; acc.w += v.w;
        }
    }
    float4 e = *(const float4*)&g_env_inv[m0];
    *(float4*)&out[(size_t)b * OUT_LEN + mo0] =
        make_float4(acc.x * e.x, acc.y * e.y, acc.z * e.z, acc.w * e.w);
}

// ---------------------------------------------------------------------------
// Launch
// ---------------------------------------------------------------------------
extern "C" void kernel_launch(void* const* d_in, const int* in_sizes, int n_in,
                              void* d_out, int out_size)
{
    const float* x    = (const float*)d_in[0];   // [8, 2048, 512]
    const float* W    = (const float*)d_in[1];   // [512, 1026]
    const float* bias = (const float*)d_in[2];   // [1026]
    float* out = (float*)d_out;                  // [8, 524544]

    cudaFuncSetAttribute(gemm_mma_kernel,
                         cudaFuncAttributeMaxDynamicSharedMemorySize,
                         GEMM_SMEM);

    // 0) prep: bf16 splits + tables/window/envelope
    split_x_kernel<<<(M_TOTAL * K_DIM) / (256 * 8), 256>>>(x);
    prep_w_kernel<<<(N_MAIN * K_DIM) / 256, 256>>>(W);
    prep_tables_env_kernel<<<(OUT_FULL + 255) / 256, 256>>>();

    // 1a) tensor-core (HMMA) GEMM over N=1024 -> g_h  (2 CTAs/SM)
    dim3 g1(N_MAIN / 128, M_TOTAL / 128);   // (8, 128)
    gemm_mma_kernel<<<g1, 256, GEMM_SMEM>>>(bias);

    // 1b) fp32 GEMV for tail columns 1024..1025
    gemv_tail_kernel<<<M_TOTAL / 8, 256>>>(x, bias);

    // 2) spectrum -> radix-8 register irfft -> window -> g_frames
    ifft_kernel<<<M_TOTAL / 4, 256>>>();

    // 3) overlap-add * 1/env -> out (4 outputs per thread)
    int groups = (BATCH * OUT_LEN) / 4;
    ola_kernel<<<(groups + 255) / 256, 256>>>(out);
}

// round 13
// speedup vs baseline: 1.2691x; 1.1211x over previous
#include <cuda_runtime.h>
#include <cuda_bf16.h>
#include <math.h>
#include <stdint.h>

// ---------------------------------------------------------------------------
// Problem constants
// ---------------------------------------------------------------------------
#define BATCH      8
#define T_FRAMES   2048
#define M_TOTAL    (BATCH * T_FRAMES)   // 16384 frames
#define K_DIM      512
#define N_DIM      1026                 // N_FFT + 2
#define N_MAIN     1024                 // 8 x 128 tiles via tensor cores
#define NBINS      513                  // N_FFT/2 + 1
#define NFFT       1024
#define HOP        256
#define PAD        384                  // (1024-256)/2
#define OUT_FULL   ((T_FRAMES - 1) * HOP + NFFT)  // 525312
#define OUT_LEN    (OUT_FULL - 2 * PAD)           // 524544

// ---------------------------------------------------------------------------
// Scratch (device globals: no runtime allocation allowed)
// ---------------------------------------------------------------------------
__device__ float g_h[(size_t)M_TOTAL * N_DIM];        // linear head output (~67 MB)
__device__ float g_frames[(size_t)M_TOTAL * NFFT];    // windowed iFFT frames (~67 MB)
__device__ float g_wt[(size_t)N_MAIN * K_DIM];        // W^T, tf32-rounded fp32 (2 MB)
__device__ float g_wtail[2 * K_DIM];    // fp32 W columns 1024,1025 (transposed)
// precomputed tables
__device__ float2 g_tw[512];        // e^{+2*pi*i*j/512},  j<512
__device__ float2 g_pretw[512];     // e^{+2*pi*i*k/1024}, k<512  (packing twiddles)
__device__ float  g_win[NFFT];      // hann window
__device__ float  g_env_inv[OUT_FULL];  // 1 / sum win^2

// ---------------------------------------------------------------------------
// baseline-arch PTX helpers (supported on compute_103 WITHOUT 'a')
// ---------------------------------------------------------------------------
__device__ __forceinline__ uint32_t smem_u32(const void* p) {
    return (uint32_t)__cvta_generic_to_shared(p);
}

__device__ __forceinline__ void cp_async16(uint32_t saddr, const void* gptr) {
    asm volatile("cp.async.cg.shared.global [%0], [%1], 16;"
                 :: "r"(saddr), "l"(gptr));
}
#define CP_COMMIT() asm volatile("cp.async.commit_group;" ::: "memory")
#define CP_WAIT1()  asm volatile("cp.async.wait_group 1;" ::: "memory")

// LDS fp32 + round-to-nearest tf32 (returns tf32 bit pattern in a b32 reg)
__device__ __forceinline__ uint32_t lds_tf32(uint32_t addr) {
    float v;
    asm volatile("ld.shared.f32 %0, [%1];" : "=f"(v) : "r"(addr));
    uint32_t t;
    asm volatile("cvt.rna.tf32.f32 %0, %1;" : "=r"(t) : "f"(v));
    return t;
}
__device__ __forceinline__ uint32_t lds_b32(uint32_t addr) {
    uint32_t v;
    asm volatile("ld.shared.b32 %0, [%1];" : "=r"(v) : "r"(addr));
    return v;
}

#define MMATF32(c, a0, a1, a2, a3, b0, b1) \
    asm volatile("mma.sync.aligned.m16n8k8.row.col.f32.tf32.tf32.f32 " \
                 "{%0,%1,%2,%3}, {%4,%5,%6,%7}, {%8,%9}, {%0,%1,%2,%3};" \
                 : "+f"((c)[0]), "+f"((c)[1]), "+f"((c)[2]), "+f"((c)[3]) \
                 : "r"(a0), "r"(a1), "r"(a2), "r"(a3), "r"(b0), "r"(b1))

// ---------------------------------------------------------------------------
// complex helpers
// ---------------------------------------------------------------------------
__device__ __forceinline__ float2 cadd(float2 a, float2 b) { return make_float2(a.x + b.x, a.y + b.y); }
__device__ __forceinline__ float2 csub(float2 a, float2 b) { return make_float2(a.x - b.x, a.y - b.y); }
__device__ __forceinline__ float2 cmul(float2 a, float2 b) {
    return make_float2(a.x * b.x - a.y * b.y, a.x * b.y + a.y * b.x);
}
__device__ __forceinline__ float2 cmuli(float2 a) { return make_float2(-a.y, a.x); }  // * i

// inverse 8-point DFT: X[m] = sum_k c[k] e^{+2*pi*i*k*m/8}
__device__ __forceinline__ void ifft8(const float2 c[8], float2 X[8]) {
    const float r = 0.70710678118654752f;
    float2 t0 = cadd(c[0], c[4]), t1 = csub(c[0], c[4]);
    float2 t2 = cadd(c[2], c[6]), t3 = cmuli(csub(c[2], c[6]));
    float2 E0 = cadd(t0, t2), E1 = cadd(t1, t3), E2 = csub(t0, t2), E3 = csub(t1, t3);
    float2 u0 = cadd(c[1], c[5]), u1 = csub(c[1], c[5]);
    float2 u2 = cadd(c[3], c[7]), u3 = cmuli(csub(c[3], c[7]));
    float2 O0 = cadd(u0, u2), O1 = cadd(u1, u3), O2 = csub(u0, u2), O3 = csub(u1, u3);
    float2 W1 = make_float2(r * (O1.x - O1.y), r * (O1.x + O1.y));
    float2 W2 = cmuli(O2);
    float2 W3 = make_float2(-r * (O3.x + O3.y), r * (O3.x - O3.y));
    X[0] = cadd(E0, O0); X[4] = csub(E0, O0);
    X[1] = cadd(E1, W1); X[5] = csub(E1, W1);
    X[2] = cadd(E2, W2); X[6] = csub(E2, W2);
    X[3] = cadd(E3, W3); X[7] = csub(E3, W3);
}

// ---------------------------------------------------------------------------
// Prep: W [K, 1026] -> g_wt [1024][512] tf32-rounded fp32 + fp32 tail cols
// ---------------------------------------------------------------------------
__global__ void __launch_bounds__(256)
prep_w_kernel(const float* __restrict__ W)
{
    int idx = blockIdx.x * 256 + threadIdx.x;       // over N_MAIN * K_DIM
    int n = idx >> 9;          // 0..1023
    int k = idx & 511;
    float v = W[(size_t)k * N_DIM + n];
    uint32_t t;
    asm("cvt.rna.tf32.f32 %0, %1;" : "=r"(t) : "f"(v));
    g_wt[idx] = __uint_as_float(t);
    // tail columns: block 0 extracts W[:,1024:1026] transposed, fp32
    if (blockIdx.x == 0) {
        int tid = threadIdx.x;
        for (int i = tid; i < 2 * K_DIM; i += 256) {
            int j  = i >> 9;           // 0/1
            int kk = i & 511;
            g_wtail[i] = W[(size_t)kk * N_DIM + 1024 + j];
        }
    }
}

// ---------------------------------------------------------------------------
// Prep: trig tables + window + envelope reciprocal (merged)
// ---------------------------------------------------------------------------
__global__ void __launch_bounds__(256)
prep_tables_env_kernel()
{
    int i = blockIdx.x * 256 + threadIdx.x;
    float s, c;
    if (i < 512) {                               // e^{2*pi*i*j/512}
        sincospif((float)i * (1.0f / 256.0f), &s, &c);
        g_tw[i] = make_float2(c, s);
    }
    if (i < 512) {                               // e^{2*pi*i*k/1024}
        sincospif((float)i * (1.0f / 512.0f), &s, &c);
        g_pretw[i] = make_float2(c, s);
    }
    if (i < NFFT) {
        g_win[i] = 0.5f * (1.0f - cospif((float)i * (1.0f / 512.0f)));
    }
    if (i < OUT_FULL) {
        int m = i;
        int t_hi = m >> 8;
        if (t_hi > T_FRAMES - 1) t_hi = T_FRAMES - 1;
        int t_lo = (m >= (NFFT - HOP)) ? ((m - (NFFT - HOP)) >> 8) : 0;
        float env = 0.0f;
        for (int t = t_lo; t <= t_hi; t++) {
            int n = m - (t << 8);
            float win = 0.5f * (1.0f - cospif((float)n * (1.0f / 512.0f)));
            env += win * win;
        }
        g_env_inv[m] = (env > 0.0f) ? (1.0f / env) : 0.0f;
    }
}

// ---------------------------------------------------------------------------
// Kernel 1a: single-pass TF32 GEMM  h[:, :1024] = x @ W[:, :1024] + b.
// CTA tile 128x128, BK=32, 3-stage cp.async, 8 warps (64x32), 2 CTAs/SM.
// A = raw fp32 x (tf32-rounded in-register via cvt.rna); B pre-rounded.
// SMEM: fp32 tiles, 128B rows of 8x16B granules, xor swizzle g^=row&7.
// ---------------------------------------------------------------------------
#define MAT_BYTES   16384                 // 128 rows x 128 B (32 fp32)
#define STAGE_BYTES (2 * MAT_BYTES)       // 32768 (A, B)
#define N_STAGES    3
#define GEMM_SMEM   (N_STAGES * STAGE_BYTES)   // 98304
#define N_CHUNKS_K  (K_DIM / 32)          // 16
#define OFF_A 0
#define OFF_B MAT_BYTES

// byte offset of (row, 16B-granule g in 0..7) within a 128B-row fp32 tile
#define SWZ(row, g) (((row) << 7) + ((((g) ^ ((row) & 7))) << 4))

__device__ __forceinline__ void load_stage(uint32_t sdst,
                                           const float* pA, const float* pB,
                                           int k0, int tid)
{
    // each matrix: 128 rows x 8 granules = 1024 transfers (4 iters of 256)
#pragma unroll
    for (int t = 0; t < 4; t++) {
        int idx = tid + (t << 8);
        int row = idx >> 3;
        int g   = idx & 7;
        uint32_t soff = SWZ(row, g);
        size_t goff = (size_t)row * K_DIM + k0 + (g << 2);
        cp_async16(sdst + OFF_A + soff, pA + goff);
        cp_async16(sdst + OFF_B + soff, pB + goff);
    }
}

__global__ void __launch_bounds__(256, 2)
gemm_mma_kernel(const float* __restrict__ x, const float* __restrict__ bias)
{
    extern __shared__ __align__(128) char smem[];
    const int tid  = threadIdx.x;
    const int lane = tid & 31;
    const int warp = tid >> 5;
    const int wm   = (warp >> 2) << 6;   // 0 / 64
    const int wn   = (warp & 3) << 5;    // 0,32,64,96
    const int bm   = blockIdx.y << 7;    // 128-row tiles
    const int bn   = blockIdx.x << 7;    // 128-col tiles
    const uint32_t sbase = smem_u32(smem);

    const float* pA = x    + (size_t)bm * K_DIM;
    const float* pB = g_wt + (size_t)bn * K_DIM;

    float acc[4][4][4];
#pragma unroll
    for (int i = 0; i < 4; i++)
#pragma unroll
        for (int j = 0; j < 4; j++)
#pragma unroll
            for (int r = 0; r < 4; r++) acc[i][j][r] = 0.0f;

    // per-thread fragment addressing (row&7 pattern constant across tiles)
    const int qr = lane >> 2;            // quad row 0..7 (also xor key e)
    const int qc = lane & 3;             // 0..3
    // A: row base = wm + qr (+16*i, +8); col = kb + qc (+4)
    const uint32_t aBase = (uint32_t)((wm + qr) << 7) + (qc << 2);
    // B: row base = wn + qr (+8*j); col = kb + qc (+4)
    const uint32_t bBase = (uint32_t)((wn + qr) << 7) + (qc << 2);

    // prologue: 2 stages in flight
    load_stage(sbase + 0 * STAGE_BYTES, pA, pB,  0, tid); CP_COMMIT();
    load_stage(sbase + 1 * STAGE_BYTES, pA, pB, 32, tid); CP_COMMIT();

    int buf = 0;
    for (int ck = 0; ck < N_CHUNKS_K; ck++) {
        CP_WAIT1();                        // stage ck landed (1 still flying)
        __syncthreads();
        if (ck + 2 < N_CHUNKS_K) {
            int nb = buf + 2; if (nb >= N_STAGES) nb -= N_STAGES;
            load_stage(sbase + nb * STAGE_BYTES, pA, pB, (ck + 2) << 5, tid);
        }
        CP_COMMIT();                       // commit (possibly empty) group

        const uint32_t stg = sbase + buf * STAGE_BYTES;
        if (++buf == N_STAGES) buf = 0;

#pragma unroll
        for (int s8 = 0; s8 < 4; s8++) {
            const int kb = s8 << 3;
            // swizzled granule offsets for k-cols kb..kb+3 and kb+4..kb+7
            const uint32_t off0 = (uint32_t)(((kb >> 2) ^ qr) << 4);
            const uint32_t off1 = (uint32_t)((((kb >> 2) + 1) ^ qr) << 4);

            uint32_t a[4][4], b[4][2];
#pragma unroll
            for (int i = 0; i < 4; i++) {
                uint32_t ra = stg + OFF_A + aBase + (uint32_t)(i << 11);
                a[i][0] = lds_tf32(ra + off0);           // (r,   c)
                a[i][1] = lds_tf32(ra + 1024 + off0);    // (r+8, c)
                a[i][2] = lds_tf32(ra + off1);           // (r,   c+4)
                a[i][3] = lds_tf32(ra + 1024 + off1);    // (r+8, c+4)
            }
#pragma unroll
            for (int j = 0; j < 4; j++) {
                uint32_t rb = stg + OFF_B + bBase + (uint32_t)(j << 10);
                b[j][0] = lds_b32(rb + off0);            // (k,   n)
                b[j][1] = lds_b32(rb + off1);            // (k+4, n)
            }
#pragma unroll
            for (int i = 0; i < 4; i++)
#pragma unroll
                for (int j = 0; j < 4; j++)
                    MMATF32(acc[i][j], a[i][0], a[i][1], a[i][2], a[i][3],
                            b[j][0], b[j][1]);
        }
    }

    // epilogue: bias + direct float2 stores (all cols < 1024 < N_DIM)
    const int r0 = bm + wm + (lane >> 2);
    const int c0 = bn + wn + ((lane & 3) << 1);
#pragma unroll
    for (int j = 0; j < 4; j++) {
        int col = c0 + (j << 3);
        float bx = bias[col];
        float by = bias[col + 1];
#pragma unroll
        for (int i = 0; i < 4; i++) {
            int row = r0 + (i << 4);
            *(float2*)&g_h[(size_t)row * N_DIM + col] =
                make_float2(acc[i][j][0] + bx, acc[i][j][1] + by);
            *(float2*)&g_h[(size_t)(row + 8) * N_DIM + col] =
                make_float2(acc[i][j][2] + bx, acc[i][j][3] + by);
        }
    }
}

// ---------------------------------------------------------------------------
// Kernel 1b: fp32 GEMV for tail columns 1024..1025 (one warp per row).
// ---------------------------------------------------------------------------
__global__ void __launch_bounds__(256)
gemv_tail_kernel(const float* __restrict__ x, const float* __restrict__ bias)
{
    __shared__ float w0[K_DIM], w1[K_DIM];
    const int tid  = threadIdx.x;
    const int warp = tid >> 5;
    const int lane = tid & 31;

    for (int i = tid; i < K_DIM; i += 256) {
        w0[i] = g_wtail[i];
        w1[i] = g_wtail[K_DIM + i];
    }
    __syncthreads();

    const int m = (blockIdx.x << 3) + warp;
    const float* __restrict__ xr = x + (size_t)m * K_DIM;
    float a0 = 0.0f, a1 = 0.0f;
#pragma unroll
    for (int p = 0; p < 4; p++) {
        int k = (p << 7) + (lane << 2);
        float4 v = *(const float4*)&xr[k];
        a0 += v.x * w0[k] + v.y * w0[k + 1] + v.z * w0[k + 2] + v.w * w0[k + 3];
        a1 += v.x * w1[k] + v.y * w1[k + 1] + v.z * w1[k + 2] + v.w * w1[k + 3];
    }
#pragma unroll
    for (int off = 16; off > 0; off >>= 1) {
        a0 += __shfl_down_sync(0xFFFFFFFFu, a0, off);
        a1 += __shfl_down_sync(0xFFFFFFFFu, a1, off);
    }
    if (lane == 0) {
        g_h[(size_t)m * N_DIM + 1024] = a0 + bias[1024];
        g_h[(size_t)m * N_DIM + 1025] = a1 + bias[1025];
    }
}

// ---------------------------------------------------------------------------
// Kernel 2: spectrum -> 512-pt inverse FFT as 3x radix-8 register passes
// (2 smem transposes, 64 threads/frame, 4 frames/block) -> window -> frames.
// ---------------------------------------------------------------------------
__global__ void __launch_bounds__(256)
ifft_kernel()
{
    __shared__ float2 s_spec[4][513];   // packed spectrum per frame
    __shared__ float2 s_buf[4][540];    // transpose buffer per frame
    __shared__ float2 s_tw[512];        // e^{2*pi*i*j/512}

    const int tid = threadIdx.x;
    const int fid = tid >> 6;                      // frame within block
    const int t   = tid & 63;                      // thread within frame
    const int f   = (blockIdx.x << 2) + fid;       // global frame id
    const float* __restrict__ h = g_h + (size_t)f * N_DIM;

    s_tw[tid]       = g_tw[tid];
    s_tw[tid + 256] = g_tw[tid + 256];

    // spectrum: S_k = min(exp(h_k),100) * (cos p_k + i sin p_k)
    for (int k = t; k <= 512; k += 64) {
        float mag = fminf(__expf(h[k]), 100.0f);
        float s, c;
        __sincosf(h[NBINS + k], &s, &c);
        if (k == 0 || k == 512) s = 0.0f;          // irfft ignores Im of DC/Nyquist
        s_spec[fid][k] = make_float2(mag * c, mag * s);
    }
    __syncthreads();

    // ---- pass A: pack + IFFT8 over k1 (k2 = t) ----
    {
        float2 c[8];
#pragma unroll
        for (int k1 = 0; k1 < 8; k1++) {
            int k = (k1 << 6) + t;
            float2 Xk = s_spec[fid][k];
            float2 Xr = s_spec[fid][512 - k];
            float Ex = 0.5f * (Xk.x + Xr.x);
            float Ey = 0.5f * (Xk.y - Xr.y);
            float Dx = 0.5f * (Xk.x - Xr.x);
            float Dy = 0.5f * (Xk.y + Xr.y);
            float2 w = g_pretw[k];
            c[k1] = make_float2(Ex - (w.x * Dy + w.y * Dx),
                                Ey + (w.x * Dx - w.y * Dy));
        }
        float2 X[8];
        ifft8(c, X);
#pragma unroll
        for (int n1 = 1; n1 < 8; n1++) X[n1] = cmul(X[n1], s_tw[t * n1]);
        const int base = (t >> 3) * 68 + (t & 7);
#pragma unroll
        for (int n1 = 0; n1 < 8; n1++) s_buf[fid][base + (n1 << 3)] = X[n1];
    }
    __syncthreads();

    // ---- pass B: IFFT8 over j1, thread = (n1, j2) ----
    {
        const int n1 = t >> 3, j2 = t & 7;
        float2 y[8];
#pragma unroll
        for (int j1 = 0; j1 < 8; j1++) y[j1] = s_buf[fid][j1 * 68 + (n1 << 3) + j2];
        __syncthreads();                          // reads done before in-place writes
        float2 V[8];
        ifft8(y, V);
#pragma unroll
        for (int m1 = 1; m1 < 8; m1++) V[m1] = cmul(V[m1], s_tw[((j2 * m1) << 3)]);
        const int base = j2 * 66 + (n1 << 3);
#pragma unroll
        for (int m1 = 0; m1 < 8; m1++) s_buf[fid][base + m1] = V[m1];
    }
    __syncthreads();

    // ---- pass C: IFFT8 over j2, thread = (n1, m1); scale + window + store ----
    {
        const int n1 = t >> 3, m1 = t & 7;
        float2 d[8];
#pragma unroll
        for (int j2 = 0; j2 < 8; j2++) d[j2] = s_buf[fid][j2 * 66 + (n1 << 3) + m1];
        float2 X[8];
        ifft8(d, X);
        const float inv = 1.0f / 512.0f;
        float* __restrict__ fr = g_frames + (size_t)f * NFFT;
        const int nb = n1 + (m1 << 3);
#pragma unroll
        for (int m2 = 0; m2 < 8; m2++) {
            int n = nb + (m2 << 6);
            float2 w2 = *(const float2*)&g_win[2 * n];
            *(float2*)&fr[2 * n] = make_float2(X[m2].x * inv * w2.x,
                                               X[m2].y * inv * w2.y);
        }
    }
}

// ---------------------------------------------------------------------------
// Kernel 3: overlap-add, 4 outputs/thread, float4 loads, precomputed 1/env.
// Interior samples always have exactly 4 taps -> unrolled fast path.
// ---------------------------------------------------------------------------
__global__ void __launch_bounds__(256)
ola_kernel(float* __restrict__ out)
{
    int g = blockIdx.x * blockDim.x + threadIdx.x;       // group id
    if (g >= (BATCH * OUT_LEN) / 4) return;
    int b   = g / (OUT_LEN / 4);
    int mo0 = (g - b * (OUT_LEN / 4)) << 2;
    int m0  = mo0 + PAD;

    int t_hi = m0 >> 8;
    if (t_hi > T_FRAMES - 1) t_hi = T_FRAMES - 1;
    int t_lo = (m0 >= (NFFT - HOP)) ? ((m0 - (NFFT - HOP)) >> 8) : 0;

    float4 acc = make_float4(0.0f, 0.0f, 0.0f, 0.0f);
    const float* __restrict__ base = g_frames + (size_t)b * T_FRAMES * NFFT;
    if (t_hi - t_lo == 3) {
#pragma unroll
        for (int d = 0; d < 4; d++) {
            int t = t_lo + d;
            float4 v = *(const float4*)(base + (size_t)t * NFFT + (m0 - (t << 8)));
            acc.x += v.x; acc.y += v.y; acc.z += v.z; acc.w += v.w;
        }
    } else {
        for (int t = t_lo; t <= t_hi; t++) {
            float4 v = *(const float4*)(base + (size_t)t * NFFT + (m0 - (t << 8)));
            acc.x += v.x; acc.y += v.y; acc.z += v.z; acc.w += v.w;
        }
    }
    float4 e = *(const float4*)&g_env_inv[m0];
    *(float4*)&out[(size_t)b * OUT_LEN + mo0] =
        make_float4(acc.x * e.x, acc.y * e.y, acc.z * e.z, acc.w * e.w);
}

// ---------------------------------------------------------------------------
// Launch
// ---------------------------------------------------------------------------
extern "C" void kernel_launch(void* const* d_in, const int* in_sizes, int n_in,
                              void* d_out, int out_size)
{
    const float* x    = (const float*)d_in[0];   // [8, 2048, 512]
    const float* W    = (const float*)d_in[1];   // [512, 1026]
    const float* bias = (const float*)d_in[2];   // [1026]
    float* out = (float*)d_out;                  // [8, 524544]

    cudaFuncSetAttribute(gemm_mma_kernel,
                         cudaFuncAttributeMaxDynamicSharedMemorySize,
                         GEMM_SMEM);

    // 0) prep: W tf32 rounding + tables/window/envelope
    prep_w_kernel<<<(N_MAIN * K_DIM) / 256, 256>>>(W);
    prep_tables_env_kernel<<<(OUT_FULL + 255) / 256, 256>>>();

    // 1a) single-pass TF32 tensor-core GEMM over N=1024 -> g_h  (2 CTAs/SM)
    dim3 g1(N_MAIN / 128, M_TOTAL / 128);   // (8, 128)
    gemm_mma_kernel<<<g1, 256, GEMM_SMEM>>>(x, bias);

    // 1b) fp32 GEMV for tail columns 1024..1025
    gemv_tail_kernel<<<M_TOTAL / 8, 256>>>(x, bias);

    // 2) spectrum -> radix-8 register irfft -> window -> g_frames
    ifft_kernel<<<M_TOTAL / 4, 256>>>();

    // 3) overlap-add * 1/env -> out (4 outputs per thread)
    int groups = (BATCH * OUT_LEN) / 4;
    ola_kernel<<<(groups + 255) / 256, 256>>>(out);
}

// round 14
// speedup vs baseline: 1.2944x; 1.0199x over previous
#include <cuda_runtime.h>
#include <cuda_bf16.h>
#include <math.h>
#include <stdint.h>

// ---------------------------------------------------------------------------
// Problem constants
// ---------------------------------------------------------------------------
#define BATCH      8
#define T_FRAMES   2048
#define M_TOTAL    (BATCH * T_FRAMES)   // 16384 frames
#define K_DIM      512
#define N_DIM      1026                 // N_FFT + 2
#define N_MAIN     1024                 // 8 x 128 tiles via tensor cores
#define NBINS      513                  // N_FFT/2 + 1
#define NFFT       1024
#define HOP        256
#define PAD        384                  // (1024-256)/2
#define OUT_FULL   ((T_FRAMES - 1) * HOP + NFFT)  // 525312
#define OUT_LEN    (OUT_FULL - 2 * PAD)           // 524544

// ---------------------------------------------------------------------------
// Scratch (device globals: no runtime allocation allowed)
// ---------------------------------------------------------------------------
__device__ float g_h[(size_t)M_TOTAL * N_DIM];        // linear head output (~67 MB)
__device__ float g_frames[(size_t)M_TOTAL * NFFT];    // windowed iFFT frames (~67 MB)
__device__ float g_wt[(size_t)N_MAIN * K_DIM];        // W^T, tf32-rounded fp32 (2 MB)
__device__ float g_wtail[2 * K_DIM];    // fp32 W columns 1024,1025 (transposed)
// precomputed tables
__device__ float2 g_tw[512];        // e^{+2*pi*i*j/512},  j<512
__device__ float2 g_pretw[512];     // e^{+2*pi*i*k/1024}, k<512  (packing twiddles)
__device__ float  g_win[NFFT];      // hann window
__device__ float  g_env_inv[OUT_FULL];  // 1 / sum win^2

// ---------------------------------------------------------------------------
// baseline-arch PTX helpers (supported on compute_103 WITHOUT 'a')
// ---------------------------------------------------------------------------
__device__ __forceinline__ uint32_t smem_u32(const void* p) {
    return (uint32_t)__cvta_generic_to_shared(p);
}

__device__ __forceinline__ void cp_async16(uint32_t saddr, const void* gptr) {
    asm volatile("cp.async.cg.shared.global [%0], [%1], 16;"
                 :: "r"(saddr), "l"(gptr));
}
#define CP_COMMIT() asm volatile("cp.async.commit_group;" ::: "memory")
#define CP_WAIT1()  asm volatile("cp.async.wait_group 1;" ::: "memory")

// LDS fp32 + round-to-nearest tf32 (returns tf32 bit pattern in a b32 reg)
__device__ __forceinline__ uint32_t lds_tf32(uint32_t addr) {
    float v;
    asm volatile("ld.shared.f32 %0, [%1];" : "=f"(v) : "r"(addr));
    uint32_t t;
    asm volatile("cvt.rna.tf32.f32 %0, %1;" : "=r"(t) : "f"(v));
    return t;
}
__device__ __forceinline__ uint32_t lds_b32(uint32_t addr) {
    uint32_t v;
    asm volatile("ld.shared.b32 %0, [%1];" : "=r"(v) : "r"(addr));
    return v;
}

#define MMATF32(c, a0, a1, a2, a3, b0, b1) \
    asm volatile("mma.sync.aligned.m16n8k8.row.col.f32.tf32.tf32.f32 " \
                 "{%0,%1,%2,%3}, {%4,%5,%6,%7}, {%8,%9}, {%0,%1,%2,%3};" \
                 : "+f"((c)[0]), "+f"((c)[1]), "+f"((c)[2]), "+f"((c)[3]) \
                 : "r"(a0), "r"(a1), "r"(a2), "r"(a3), "r"(b0), "r"(b1))

// ---------------------------------------------------------------------------
// complex helpers
// ---------------------------------------------------------------------------
__device__ __forceinline__ float2 cadd(float2 a, float2 b) { return make_float2(a.x + b.x, a.y + b.y); }
__device__ __forceinline__ float2 csub(float2 a, float2 b) { return make_float2(a.x - b.x, a.y - b.y); }
__device__ __forceinline__ float2 cmul(float2 a, float2 b) {
    return make_float2(a.x * b.x - a.y * b.y, a.x * b.y + a.y * b.x);
}
__device__ __forceinline__ float2 cmuli(float2 a) { return make_float2(-a.y, a.x); }  // * i

// inverse 8-point DFT: X[m] = sum_k c[k] e^{+2*pi*i*k*m/8}
__device__ __forceinline__ void ifft8(const float2 c[8], float2 X[8]) {
    const float r = 0.70710678118654752f;
    float2 t0 = cadd(c[0], c[4]), t1 = csub(c[0], c[4]);
    float2 t2 = cadd(c[2], c[6]), t3 = cmuli(csub(c[2], c[6]));
    float2 E0 = cadd(t0, t2), E1 = cadd(t1, t3), E2 = csub(t0, t2), E3 = csub(t1, t3);
    float2 u0 = cadd(c[1], c[5]), u1 = csub(c[1], c[5]);
    float2 u2 = cadd(c[3], c[7]), u3 = cmuli(csub(c[3], c[7]));
    float2 O0 = cadd(u0, u2), O1 = cadd(u1, u3), O2 = csub(u0, u2), O3 = csub(u1, u3);
    float2 W1 = make_float2(r * (O1.x - O1.y), r * (O1.x + O1.y));
    float2 W2 = cmuli(O2);
    float2 W3 = make_float2(-r * (O3.x + O3.y), r * (O3.x - O3.y));
    X[0] = cadd(E0, O0); X[4] = csub(E0, O0);
    X[1] = cadd(E1, W1); X[5] = csub(E1, W1);
    X[2] = cadd(E2, W2); X[6] = csub(E2, W2);
    X[3] = cadd(E3, W3); X[7] = csub(E3, W3);
}

// ---------------------------------------------------------------------------
// Prep 1: W [K, 1026] -> g_wt [1024][512] tf32-rounded fp32 + fp32 tail cols
// ---------------------------------------------------------------------------
__global__ void __launch_bounds__(256)
prep_w_kernel(const float* __restrict__ W)
{
    int idx = blockIdx.x * 256 + threadIdx.x;       // over N_MAIN * K_DIM
    int n = idx >> 9;          // 0..1023
    int k = idx & 511;
    float v = W[(size_t)k * N_DIM + n];
    uint32_t t;
    asm("cvt.rna.tf32.f32 %0, %1;" : "=r"(t) : "f"(v));
    g_wt[idx] = __uint_as_float(t);
    // tail columns: block 0 extracts W[:,1024:1026] transposed, fp32
    if (blockIdx.x == 0) {
        int tid = threadIdx.x;
        for (int i = tid; i < 2 * K_DIM; i += 256) {
            int j  = i >> 9;           // 0/1
            int kk = i & 511;
            g_wtail[i] = W[(size_t)kk * N_DIM + 1024 + j];
        }
    }
}

// ---------------------------------------------------------------------------
// Prep 2 (MERGED): trig tables + window + envelope reciprocal + tail GEMV.
// Grid = 2052 blocks x 256 (2052*256 == OUT_FULL exactly).
//   - all blocks: env_inv for sample i = blockIdx*256+tid
//   - blocks 0..3: twiddle/pretwiddle/window tables
//   - blocks 0..2047: fp32 GEMV rows 8*blockIdx .. +7 for tail cols 1024,1025
// The GEMV is DRAM-bound, the env loop is MUFU-bound -> they overlap.
// ---------------------------------------------------------------------------
__global__ void __launch_bounds__(256)
prep_tables_env_gemv_kernel(const float* __restrict__ x,
                            const float* __restrict__ bias)
{
    __shared__ float w0[K_DIM], w1[K_DIM];
    const int tid  = threadIdx.x;
    const int bid  = blockIdx.x;
    const int i    = bid * 256 + tid;
    const bool do_gemv = (bid < M_TOTAL / 8);

    // ---- stage tail weights (only blocks that run the GEMV) ----
    if (do_gemv) {
        for (int t = tid; t < K_DIM; t += 256) {
            w0[t] = g_wtail[t];
            w1[t] = g_wtail[K_DIM + t];
        }
        __syncthreads();
    }

    // ---- tables (first 1024 threads globally) ----
    float s, c;
    if (i < 512) {                               // e^{2*pi*i*j/512}
        sincospif((float)i * (1.0f / 256.0f), &s, &c);
        g_tw[i] = make_float2(c, s);
        sincospif((float)i * (1.0f / 512.0f), &s, &c);   // e^{2*pi*i*k/1024}
        g_pretw[i] = make_float2(c, s);
    }
    if (i < NFFT) {
        g_win[i] = 0.5f * (1.0f - cospif((float)i * (1.0f / 512.0f)));
    }

    // ---- tail GEMV: one warp per row, 8 rows per block ----
    if (do_gemv) {
        const int warp = tid >> 5;
        const int lane = tid & 31;
        const int m = (bid << 3) + warp;
        const float* __restrict__ xr = x + (size_t)m * K_DIM;
        float a0 = 0.0f, a1 = 0.0f;
#pragma unroll
        for (int p = 0; p < 4; p++) {
            int k = (p << 7) + (lane << 2);
            float4 v = *(const float4*)&xr[k];
            a0 += v.x * w0[k] + v.y * w0[k + 1] + v.z * w0[k + 2] + v.w * w0[k + 3];
            a1 += v.x * w1[k] + v.y * w1[k + 1] + v.z * w1[k + 2] + v.w * w1[k + 3];
        }
#pragma unroll
        for (int off = 16; off > 0; off >>= 1) {
            a0 += __shfl_down_sync(0xFFFFFFFFu, a0, off);
            a1 += __shfl_down_sync(0xFFFFFFFFu, a1, off);
        }
        if (lane == 0) {
            g_h[(size_t)m * N_DIM + 1024] = a0 + bias[1024];
            g_h[(size_t)m * N_DIM + 1025] = a1 + bias[1025];
        }
    }

    // ---- envelope reciprocal (i covers exactly OUT_FULL) ----
    {
        int m = i;
        int t_hi = m >> 8;
        if (t_hi > T_FRAMES - 1) t_hi = T_FRAMES - 1;
        int t_lo = (m >= (NFFT - HOP)) ? ((m - (NFFT - HOP)) >> 8) : 0;
        float env = 0.0f;
        for (int t = t_lo; t <= t_hi; t++) {
            int n = m - (t << 8);
            float win = 0.5f * (1.0f - cospif((float)n * (1.0f / 512.0f)));
            env += win * win;
        }
        g_env_inv[m] = (env > 0.0f) ? (1.0f / env) : 0.0f;
    }
}

// ---------------------------------------------------------------------------
// Kernel 1: single-pass TF32 GEMM  h[:, :1024] = x @ W[:, :1024] + b.
// CTA tile 128x128, BK=32, 3-stage cp.async, 8 warps (64x32), 2 CTAs/SM.
// A = raw fp32 x (tf32-rounded in-register via cvt.rna); B pre-rounded.
// SMEM: fp32 tiles, 128B rows of 8x16B granules, xor swizzle g^=row&7.
// ---------------------------------------------------------------------------
#define MAT_BYTES   16384                 // 128 rows x 128 B (32 fp32)
#define STAGE_BYTES (2 * MAT_BYTES)       // 32768 (A, B)
#define N_STAGES    3
#define GEMM_SMEM   (N_STAGES * STAGE_BYTES)   // 98304
#define N_CHUNKS_K  (K_DIM / 32)          // 16
#define OFF_A 0
#define OFF_B MAT_BYTES

// byte offset of (row, 16B-granule g in 0..7) within a 128B-row fp32 tile
#define SWZ(row, g) (((row) << 7) + ((((g) ^ ((row) & 7))) << 4))

__device__ __forceinline__ void load_stage(uint32_t sdst,
                                           const float* pA, const float* pB,
                                           int k0, int tid)
{
#pragma unroll
    for (int t = 0; t < 4; t++) {
        int idx = tid + (t << 8);
        int row = idx >> 3;
        int g   = idx & 7;
        uint32_t soff = SWZ(row, g);
        size_t goff = (size_t)row * K_DIM + k0 + (g << 2);
        cp_async16(sdst + OFF_A + soff, pA + goff);
        cp_async16(sdst + OFF_B + soff, pB + goff);
    }
}

__global__ void __launch_bounds__(256, 2)
gemm_mma_kernel(const float* __restrict__ x, const float* __restrict__ bias)
{
    extern __shared__ __align__(128) char smem[];
    const int tid  = threadIdx.x;
    const int lane = tid & 31;
    const int warp = tid >> 5;
    const int wm   = (warp >> 2) << 6;   // 0 / 64
    const int wn   = (warp & 3) << 5;    // 0,32,64,96
    const int bm   = blockIdx.y << 7;    // 128-row tiles
    const int bn   = blockIdx.x << 7;    // 128-col tiles
    const uint32_t sbase = smem_u32(smem);

    const float* pA = x    + (size_t)bm * K_DIM;
    const float* pB = g_wt + (size_t)bn * K_DIM;

    float acc[4][4][4];
#pragma unroll
    for (int i = 0; i < 4; i++)
#pragma unroll
        for (int j = 0; j < 4; j++)
#pragma unroll
            for (int r = 0; r < 4; r++) acc[i][j][r] = 0.0f;

    const int qr = lane >> 2;            // quad row 0..7 (xor key)
    const int qc = lane & 3;             // 0..3
    const uint32_t aBase = (uint32_t)((wm + qr) << 7) + (qc << 2);
    const uint32_t bBase = (uint32_t)((wn + qr) << 7) + (qc << 2);

    // prologue: 2 stages in flight
    load_stage(sbase + 0 * STAGE_BYTES, pA, pB,  0, tid); CP_COMMIT();
    load_stage(sbase + 1 * STAGE_BYTES, pA, pB, 32, tid); CP_COMMIT();

    int buf = 0;
    for (int ck = 0; ck < N_CHUNKS_K; ck++) {
        CP_WAIT1();                        // stage ck landed (1 still flying)
        __syncthreads();
        if (ck + 2 < N_CHUNKS_K) {
            int nb = buf + 2; if (nb >= N_STAGES) nb -= N_STAGES;
            load_stage(sbase + nb * STAGE_BYTES, pA, pB, (ck + 2) << 5, tid);
        }
        CP_COMMIT();                       // commit (possibly empty) group

        const uint32_t stg = sbase + buf * STAGE_BYTES;
        if (++buf == N_STAGES) buf = 0;

#pragma unroll
        for (int s8 = 0; s8 < 4; s8++) {
            const int kb = s8 << 3;
            const uint32_t off0 = (uint32_t)(((kb >> 2) ^ qr) << 4);
            const uint32_t off1 = (uint32_t)((((kb >> 2) + 1) ^ qr) << 4);

            uint32_t a[4][4], b[4][2];
#pragma unroll
            for (int i = 0; i < 4; i++) {
                uint32_t ra = stg + OFF_A + aBase + (uint32_t)(i << 11);
                a[i][0] = lds_tf32(ra + off0);           // (r,   c)
                a[i][1] = lds_tf32(ra + 1024 + off0);    // (r+8, c)
                a[i][2] = lds_tf32(ra + off1);           // (r,   c+4)
                a[i][3] = lds_tf32(ra + 1024 + off1);    // (r+8, c+4)
            }
#pragma unroll
            for (int j = 0; j < 4; j++) {
                uint32_t rb = stg + OFF_B + bBase + (uint32_t)(j << 10);
                b[j][0] = lds_b32(rb + off0);            // (k,   n)
                b[j][1] = lds_b32(rb + off1);            // (k+4, n)
            }
#pragma unroll
            for (int i = 0; i < 4; i++)
#pragma unroll
                for (int j = 0; j < 4; j++)
                    MMATF32(acc[i][j], a[i][0], a[i][1], a[i][2], a[i][3],
                            b[j][0], b[j][1]);
        }
    }

    // epilogue: bias + direct float2 stores (all cols < 1024 < N_DIM)
    const int r0 = bm + wm + (lane >> 2);
    const int c0 = bn + wn + ((lane & 3) << 1);
#pragma unroll
    for (int j = 0; j < 4; j++) {
        int col = c0 + (j << 3);
        float bx = bias[col];
        float by = bias[col + 1];
#pragma unroll
        for (int i = 0; i < 4; i++) {
            int row = r0 + (i << 4);
            *(float2*)&g_h[(size_t)row * N_DIM + col] =
                make_float2(acc[i][j][0] + bx, acc[i][j][1] + by);
            *(float2*)&g_h[(size_t)(row + 8) * N_DIM + col] =
                make_float2(acc[i][j][2] + bx, acc[i][j][3] + by);
        }
    }
}

// ---------------------------------------------------------------------------
// Kernel 2: spectrum -> 512-pt inverse FFT as 3x radix-8 register passes
// (2 smem transposes, 64 threads/frame, 4 frames/block) -> window -> frames.
// ---------------------------------------------------------------------------
__global__ void __launch_bounds__(256)
ifft_kernel()
{
    __shared__ float2 s_spec[4][513];   // packed spectrum per frame
    __shared__ float2 s_buf[4][540];    // transpose buffer per frame
    __shared__ float2 s_tw[512];        // e^{2*pi*i*j/512}

    const int tid = threadIdx.x;
    const int fid = tid >> 6;                      // frame within block
    const int t   = tid & 63;                      // thread within frame
    const int f   = (blockIdx.x << 2) + fid;       // global frame id
    const float* __restrict__ h = g_h + (size_t)f * N_DIM;

    s_tw[tid]       = g_tw[tid];
    s_tw[tid + 256] = g_tw[tid + 256];

    // spectrum: S_k = min(exp(h_k),100) * (cos p_k + i sin p_k)
    for (int k = t; k <= 512; k += 64) {
        float mag = fminf(__expf(h[k]), 100.0f);
        float s, c;
        __sincosf(h[NBINS + k], &s, &c);
        if (k == 0 || k == 512) s = 0.0f;          // irfft ignores Im of DC/Nyquist
        s_spec[fid][k] = make_float2(mag * c, mag * s);
    }
    __syncthreads();

    // ---- pass A: pack + IFFT8 over k1 (k2 = t) ----
    {
        float2 c[8];
#pragma unroll
        for (int k1 = 0; k1 < 8; k1++) {
            int k = (k1 << 6) + t;
            float2 Xk = s_spec[fid][k];
            float2 Xr = s_spec[fid][512 - k];
            float Ex = 0.5f * (Xk.x + Xr.x);
            float Ey = 0.5f * (Xk.y - Xr.y);
            float Dx = 0.5f * (Xk.x - Xr.x);
            float Dy = 0.5f * (Xk.y + Xr.y);
            float2 w = g_pretw[k];
            c[k1] = make_float2(Ex - (w.x * Dy + w.y * Dx),
                                Ey + (w.x * Dx - w.y * Dy));
        }
        float2 X[8];
        ifft8(c, X);
#pragma unroll
        for (int n1 = 1; n1 < 8; n1++) X[n1] = cmul(X[n1], s_tw[t * n1]);
        const int base = (t >> 3) * 68 + (t & 7);
#pragma unroll
        for (int n1 = 0; n1 < 8; n1++) s_buf[fid][base + (n1 << 3)] = X[n1];
    }
    __syncthreads();

    // ---- pass B: IFFT8 over j1, thread = (n1, j2) ----
    {
        const int n1 = t >> 3, j2 = t & 7;
        float2 y[8];
#pragma unroll
        for (int j1 = 0; j1 < 8; j1++) y[j1] = s_buf[fid][j1 * 68 + (n1 << 3) + j2];
        __syncthreads();                          // reads done before in-place writes
        float2 V[8];
        ifft8(y, V);
#pragma unroll
        for (int m1 = 1; m1 < 8; m1++) V[m1] = cmul(V[m1], s_tw[((j2 * m1) << 3)]);
        const int base = j2 * 66 + (n1 << 3);
#pragma unroll
        for (int m1 = 0; m1 < 8; m1++) s_buf[fid][base + m1] = V[m1];
    }
    __syncthreads();

    // ---- pass C: IFFT8 over j2, thread = (n1, m1); scale + window + store ----
    {
        const int n1 = t >> 3, m1 = t & 7;
        float2 d[8];
#pragma unroll
        for (int j2 = 0; j2 < 8; j2++) d[j2] = s_buf[fid][j2 * 66 + (n1 << 3) + m1];
        float2 X[8];
        ifft8(d, X);
        const float inv = 1.0f / 512.0f;
        float* __restrict__ fr = g_frames + (size_t)f * NFFT;
        const int nb = n1 + (m1 << 3);
#pragma unroll
        for (int m2 = 0; m2 < 8; m2++) {
            int n = nb + (m2 << 6);
            float2 w2 = *(const float2*)&g_win[2 * n];
            *(float2*)&fr[2 * n] = make_float2(X[m2].x * inv * w2.x,
                                               X[m2].y * inv * w2.y);
        }
    }
}

// ---------------------------------------------------------------------------
// Kernel 3: overlap-add, 4 outputs/thread, float4 loads, precomputed 1/env.
// Interior samples always have exactly 4 taps -> unrolled fast path.
// ---------------------------------------------------------------------------
__global__ void __launch_bounds__(256)
ola_kernel(float* __restrict__ out)
{
    int g = blockIdx.x * blockDim.x + threadIdx.x;       // group id
    if (g >= (BATCH * OUT_LEN) / 4) return;
    int b   = g / (OUT_LEN / 4);
    int mo0 = (g - b * (OUT_LEN / 4)) << 2;
    int m0  = mo0 + PAD;

    int t_hi = m0 >> 8;
    if (t_hi > T_FRAMES - 1) t_hi = T_FRAMES - 1;
    int t_lo = (m0 >= (NFFT - HOP)) ? ((m0 - (NFFT - HOP)) >> 8) : 0;

    float4 acc = make_float4(0.0f, 0.0f, 0.0f, 0.0f);
    const float* __restrict__ base = g_frames + (size_t)b * T_FRAMES * NFFT;
    if (t_hi - t_lo == 3) {
#pragma unroll
        for (int d = 0; d < 4; d++) {
            int t = t_lo + d;
            float4 v = *(const float4*)(base + (size_t)t * NFFT + (m0 - (t << 8)));
            acc.x += v.x; acc.y += v.y; acc.z += v.z; acc.w += v.w;
        }
    } else {
        for (int t = t_lo; t <= t_hi; t++) {
            float4 v = *(const float4*)(base + (size_t)t * NFFT + (m0 - (t << 8)));
            acc.x += v.x; acc.y += v.y; acc.z += v.z; acc.w += v.w;
        }
    }
    float4 e = *(const float4*)&g_env_inv[m0];
    *(float4*)&out[(size_t)b * OUT_LEN + mo0] =
        make_float4(acc.x * e.x, acc.y * e.y, acc.z * e.z, acc.w * e.w);
}

// ---------------------------------------------------------------------------
// Launch
// ---------------------------------------------------------------------------
extern "C" void kernel_launch(void* const* d_in, const int* in_sizes, int n_in,
                              void* d_out, int out_size)
{
    const float* x    = (const float*)d_in[0];   // [8, 2048, 512]
    const float* W    = (const float*)d_in[1];   // [512, 1026]
    const float* bias = (const float*)d_in[2];   // [1026]
    float* out = (float*)d_out;                  // [8, 524544]

    cudaFuncSetAttribute(gemm_mma_kernel,
                         cudaFuncAttributeMaxDynamicSharedMemorySize,
                         GEMM_SMEM);

    // 0) prep: W tf32 rounding + tail extraction
    prep_w_kernel<<<(N_MAIN * K_DIM) / 256, 256>>>(W);

    // 0b) merged: tables + window + env + tail GEMV (2052*256 == OUT_FULL)
    prep_tables_env_gemv_kernel<<<OUT_FULL / 256, 256>>>(x, bias);

    // 1) single-pass TF32 tensor-core GEMM over N=1024 -> g_h  (2 CTAs/SM)
    dim3 g1(N_MAIN / 128, M_TOTAL / 128);   // (8, 128)
    gemm_mma_kernel<<<g1, 256, GEMM_SMEM>>>(x, bias);

    // 2) spectrum -> radix-8 register irfft -> window -> g_frames
    ifft_kernel<<<M_TOTAL / 4, 256>>>();

    // 3) overlap-add * 1/env -> out (4 outputs per thread)
    int groups = (BATCH * OUT_LEN) / 4;
    ola_kernel<<<(groups + 255) / 256, 256>>>(out);
}

// round 15
// speedup vs baseline: 1.3785x; 1.0650x over previous
#include <cuda_runtime.h>
#include <cuda_bf16.h>
#include <cuda_fp16.h>
#include <math.h>
#include <stdint.h>

// ---------------------------------------------------------------------------
// Problem constants
// ---------------------------------------------------------------------------
#define BATCH      8
#define T_FRAMES   2048
#define M_TOTAL    (BATCH * T_FRAMES)   // 16384 frames
#define K_DIM      512
#define N_DIM      1026                 // N_FFT + 2
#define N_MAIN     1024                 // 8 x 128 tiles via tensor cores
#define NBINS      513                  // N_FFT/2 + 1
#define NFFT       1024
#define HOP        256
#define PAD        384                  // (1024-256)/2
#define OUT_FULL   ((T_FRAMES - 1) * HOP + NFFT)  // 525312
#define OUT_LEN    (OUT_FULL - 2 * PAD)           // 524544

// ---------------------------------------------------------------------------
// Scratch (device globals: no runtime allocation allowed)
// ---------------------------------------------------------------------------
__device__ float  g_h[(size_t)M_TOTAL * N_DIM];       // linear head output (~67 MB)
__device__ __half g_frames[(size_t)M_TOTAL * NFFT];   // windowed frames, fp16 (~34 MB)
__device__ float  g_wt[(size_t)N_MAIN * K_DIM];       // W^T, tf32-rounded fp32 (2 MB)
__device__ float  g_wtail[2 * K_DIM];   // fp32 W columns 1024,1025 (transposed)
// precomputed tables
__device__ float2 g_tw[512];        // e^{+2*pi*i*j/512},  j<512
__device__ float2 g_pretw[512];     // e^{+2*pi*i*k/1024}, k<512  (packing twiddles)
__device__ float  g_win[NFFT];      // hann window
__device__ float  g_env_inv[OUT_FULL];  // 1 / sum win^2

// ---------------------------------------------------------------------------
// baseline-arch PTX helpers (supported on compute_103 WITHOUT 'a')
// ---------------------------------------------------------------------------
__device__ __forceinline__ uint32_t smem_u32(const void* p) {
    return (uint32_t)__cvta_generic_to_shared(p);
}

__device__ __forceinline__ void cp_async16(uint32_t saddr, const void* gptr) {
    asm volatile("cp.async.cg.shared.global [%0], [%1], 16;"
                 :: "r"(saddr), "l"(gptr));
}
#define CP_COMMIT() asm volatile("cp.async.commit_group;" ::: "memory")
#define CP_WAIT1()  asm volatile("cp.async.wait_group 1;" ::: "memory")

// LDS fp32 + round-to-nearest tf32 (returns tf32 bit pattern in a b32 reg)
__device__ __forceinline__ uint32_t lds_tf32(uint32_t addr) {
    float v;
    asm volatile("ld.shared.f32 %0, [%1];" : "=f"(v) : "r"(addr));
    uint32_t t;
    asm volatile("cvt.rna.tf32.f32 %0, %1;" : "=r"(t) : "f"(v));
    return t;
}
__device__ __forceinline__ uint32_t lds_b32(uint32_t addr) {
    uint32_t v;
    asm volatile("ld.shared.b32 %0, [%1];" : "=r"(v) : "r"(addr));
    return v;
}

#define MMATF32(c, a0, a1, a2, a3, b0, b1) \
    asm volatile("mma.sync.aligned.m16n8k8.row.col.f32.tf32.tf32.f32 " \
                 "{%0,%1,%2,%3}, {%4,%5,%6,%7}, {%8,%9}, {%0,%1,%2,%3};" \
                 : "+f"((c)[0]), "+f"((c)[1]), "+f"((c)[2]), "+f"((c)[3]) \
                 : "r"(a0), "r"(a1), "r"(a2), "r"(a3), "r"(b0), "r"(b1))

// ---------------------------------------------------------------------------
// complex helpers
// ---------------------------------------------------------------------------
__device__ __forceinline__ float2 cadd(float2 a, float2 b) { return make_float2(a.x + b.x, a.y + b.y); }
__device__ __forceinline__ float2 csub(float2 a, float2 b) { return make_float2(a.x - b.x, a.y - b.y); }
__device__ __forceinline__ float2 cmul(float2 a, float2 b) {
    return make_float2(a.x * b.x - a.y * b.y, a.x * b.y + a.y * b.x);
}
__device__ __forceinline__ float2 cmuli(float2 a) { return make_float2(-a.y, a.x); }  // * i

// inverse 8-point DFT: X[m] = sum_k c[k] e^{+2*pi*i*k*m/8}
__device__ __forceinline__ void ifft8(const float2 c[8], float2 X[8]) {
    const float r = 0.70710678118654752f;
    float2 t0 = cadd(c[0], c[4]), t1 = csub(c[0], c[4]);
    float2 t2 = cadd(c[2], c[6]), t3 = cmuli(csub(c[2], c[6]));
    float2 E0 = cadd(t0, t2), E1 = cadd(t1, t3), E2 = csub(t0, t2), E3 = csub(t1, t3);
    float2 u0 = cadd(c[1], c[5]), u1 = csub(c[1], c[5]);
    float2 u2 = cadd(c[3], c[7]), u3 = cmuli(csub(c[3], c[7]));
    float2 O0 = cadd(u0, u2), O1 = cadd(u1, u3), O2 = csub(u0, u2), O3 = csub(u1, u3);
    float2 W1 = make_float2(r * (O1.x - O1.y), r * (O1.x + O1.y));
    float2 W2 = cmuli(O2);
    float2 W3 = make_float2(-r * (O3.x + O3.y), r * (O3.x - O3.y));
    X[0] = cadd(E0, O0); X[4] = csub(E0, O0);
    X[1] = cadd(E1, W1); X[5] = csub(E1, W1);
    X[2] = cadd(E2, W2); X[6] = csub(E2, W2);
    X[3] = cadd(E3, W3); X[7] = csub(E3, W3);
}

// ---------------------------------------------------------------------------
// Prep 1: W [K, 1026] -> g_wt [1024][512] tf32-rounded fp32 + fp32 tail cols
// ---------------------------------------------------------------------------
__global__ void __launch_bounds__(256)
prep_w_kernel(const float* __restrict__ W)
{
    int idx = blockIdx.x * 256 + threadIdx.x;       // over N_MAIN * K_DIM
    int n = idx >> 9;          // 0..1023
    int k = idx & 511;
    float v = W[(size_t)k * N_DIM + n];
    uint32_t t;
    asm("cvt.rna.tf32.f32 %0, %1;" : "=r"(t) : "f"(v));
    g_wt[idx] = __uint_as_float(t);
    // tail columns: block 0 extracts W[:,1024:1026] transposed, fp32
    if (blockIdx.x == 0) {
        int tid = threadIdx.x;
        for (int i = tid; i < 2 * K_DIM; i += 256) {
            int j  = i >> 9;           // 0/1
            int kk = i & 511;
            g_wtail[i] = W[(size_t)kk * N_DIM + 1024 + j];
        }
    }
}

// ---------------------------------------------------------------------------
// Prep 2 (MERGED): trig tables + window + envelope reciprocal + tail GEMV.
// Grid = 2052 blocks x 256 (2052*256 == OUT_FULL exactly).
// ---------------------------------------------------------------------------
__global__ void __launch_bounds__(256)
prep_tables_env_gemv_kernel(const float* __restrict__ x,
                            const float* __restrict__ bias)
{
    __shared__ float w0[K_DIM], w1[K_DIM];
    const int tid  = threadIdx.x;
    const int bid  = blockIdx.x;
    const int i    = bid * 256 + tid;
    const bool do_gemv = (bid < M_TOTAL / 8);

    // ---- stage tail weights (only blocks that run the GEMV) ----
    if (do_gemv) {
        for (int t = tid; t < K_DIM; t += 256) {
            w0[t] = g_wtail[t];
            w1[t] = g_wtail[K_DIM + t];
        }
        __syncthreads();
    }

    // ---- tables (first 1024 threads globally) ----
    float s, c;
    if (i < 512) {                               // e^{2*pi*i*j/512}
        sincospif((float)i * (1.0f / 256.0f), &s, &c);
        g_tw[i] = make_float2(c, s);
        sincospif((float)i * (1.0f / 512.0f), &s, &c);   // e^{2*pi*i*k/1024}
        g_pretw[i] = make_float2(c, s);
    }
    if (i < NFFT) {
        g_win[i] = 0.5f * (1.0f - cospif((float)i * (1.0f / 512.0f)));
    }

    // ---- tail GEMV: one warp per row, 8 rows per block ----
    if (do_gemv) {
        const int warp = tid >> 5;
        const int lane = tid & 31;
        const int m = (bid << 3) + warp;
        const float* __restrict__ xr = x + (size_t)m * K_DIM;
        float a0 = 0.0f, a1 = 0.0f;
#pragma unroll
        for (int p = 0; p < 4; p++) {
            int k = (p << 7) + (lane << 2);
            float4 v = *(const float4*)&xr[k];
            a0 += v.x * w0[k] + v.y * w0[k + 1] + v.z * w0[k + 2] + v.w * w0[k + 3];
            a1 += v.x * w1[k] + v.y * w1[k + 1] + v.z * w1[k + 2] + v.w * w1[k + 3];
        }
#pragma unroll
        for (int off = 16; off > 0; off >>= 1) {
            a0 += __shfl_down_sync(0xFFFFFFFFu, a0, off);
            a1 += __shfl_down_sync(0xFFFFFFFFu, a1, off);
        }
        if (lane == 0) {
            g_h[(size_t)m * N_DIM + 1024] = a0 + bias[1024];
            g_h[(size_t)m * N_DIM + 1025] = a1 + bias[1025];
        }
    }

    // ---- envelope reciprocal (i covers exactly OUT_FULL) ----
    {
        int m = i;
        int t_hi = m >> 8;
        if (t_hi > T_FRAMES - 1) t_hi = T_FRAMES - 1;
        int t_lo = (m >= (NFFT - HOP)) ? ((m - (NFFT - HOP)) >> 8) : 0;
        float env = 0.0f;
        for (int t = t_lo; t <= t_hi; t++) {
            int n = m - (t << 8);
            float win = 0.5f * (1.0f - cospif((float)n * (1.0f / 512.0f)));
            env += win * win;
        }
        g_env_inv[m] = (env > 0.0f) ? (1.0f / env) : 0.0f;
    }
}

// ---------------------------------------------------------------------------
// Kernel 1: single-pass TF32 GEMM  h[:, :1024] = x @ W[:, :1024] + b.
// CTA tile 128x128, BK=32, 3-stage cp.async, 8 warps (64x32), 2 CTAs/SM.
// ---------------------------------------------------------------------------
#define MAT_BYTES   16384                 // 128 rows x 128 B (32 fp32)
#define STAGE_BYTES (2 * MAT_BYTES)       // 32768 (A, B)
#define N_STAGES    3
#define GEMM_SMEM   (N_STAGES * STAGE_BYTES)   // 98304
#define N_CHUNKS_K  (K_DIM / 32)          // 16
#define OFF_A 0
#define OFF_B MAT_BYTES

// byte offset of (row, 16B-granule g in 0..7) within a 128B-row fp32 tile
#define SWZ(row, g) (((row) << 7) + ((((g) ^ ((row) & 7))) << 4))

__device__ __forceinline__ void load_stage(uint32_t sdst,
                                           const float* pA, const float* pB,
                                           int k0, int tid)
{
#pragma unroll
    for (int t = 0; t < 4; t++) {
        int idx = tid + (t << 8);
        int row = idx >> 3;
        int g   = idx & 7;
        uint32_t soff = SWZ(row, g);
        size_t goff = (size_t)row * K_DIM + k0 + (g << 2);
        cp_async16(sdst + OFF_A + soff, pA + goff);
        cp_async16(sdst + OFF_B + soff, pB + goff);
    }
}

__global__ void __launch_bounds__(256, 2)
gemm_mma_kernel(const float* __restrict__ x, const float* __restrict__ bias)
{
    extern __shared__ __align__(128) char smem[];
    const int tid  = threadIdx.x;
    const int lane = tid & 31;
    const int warp = tid >> 5;
    const int wm   = (warp >> 2) << 6;   // 0 / 64
    const int wn   = (warp & 3) << 5;    // 0,32,64,96
    const int bm   = blockIdx.y << 7;    // 128-row tiles
    const int bn   = blockIdx.x << 7;    // 128-col tiles
    const uint32_t sbase = smem_u32(smem);

    const float* pA = x    + (size_t)bm * K_DIM;
    const float* pB = g_wt + (size_t)bn * K_DIM;

    float acc[4][4][4];
#pragma unroll
    for (int i = 0; i < 4; i++)
#pragma unroll
        for (int j = 0; j < 4; j++)
#pragma unroll
            for (int r = 0; r < 4; r++) acc[i][j][r] = 0.0f;

    const int qr = lane >> 2;            // quad row 0..7 (xor key)
    const int qc = lane & 3;             // 0..3
    const uint32_t aBase = (uint32_t)((wm + qr) << 7) + (qc << 2);
    const uint32_t bBase = (uint32_t)((wn + qr) << 7) + (qc << 2);

    // prologue: 2 stages in flight
    load_stage(sbase + 0 * STAGE_BYTES, pA, pB,  0, tid); CP_COMMIT();
    load_stage(sbase + 1 * STAGE_BYTES, pA, pB, 32, tid); CP_COMMIT();

    int buf = 0;
    for (int ck = 0; ck < N_CHUNKS_K; ck++) {
        CP_WAIT1();                        // stage ck landed (1 still flying)
        __syncthreads();
        if (ck + 2 < N_CHUNKS_K) {
            int nb = buf + 2; if (nb >= N_STAGES) nb -= N_STAGES;
            load_stage(sbase + nb * STAGE_BYTES, pA, pB, (ck + 2) << 5, tid);
        }
        CP_COMMIT();                       // commit (possibly empty) group

        const uint32_t stg = sbase + buf * STAGE_BYTES;
        if (++buf == N_STAGES) buf = 0;

#pragma unroll
        for (int s8 = 0; s8 < 4; s8++) {
            const int kb = s8 << 3;
            const uint32_t off0 = (uint32_t)(((kb >> 2) ^ qr) << 4);
            const uint32_t off1 = (uint32_t)((((kb >> 2) + 1) ^ qr) << 4);

            uint32_t a[4][4], b[4][2];
#pragma unroll
            for (int i = 0; i < 4; i++) {
                uint32_t ra = stg + OFF_A + aBase + (uint32_t)(i << 11);
                a[i][0] = lds_tf32(ra + off0);           // (r,   c)
                a[i][1] = lds_tf32(ra + 1024 + off0);    // (r+8, c)
                a[i][2] = lds_tf32(ra + off1);           // (r,   c+4)
                a[i][3] = lds_tf32(ra + 1024 + off1);    // (r+8, c+4)
            }
#pragma unroll
            for (int j = 0; j < 4; j++) {
                uint32_t rb = stg + OFF_B + bBase + (uint32_t)(j << 10);
                b[j][0] = lds_b32(rb + off0);            // (k,   n)
                b[j][1] = lds_b32(rb + off1);            // (k+4, n)
            }
#pragma unroll
            for (int i = 0; i < 4; i++)
#pragma unroll
                for (int j = 0; j < 4; j++)
                    MMATF32(acc[i][j], a[i][0], a[i][1], a[i][2], a[i][3],
                            b[j][0], b[j][1]);
        }
    }

    // epilogue: bias + direct float2 stores (all cols < 1024 < N_DIM)
    const int r0 = bm + wm + (lane >> 2);
    const int c0 = bn + wn + ((lane & 3) << 1);
#pragma unroll
    for (int j = 0; j < 4; j++) {
        int col = c0 + (j << 3);
        float bx = bias[col];
        float by = bias[col + 1];
#pragma unroll
        for (int i = 0; i < 4; i++) {
            int row = r0 + (i << 4);
            *(float2*)&g_h[(size_t)row * N_DIM + col] =
                make_float2(acc[i][j][0] + bx, acc[i][j][1] + by);
            *(float2*)&g_h[(size_t)(row + 8) * N_DIM + col] =
                make_float2(acc[i][j][2] + bx, acc[i][j][3] + by);
        }
    }
}

// ---------------------------------------------------------------------------
// Kernel 2: spectrum -> 512-pt inverse FFT as 3x radix-8 register passes
// (2 smem transposes, 64 threads/frame, 4 frames/block) -> window ->
// fp16 frames (half2 stores).
// ---------------------------------------------------------------------------
__global__ void __launch_bounds__(256)
ifft_kernel()
{
    __shared__ float2 s_spec[4][513];   // packed spectrum per frame
    __shared__ float2 s_buf[4][540];    // transpose buffer per frame
    __shared__ float2 s_tw[512];        // e^{2*pi*i*j/512}

    const int tid = threadIdx.x;
    const int fid = tid >> 6;                      // frame within block
    const int t   = tid & 63;                      // thread within frame
    const int f   = (blockIdx.x << 2) + fid;       // global frame id
    const float* __restrict__ h = g_h + (size_t)f * N_DIM;

    s_tw[tid]       = g_tw[tid];
    s_tw[tid + 256] = g_tw[tid + 256];

    // spectrum: S_k = min(exp(h_k),100) * (cos p_k + i sin p_k)
    for (int k = t; k <= 512; k += 64) {
        float mag = fminf(__expf(h[k]), 100.0f);
        float s, c;
        __sincosf(h[NBINS + k], &s, &c);
        if (k == 0 || k == 512) s = 0.0f;          // irfft ignores Im of DC/Nyquist
        s_spec[fid][k] = make_float2(mag * c, mag * s);
    }
    __syncthreads();

    // ---- pass A: pack + IFFT8 over k1 (k2 = t) ----
    {
        float2 c[8];
#pragma unroll
        for (int k1 = 0; k1 < 8; k1++) {
            int k = (k1 << 6) + t;
            float2 Xk = s_spec[fid][k];
            float2 Xr = s_spec[fid][512 - k];
            float Ex = 0.5f * (Xk.x + Xr.x);
            float Ey = 0.5f * (Xk.y - Xr.y);
            float Dx = 0.5f * (Xk.x - Xr.x);
            float Dy = 0.5f * (Xk.y + Xr.y);
            float2 w = g_pretw[k];
            c[k1] = make_float2(Ex - (w.x * Dy + w.y * Dx),
                                Ey + (w.x * Dx - w.y * Dy));
        }
        float2 X[8];
        ifft8(c, X);
#pragma unroll
        for (int n1 = 1; n1 < 8; n1++) X[n1] = cmul(X[n1], s_tw[t * n1]);
        const int base = (t >> 3) * 68 + (t & 7);
#pragma unroll
        for (int n1 = 0; n1 < 8; n1++) s_buf[fid][base + (n1 << 3)] = X[n1];
    }
    __syncthreads();

    // ---- pass B: IFFT8 over j1, thread = (n1, j2) ----
    {
        const int n1 = t >> 3, j2 = t & 7;
        float2 y[8];
#pragma unroll
        for (int j1 = 0; j1 < 8; j1++) y[j1] = s_buf[fid][j1 * 68 + (n1 << 3) + j2];
        __syncthreads();                          // reads done before in-place writes
        float2 V[8];
        ifft8(y, V);
#pragma unroll
        for (int m1 = 1; m1 < 8; m1++) V[m1] = cmul(V[m1], s_tw[((j2 * m1) << 3)]);
        const int base = j2 * 66 + (n1 << 3);
#pragma unroll
        for (int m1 = 0; m1 < 8; m1++) s_buf[fid][base + m1] = V[m1];
    }
    __syncthreads();

    // ---- pass C: IFFT8 over j2; scale + window; store fp16 pairs ----
    {
        const int n1 = t >> 3, m1 = t & 7;
        float2 d[8];
#pragma unroll
        for (int j2 = 0; j2 < 8; j2++) d[j2] = s_buf[fid][j2 * 66 + (n1 << 3) + m1];
        float2 X[8];
        ifft8(d, X);
        const float inv = 1.0f / 512.0f;
        __half* __restrict__ fr = g_frames + (size_t)f * NFFT;
        const int nb = n1 + (m1 << 3);
#pragma unroll
        for (int m2 = 0; m2 < 8; m2++) {
            int n = nb + (m2 << 6);
            float2 w2 = *(const float2*)&g_win[2 * n];
            __half2 hv = __floats2half2_rn(X[m2].x * inv * w2.x,
                                           X[m2].y * inv * w2.y);
            *(__half2*)&fr[2 * n] = hv;
        }
    }
}

// ---------------------------------------------------------------------------
// Kernel 3: overlap-add, 4 outputs/thread, fp16 frame loads (uint2 = 4 halves),
// precomputed 1/env. Interior fast path: exactly 4 taps.
// ---------------------------------------------------------------------------
__device__ __forceinline__ float4 load_tap_h4(const __half* p) {
    uint2 raw = *(const uint2*)p;                 // 4 halves, 8B aligned
    __half2 h01 = *reinterpret_cast<__half2*>(&raw.x);
    __half2 h23 = *reinterpret_cast<__half2*>(&raw.y);
    float2 f01 = __half22float2(h01);
    float2 f23 = __half22float2(h23);
    return make_float4(f01.x, f01.y, f23.x, f23.y);
}

__global__ void __launch_bounds__(256)
ola_kernel(float* __restrict__ out)
{
    int g = blockIdx.x * blockDim.x + threadIdx.x;       // group id
    if (g >= (BATCH * OUT_LEN) / 4) return;
    int b   = g / (OUT_LEN / 4);
    int mo0 = (g - b * (OUT_LEN / 4)) << 2;
    int m0  = mo0 + PAD;

    int t_hi = m0 >> 8;
    if (t_hi > T_FRAMES - 1) t_hi = T_FRAMES - 1;
    int t_lo = (m0 >= (NFFT - HOP)) ? ((m0 - (NFFT - HOP)) >> 8) : 0;

    float4 acc = make_float4(0.0f, 0.0f, 0.0f, 0.0f);
    const __half* __restrict__ base = g_frames + (size_t)b * T_FRAMES * NFFT;
    if (t_hi - t_lo == 3) {
#pragma unroll
        for (int d = 0; d < 4; d++) {
            int t = t_lo + d;
            float4 v = load_tap_h4(base + (size_t)t * NFFT + (m0 - (t << 8)));
            acc.x += v.x; acc.y += v.y; acc.z += v.z; acc.w += v.w;
        }
    } else {
        for (int t = t_lo; t <= t_hi; t++) {
            float4 v = load_tap_h4(base + (size_t)t * NFFT + (m0 - (t << 8)));
            acc.x += v.x; acc.y += v.y; acc.z += v.z; acc.w += v.w;
        }
    }
    float4 e = *(const float4*)&g_env_inv[m0];
    *(float4*)&out[(size_t)b * OUT_LEN + mo0] =
        make_float4(acc.x * e.x, acc.y * e.y, acc.z * e.z, acc.w * e.w);
}

// ---------------------------------------------------------------------------
// Launch
// ---------------------------------------------------------------------------
extern "C" void kernel_launch(void* const* d_in, const int* in_sizes, int n_in,
                              void* d_out, int out_size)
{
    const float* x    = (const float*)d_in[0];   // [8, 2048, 512]
    const float* W    = (const float*)d_in[1];   // [512, 1026]
    const float* bias = (const float*)d_in[2];   // [1026]
    float* out = (float*)d_out;                  // [8, 524544]

    cudaFuncSetAttribute(gemm_mma_kernel,
                         cudaFuncAttributeMaxDynamicSharedMemorySize,
                         GEMM_SMEM);

    // 0) prep: W tf32 rounding + tail extraction
    prep_w_kernel<<<(N_MAIN * K_DIM) / 256, 256>>>(W);

    // 0b) merged: tables + window + env + tail GEMV (2052*256 == OUT_FULL)
    prep_tables_env_gemv_kernel<<<OUT_FULL / 256, 256>>>(x, bias);

    // 1) single-pass TF32 tensor-core GEMM over N=1024 -> g_h  (2 CTAs/SM)
    dim3 g1(N_MAIN / 128, M_TOTAL / 128);   // (8, 128)
    gemm_mma_kernel<<<g1, 256, GEMM_SMEM>>>(x, bias);

    // 2) spectrum -> radix-8 register irfft -> window -> fp16 g_frames
    ifft_kernel<<<M_TOTAL / 4, 256>>>();

    // 3) overlap-add * 1/env -> out (4 outputs per thread)
    int groups = (BATCH * OUT_LEN) / 4;
    ola_kernel<<<(groups + 255) / 256, 256>>>(out);
}

// round 16
// speedup vs baseline: 1.8205x; 1.3206x over previous
#include <cuda_runtime.h>
#include <cuda_bf16.h>
#include <cuda_fp16.h>
#include <math.h>
#include <stdint.h>

// ---------------------------------------------------------------------------
// Problem constants
// ---------------------------------------------------------------------------
#define BATCH      8
#define T_FRAMES   2048
#define M_TOTAL    (BATCH * T_FRAMES)   // 16384 frames
#define K_DIM      512
#define N_DIM      1026                 // N_FFT + 2
#define N_MAIN     1024                 // 8 x 128 tiles via tensor cores
#define NBINS      513                  // N_FFT/2 + 1
#define NFFT       1024
#define HOP        256
#define PAD        384                  // (1024-256)/2
#define OUT_FULL   ((T_FRAMES - 1) * HOP + NFFT)  // 525312
#define OUT_LEN    (OUT_FULL - 2 * PAD)           // 524544

// ---------------------------------------------------------------------------
// Scratch (device globals: no runtime allocation allowed)
// ---------------------------------------------------------------------------
__device__ float  g_h[(size_t)M_TOTAL * N_DIM];       // linear head output (~67 MB)
__device__ __half g_frames[(size_t)M_TOTAL * NFFT];   // windowed frames, fp16 (~34 MB)
__device__ __half g_xh[(size_t)M_TOTAL * K_DIM];      // x in fp16 (17 MB)
__device__ __half g_wth[(size_t)N_MAIN * K_DIM];      // W^T in fp16 (1 MB)
__device__ float  g_wtail[2 * K_DIM];   // fp32 W columns 1024,1025 (transposed)
// precomputed tables
__device__ float2 g_tw[512];        // e^{+2*pi*i*j/512},  j<512
__device__ float2 g_pretw[512];     // e^{+2*pi*i*k/1024}, k<512  (packing twiddles)
__device__ float  g_win[NFFT];      // hann window
__device__ float  g_env_inv[OUT_FULL];  // 1 / sum win^2

// ---------------------------------------------------------------------------
// baseline-arch PTX helpers (supported on compute_103 WITHOUT 'a')
// ---------------------------------------------------------------------------
__device__ __forceinline__ uint32_t smem_u32(const void* p) {
    return (uint32_t)__cvta_generic_to_shared(p);
}

__device__ __forceinline__ void cp_async16(uint32_t saddr, const void* gptr) {
    asm volatile("cp.async.cg.shared.global [%0], [%1], 16;"
                 :: "r"(saddr), "l"(gptr));
}
#define CP_COMMIT() asm volatile("cp.async.commit_group;" ::: "memory")
#define CP_WAIT1()  asm volatile("cp.async.wait_group 1;" ::: "memory")

#define LDSM_X4(r0, r1, r2, r3, addr) \
    asm volatile("ldmatrix.sync.aligned.m8n8.x4.shared.b16 {%0,%1,%2,%3}, [%4];" \
                 : "=r"(r0), "=r"(r1), "=r"(r2), "=r"(r3) : "r"(addr))

#define MMAF16(c, a0, a1, a2, a3, b0, b1) \
    asm volatile("mma.sync.aligned.m16n8k16.row.col.f32.f16.f16.f32 " \
                 "{%0,%1,%2,%3}, {%4,%5,%6,%7}, {%8,%9}, {%0,%1,%2,%3};" \
                 : "+f"((c)[0]), "+f"((c)[1]), "+f"((c)[2]), "+f"((c)[3]) \
                 : "r"(a0), "r"(a1), "r"(a2), "r"(a3), "r"(b0), "r"(b1))

// ---------------------------------------------------------------------------
// complex helpers
// ---------------------------------------------------------------------------
__device__ __forceinline__ float2 cadd(float2 a, float2 b) { return make_float2(a.x + b.x, a.y + b.y); }
__device__ __forceinline__ float2 csub(float2 a, float2 b) { return make_float2(a.x - b.x, a.y - b.y); }
__device__ __forceinline__ float2 cmul(float2 a, float2 b) {
    return make_float2(a.x * b.x - a.y * b.y, a.x * b.y + a.y * b.x);
}
__device__ __forceinline__ float2 cmuli(float2 a) { return make_float2(-a.y, a.x); }  // * i

// inverse 8-point DFT: X[m] = sum_k c[k] e^{+2*pi*i*k*m/8}
__device__ __forceinline__ void ifft8(const float2 c[8], float2 X[8]) {
    const float r = 0.70710678118654752f;
    float2 t0 = cadd(c[0], c[4]), t1 = csub(c[0], c[4]);
    float2 t2 = cadd(c[2], c[6]), t3 = cmuli(csub(c[2], c[6]));
    float2 E0 = cadd(t0, t2), E1 = cadd(t1, t3), E2 = csub(t0, t2), E3 = csub(t1, t3);
    float2 u0 = cadd(c[1], c[5]), u1 = csub(c[1], c[5]);
    float2 u2 = cadd(c[3], c[7]), u3 = cmuli(csub(c[3], c[7]));
    float2 O0 = cadd(u0, u2), O1 = cadd(u1, u3), O2 = csub(u0, u2), O3 = csub(u1, u3);
    float2 W1 = make_float2(r * (O1.x - O1.y), r * (O1.x + O1.y));
    float2 W2 = cmuli(O2);
    float2 W3 = make_float2(-r * (O3.x + O3.y), r * (O3.x - O3.y));
    X[0] = cadd(E0, O0); X[4] = csub(E0, O0);
    X[1] = cadd(E1, W1); X[5] = csub(E1, W1);
    X[2] = cadd(E2, W2); X[6] = csub(E2, W2);
    X[3] = cadd(E3, W3); X[7] = csub(E3, W3);
}

// ---------------------------------------------------------------------------
// Prep 1: W [K, 1026] -> g_wth [1024][512] fp16 (transposed) + fp32 tail cols
// ---------------------------------------------------------------------------
__global__ void __launch_bounds__(256)
prep_w_kernel(const float* __restrict__ W)
{
    int idx = blockIdx.x * 256 + threadIdx.x;       // over N_MAIN * K_DIM
    int n = idx >> 9;          // 0..1023
    int k = idx & 511;
    g_wth[idx] = __float2half_rn(W[(size_t)k * N_DIM + n]);
    // tail columns: block 0 extracts W[:,1024:1026] transposed, fp32
    if (blockIdx.x == 0) {
        int tid = threadIdx.x;
        for (int i = tid; i < 2 * K_DIM; i += 256) {
            int j  = i >> 9;           // 0/1
            int kk = i & 511;
            g_wtail[i] = W[(size_t)kk * N_DIM + 1024 + j];
        }
    }
}

// ---------------------------------------------------------------------------
// Prep 2 (MERGED): trig tables + window + envelope reciprocal + tail GEMV
// + x -> fp16 conversion (x is streamed anyway for the GEMV).
// Grid = 2052 blocks x 256 (2052*256 == OUT_FULL exactly).
// ---------------------------------------------------------------------------
__global__ void __launch_bounds__(256)
prep_tables_env_gemv_kernel(const float* __restrict__ x,
                            const float* __restrict__ bias)
{
    __shared__ float w0[K_DIM], w1[K_DIM];
    const int tid  = threadIdx.x;
    const int bid  = blockIdx.x;
    const int i    = bid * 256 + tid;
    const bool do_gemv = (bid < M_TOTAL / 8);

    // ---- stage tail weights (only blocks that run the GEMV) ----
    if (do_gemv) {
        for (int t = tid; t < K_DIM; t += 256) {
            w0[t] = g_wtail[t];
            w1[t] = g_wtail[K_DIM + t];
        }
        __syncthreads();
    }

    // ---- tables (first 1024 threads globally) ----
    float s, c;
    if (i < 512) {                               // e^{2*pi*i*j/512}
        sincospif((float)i * (1.0f / 256.0f), &s, &c);
        g_tw[i] = make_float2(c, s);
        sincospif((float)i * (1.0f / 512.0f), &s, &c);   // e^{2*pi*i*k/1024}
        g_pretw[i] = make_float2(c, s);
    }
    if (i < NFFT) {
        g_win[i] = 0.5f * (1.0f - cospif((float)i * (1.0f / 512.0f)));
    }

    // ---- tail GEMV + fp16 conversion: one warp per row, 8 rows per block ----
    if (do_gemv) {
        const int warp = tid >> 5;
        const int lane = tid & 31;
        const int m = (bid << 3) + warp;
        const float* __restrict__ xr = x + (size_t)m * K_DIM;
        __half* __restrict__ xh = g_xh + (size_t)m * K_DIM;
        float a0 = 0.0f, a1 = 0.0f;
#pragma unroll
        for (int p = 0; p < 4; p++) {
            int k = (p << 7) + (lane << 2);
            float4 v = *(const float4*)&xr[k];
            a0 += v.x * w0[k] + v.y * w0[k + 1] + v.z * w0[k + 2] + v.w * w0[k + 3];
            a1 += v.x * w1[k] + v.y * w1[k + 1] + v.z * w1[k + 2] + v.w * w1[k + 3];
            // emit fp16 copy (4 halves = 8B, coalesced)
            __half2 h01 = __floats2half2_rn(v.x, v.y);
            __half2 h23 = __floats2half2_rn(v.z, v.w);
            uint2 pk;
            pk.x = *reinterpret_cast<uint32_t*>(&h01);
            pk.y = *reinterpret_cast<uint32_t*>(&h23);
            *(uint2*)&xh[k] = pk;
        }
#pragma unroll
        for (int off = 16; off > 0; off >>= 1) {
            a0 += __shfl_down_sync(0xFFFFFFFFu, a0, off);
            a1 += __shfl_down_sync(0xFFFFFFFFu, a1, off);
        }
        if (lane == 0) {
            g_h[(size_t)m * N_DIM + 1024] = a0 + bias[1024];
            g_h[(size_t)m * N_DIM + 1025] = a1 + bias[1025];
        }
    }

    // ---- envelope reciprocal (i covers exactly OUT_FULL) ----
    {
        int m = i;
        int t_hi = m >> 8;
        if (t_hi > T_FRAMES - 1) t_hi = T_FRAMES - 1;
        int t_lo = (m >= (NFFT - HOP)) ? ((m - (NFFT - HOP)) >> 8) : 0;
        float env = 0.0f;
        for (int t = t_lo; t <= t_hi; t++) {
            int n = m - (t << 8);
            float win = 0.5f * (1.0f - cospif((float)n * (1.0f / 512.0f)));
            env += win * win;
        }
        g_env_inv[m] = (env > 0.0f) ? (1.0f / env) : 0.0f;
    }
}

// ---------------------------------------------------------------------------
// Kernel 1: single-pass FP16 GEMM  h[:, :1024] = x @ W[:, :1024] + b.
// mma.sync.m16n8k16.f32.f16.f16.f32 — same operand precision as tf32 (2^-11)
// but 2048 MACs/instr. CTA tile 128x128, BK=64 (128B rows, SW128 swizzle),
// 3-stage cp.async, 8 warps (warp tile 64x32), 2 CTAs/SM.
// ---------------------------------------------------------------------------
#define MAT_BYTES   16384                 // 128 rows x 128 B (64 fp16)
#define STAGE_BYTES (2 * MAT_BYTES)       // 32768 (A, B)
#define N_STAGES    3
#define GEMM_SMEM   (N_STAGES * STAGE_BYTES)   // 98304
#define N_CHUNKS_K  (K_DIM / 64)          // 8
#define OFF_A 0
#define OFF_B MAT_BYTES

// byte offset of (row, 16B-granule g in 0..7) within a 128B-row tile
#define SWZ(row, g) (((row) << 7) + ((((g) ^ ((row) & 7))) << 4))

__device__ __forceinline__ void load_stage(uint32_t sdst,
                                           const __half* pA, const __half* pB,
                                           int k0, int tid)
{
    // each matrix: 128 rows x 8 granules = 1024 transfers (4 iters of 256)
#pragma unroll
    for (int t = 0; t < 4; t++) {
        int idx = tid + (t << 8);
        int row = idx >> 3;
        int g   = idx & 7;
        uint32_t soff = SWZ(row, g);
        size_t goff = (size_t)row * K_DIM + k0 + (g << 3);
        cp_async16(sdst + OFF_A + soff, pA + goff);
        cp_async16(sdst + OFF_B + soff, pB + goff);
    }
}

__global__ void __launch_bounds__(256, 2)
gemm_mma_kernel(const float* __restrict__ bias)
{
    extern __shared__ __align__(128) char smem[];
    const int tid  = threadIdx.x;
    const int lane = tid & 31;
    const int warp = tid >> 5;
    const int wm   = (warp >> 2) << 6;   // 0 / 64
    const int wn   = (warp & 3) << 5;    // 0,32,64,96
    const int bm   = blockIdx.y << 7;    // 128-row tiles
    const int bn   = blockIdx.x << 7;    // 128-col tiles
    const uint32_t sbase = smem_u32(smem);

    const __half* pA = g_xh  + (size_t)bm * K_DIM;
    const __half* pB = g_wth + (size_t)bn * K_DIM;

    float acc[4][4][4];
#pragma unroll
    for (int i = 0; i < 4; i++)
#pragma unroll
        for (int j = 0; j < 4; j++)
#pragma unroll
            for (int r = 0; r < 4; r++) acc[i][j][r] = 0.0f;

    const int a_row  = wm + (lane & 15);
    const int a_gadd = (lane >> 4);          // 0/1
    const int b_row  = wn + (lane & 7) + ((lane >> 4) << 3);
    const int b_gadd = ((lane >> 3) & 1);

    // prologue: 2 stages in flight
    load_stage(sbase + 0 * STAGE_BYTES, pA, pB,  0, tid); CP_COMMIT();
    load_stage(sbase + 1 * STAGE_BYTES, pA, pB, 64, tid); CP_COMMIT();

    int buf = 0;
    for (int ck = 0; ck < N_CHUNKS_K; ck++) {
        CP_WAIT1();                        // stage ck landed (1 still flying)
        __syncthreads();
        if (ck + 2 < N_CHUNKS_K) {
            int nb = buf + 2; if (nb >= N_STAGES) nb -= N_STAGES;
            load_stage(sbase + nb * STAGE_BYTES, pA, pB, (ck + 2) << 6, tid);
        }
        CP_COMMIT();                       // commit (possibly empty) group

        const uint32_t stg = sbase + buf * STAGE_BYTES;
        if (++buf == N_STAGES) buf = 0;

#pragma unroll
        for (int s16 = 0; s16 < 4; s16++) {
            const int g0 = (s16 << 1);
            uint32_t a[4][4], b[2][4];

            // A: 4 ldmatrix.x4 (64 rows x 16 k)
#pragma unroll
            for (int i = 0; i < 4; i++) {
                int row = a_row + (i << 4);
                int g   = g0 + a_gadd;
                uint32_t addr = stg + OFF_A + SWZ(row, g);
                LDSM_X4(a[i][0], a[i][1], a[i][2], a[i][3], addr);
            }
            // B: 2 ldmatrix.x4 (32 cols x 16 k)
#pragma unroll
            for (int j2 = 0; j2 < 2; j2++) {
                int row = b_row + (j2 << 4);
                int g   = g0 + b_gadd;
                uint32_t addr = stg + OFF_B + SWZ(row, g);
                LDSM_X4(b[j2][0], b[j2][1], b[j2][2], b[j2][3], addr);
            }
            // 16 MMAs
#pragma unroll
            for (int i = 0; i < 4; i++)
#pragma unroll
                for (int j = 0; j < 4; j++)
                    MMAF16(acc[i][j], a[i][0], a[i][1], a[i][2], a[i][3],
                           b[j >> 1][(j & 1) << 1], b[j >> 1][((j & 1) << 1) + 1]);
        }
    }

    // epilogue: bias + direct float2 stores (all cols < 1024 < N_DIM)
    const int r0 = bm + wm + (lane >> 2);
    const int c0 = bn + wn + ((lane & 3) << 1);
#pragma unroll
    for (int j = 0; j < 4; j++) {
        int col = c0 + (j << 3);
        float bx = bias[col];
        float by = bias[col + 1];
#pragma unroll
        for (int i = 0; i < 4; i++) {
            int row = r0 + (i << 4);
            *(float2*)&g_h[(size_t)row * N_DIM + col] =
                make_float2(acc[i][j][0] + bx, acc[i][j][1] + by);
            *(float2*)&g_h[(size_t)(row + 8) * N_DIM + col] =
                make_float2(acc[i][j][2] + bx, acc[i][j][3] + by);
        }
    }
}

// ---------------------------------------------------------------------------
// Kernel 2: spectrum -> 512-pt inverse FFT as 3x radix-8 register passes
// (2 smem transposes, 64 threads/frame, 4 frames/block) -> window ->
// fp16 frames (half2 stores).
// ---------------------------------------------------------------------------
__global__ void __launch_bounds__(256)
ifft_kernel()
{
    __shared__ float2 s_spec[4][513];   // packed spectrum per frame
    __shared__ float2 s_buf[4][540];    // transpose buffer per frame
    __shared__ float2 s_tw[512];        // e^{2*pi*i*j/512}

    const int tid = threadIdx.x;
    const int fid = tid >> 6;                      // frame within block
    const int t   = tid & 63;                      // thread within frame
    const int f   = (blockIdx.x << 2) + fid;       // global frame id
    const float* __restrict__ h = g_h + (size_t)f * N_DIM;

    s_tw[tid]       = g_tw[tid];
    s_tw[tid + 256] = g_tw[tid + 256];

    // spectrum: S_k = min(exp(h_k),100) * (cos p_k + i sin p_k)
    for (int k = t; k <= 512; k += 64) {
        float mag = fminf(__expf(h[k]), 100.0f);
        float s, c;
        __sincosf(h[NBINS + k], &s, &c);
        if (k == 0 || k == 512) s = 0.0f;          // irfft ignores Im of DC/Nyquist
        s_spec[fid][k] = make_float2(mag * c, mag * s);
    }
    __syncthreads();

    // ---- pass A: pack + IFFT8 over k1 (k2 = t) ----
    {
        float2 c[8];
#pragma unroll
        for (int k1 = 0; k1 < 8; k1++) {
            int k = (k1 << 6) + t;
            float2 Xk = s_spec[fid][k];
            float2 Xr = s_spec[fid][512 - k];
            float Ex = 0.5f * (Xk.x + Xr.x);
            float Ey = 0.5f * (Xk.y - Xr.y);
            float Dx = 0.5f * (Xk.x - Xr.x);
            float Dy = 0.5f * (Xk.y + Xr.y);
            float2 w = g_pretw[k];
            c[k1] = make_float2(Ex - (w.x * Dy + w.y * Dx),
                                Ey + (w.x * Dx - w.y * Dy));
        }
        float2 X[8];
        ifft8(c, X);
#pragma unroll
        for (int n1 = 1; n1 < 8; n1++) X[n1] = cmul(X[n1], s_tw[t * n1]);
        const int base = (t >> 3) * 68 + (t & 7);
#pragma unroll
        for (int n1 = 0; n1 < 8; n1++) s_buf[fid][base + (n1 << 3)] = X[n1];
    }
    __syncthreads();

    // ---- pass B: IFFT8 over j1, thread = (n1, j2) ----
    {
        const int n1 = t >> 3, j2 = t & 7;
        float2 y[8];
#pragma unroll
        for (int j1 = 0; j1 < 8; j1++) y[j1] = s_buf[fid][j1 * 68 + (n1 << 3) + j2];
        __syncthreads();                          // reads done before in-place writes
        float2 V[8];
        ifft8(y, V);
#pragma unroll
        for (int m1 = 1; m1 < 8; m1++) V[m1] = cmul(V[m1], s_tw[((j2 * m1) << 3)]);
        const int base = j2 * 66 + (n1 << 3);
#pragma unroll
        for (int m1 = 0; m1 < 8; m1++) s_buf[fid][base + m1] = V[m1];
    }
    __syncthreads();

    // ---- pass C: IFFT8 over j2; scale + window; store fp16 pairs ----
    {
        const int n1 = t >> 3, m1 = t & 7;
        float2 d[8];
#pragma unroll
        for (int j2 = 0; j2 < 8; j2++) d[j2] = s_buf[fid][j2 * 66 + (n1 << 3) + m1];
        float2 X[8];
        ifft8(d, X);
        const float inv = 1.0f / 512.0f;
        __half* __restrict__ fr = g_frames + (size_t)f * NFFT;
        const int nb = n1 + (m1 << 3);
#pragma unroll
        for (int m2 = 0; m2 < 8; m2++) {
            int n = nb + (m2 << 6);
            float2 w2 = *(const float2*)&g_win[2 * n];
            __half2 hv = __floats2half2_rn(X[m2].x * inv * w2.x,
                                           X[m2].y * inv * w2.y);
            *(__half2*)&fr[2 * n] = hv;
        }
    }
}

// ---------------------------------------------------------------------------
// Kernel 3: overlap-add, 4 outputs/thread, fp16 frame loads (uint2 = 4 halves),
// precomputed 1/env. Interior fast path: exactly 4 taps.
// ---------------------------------------------------------------------------
__device__ __forceinline__ float4 load_tap_h4(const __half* p) {
    uint2 raw = *(const uint2*)p;                 // 4 halves, 8B aligned
    __half2 h01 = *reinterpret_cast<__half2*>(&raw.x);
    __half2 h23 = *reinterpret_cast<__half2*>(&raw.y);
    float2 f01 = __half22float2(h01);
    float2 f23 = __half22float2(h23);
    return make_float4(f01.x, f01.y, f23.x, f23.y);
}

__global__ void __launch_bounds__(256)
ola_kernel(float* __restrict__ out)
{
    int g = blockIdx.x * blockDim.x + threadIdx.x;       // group id
    if (g >= (BATCH * OUT_LEN) / 4) return;
    int b   = g / (OUT_LEN / 4);
    int mo0 = (g - b * (OUT_LEN / 4)) << 2;
    int m0  = mo0 + PAD;

    int t_hi = m0 >> 8;
    if (t_hi > T_FRAMES - 1) t_hi = T_FRAMES - 1;
    int t_lo = (m0 >= (NFFT - HOP)) ? ((m0 - (NFFT - HOP)) >> 8) : 0;

    float4 acc = make_float4(0.0f, 0.0f, 0.0f, 0.0f);
    const __half* __restrict__ base = g_frames + (size_t)b * T_FRAMES * NFFT;
    if (t_hi - t_lo == 3) {
#pragma unroll
        for (int d = 0; d < 4; d++) {
            int t = t_lo + d;
            float4 v = load_tap_h4(base + (size_t)t * NFFT + (m0 - (t << 8)));
            acc.x += v.x; acc.y += v.y; acc.z += v.z; acc.w += v.w;
        }
    } else {
        for (int t = t_lo; t <= t_hi; t++) {
            float4 v = load_tap_h4(base + (size_t)t * NFFT + (m0 - (t << 8)));
            acc.x += v.x; acc.y += v.y; acc.z += v.z; acc.w += v.w;
        }
    }
    float4 e = *(const float4*)&g_env_inv[m0];
    *(float4*)&out[(size_t)b * OUT_LEN + mo0] =
        make_float4(acc.x * e.x, acc.y * e.y, acc.z * e.z, acc.w * e.w);
}

// ---------------------------------------------------------------------------
// Launch
// ---------------------------------------------------------------------------
extern "C" void kernel_launch(void* const* d_in, const int* in_sizes, int n_in,
                              void* d_out, int out_size)
{
    const float* x    = (const float*)d_in[0];   // [8, 2048, 512]
    const float* W    = (const float*)d_in[1];   // [512, 1026]
    const float* bias = (const float*)d_in[2];   // [1026]
    float* out = (float*)d_out;                  // [8, 524544]

    cudaFuncSetAttribute(gemm_mma_kernel,
                         cudaFuncAttributeMaxDynamicSharedMemorySize,
                         GEMM_SMEM);

    // 0) prep: W -> fp16 W^T + tail extraction
    prep_w_kernel<<<(N_MAIN * K_DIM) / 256, 256>>>(W);

    // 0b) merged: tables + window + env + tail GEMV + x->fp16
    prep_tables_env_gemv_kernel<<<OUT_FULL / 256, 256>>>(x, bias);

    // 1) single-pass FP16 tensor-core GEMM over N=1024 -> g_h  (2 CTAs/SM)
    dim3 g1(N_MAIN / 128, M_TOTAL / 128);   // (8, 128)
    gemm_mma_kernel<<<g1, 256, GEMM_SMEM>>>(bias);

    // 2) spectrum -> radix-8 register irfft -> window -> fp16 g_frames
    ifft_kernel<<<M_TOTAL / 4, 256>>>();

    // 3) overlap-add * 1/env -> out (4 outputs per thread)
    int groups = (BATCH * OUT_LEN) / 4;
    ola_kernel<<<(groups + 255) / 256, 256>>>(out);
}

// round 17
// speedup vs baseline: 2.0559x; 1.1293x over previous
#include <cuda_runtime.h>
#include <cuda_bf16.h>
#include <cuda_fp16.h>
#include <math.h>
#include <stdint.h>

// ---------------------------------------------------------------------------
// Problem constants
// ---------------------------------------------------------------------------
#define BATCH      8
#define T_FRAMES   2048
#define M_TOTAL    (BATCH * T_FRAMES)   // 16384 frames
#define K_DIM      512
#define N_DIM      1026                 // N_FFT + 2
#define N_MAIN     1024                 // 8 x 128 tiles via tensor cores
#define NBINS      513                  // N_FFT/2 + 1
#define NFFT       1024
#define HOP        256
#define PAD        384                  // (1024-256)/2
#define OUT_FULL   ((T_FRAMES - 1) * HOP + NFFT)  // 525312
#define OUT_LEN    (OUT_FULL - 2 * PAD)           // 524544

// ---------------------------------------------------------------------------
// Scratch (device globals: no runtime allocation allowed)
// ---------------------------------------------------------------------------
__device__ __half g_h[(size_t)M_TOTAL * N_DIM];       // linear head output, fp16 (~34 MB)
__device__ __half g_frames[(size_t)M_TOTAL * NFFT];   // windowed frames, fp16 (~34 MB)
__device__ __half g_xh[(size_t)M_TOTAL * K_DIM];      // x in fp16 (17 MB)
__device__ __half g_wth[(size_t)N_MAIN * K_DIM];      // W^T in fp16 (1 MB)
__device__ float  g_wtail[2 * K_DIM];   // fp32 W columns 1024,1025 (transposed)
// precomputed tables
__device__ float2 g_tw[512];        // e^{+2*pi*i*j/512},  j<512
__device__ float2 g_pretw[512];     // e^{+2*pi*i*k/1024}, k<512  (packing twiddles)
__device__ float  g_win[NFFT];      // hann window
__device__ float  g_env_inv[OUT_FULL];  // 1 / sum win^2

// ---------------------------------------------------------------------------
// baseline-arch PTX helpers (supported on compute_103 WITHOUT 'a')
// ---------------------------------------------------------------------------
__device__ __forceinline__ uint32_t smem_u32(const void* p) {
    return (uint32_t)__cvta_generic_to_shared(p);
}

__device__ __forceinline__ void cp_async16(uint32_t saddr, const void* gptr) {
    asm volatile("cp.async.cg.shared.global [%0], [%1], 16;"
                 :: "r"(saddr), "l"(gptr));
}
#define CP_COMMIT() asm volatile("cp.async.commit_group;" ::: "memory")
#define CP_WAIT1()  asm volatile("cp.async.wait_group 1;" ::: "memory")

#define LDSM_X4(r0, r1, r2, r3, addr) \
    asm volatile("ldmatrix.sync.aligned.m8n8.x4.shared.b16 {%0,%1,%2,%3}, [%4];" \
                 : "=r"(r0), "=r"(r1), "=r"(r2), "=r"(r3) : "r"(addr))

#define MMAF16(c, a0, a1, a2, a3, b0, b1) \
    asm volatile("mma.sync.aligned.m16n8k16.row.col.f32.f16.f16.f32 " \
                 "{%0,%1,%2,%3}, {%4,%5,%6,%7}, {%8,%9}, {%0,%1,%2,%3};" \
                 : "+f"((c)[0]), "+f"((c)[1]), "+f"((c)[2]), "+f"((c)[3]) \
                 : "r"(a0), "r"(a1), "r"(a2), "r"(a3), "r"(b0), "r"(b1))

// ---------------------------------------------------------------------------
// complex helpers
// ---------------------------------------------------------------------------
__device__ __forceinline__ float2 cadd(float2 a, float2 b) { return make_float2(a.x + b.x, a.y + b.y); }
__device__ __forceinline__ float2 csub(float2 a, float2 b) { return make_float2(a.x - b.x, a.y - b.y); }
__device__ __forceinline__ float2 cmul(float2 a, float2 b) {
    return make_float2(a.x * b.x - a.y * b.y, a.x * b.y + a.y * b.x);
}
__device__ __forceinline__ float2 cmuli(float2 a) { return make_float2(-a.y, a.x); }  // * i

// inverse 8-point DFT: X[m] = sum_k c[k] e^{+2*pi*i*k*m/8}
__device__ __forceinline__ void ifft8(const float2 c[8], float2 X[8]) {
    const float r = 0.70710678118654752f;
    float2 t0 = cadd(c[0], c[4]), t1 = csub(c[0], c[4]);
    float2 t2 = cadd(c[2], c[6]), t3 = cmuli(csub(c[2], c[6]));
    float2 E0 = cadd(t0, t2), E1 = cadd(t1, t3), E2 = csub(t0, t2), E3 = csub(t1, t3);
    float2 u0 = cadd(c[1], c[5]), u1 = csub(c[1], c[5]);
    float2 u2 = cadd(c[3], c[7]), u3 = cmuli(csub(c[3], c[7]));
    float2 O0 = cadd(u0, u2), O1 = cadd(u1, u3), O2 = csub(u0, u2), O3 = csub(u1, u3);
    float2 W1 = make_float2(r * (O1.x - O1.y), r * (O1.x + O1.y));
    float2 W2 = cmuli(O2);
    float2 W3 = make_float2(-r * (O3.x + O3.y), r * (O3.x - O3.y));
    X[0] = cadd(E0, O0); X[4] = csub(E0, O0);
    X[1] = cadd(E1, W1); X[5] = csub(E1, W1);
    X[2] = cadd(E2, W2); X[6] = csub(E2, W2);
    X[3] = cadd(E3, W3); X[7] = csub(E3, W3);
}

// ---------------------------------------------------------------------------
// Prep 1: W [K, 1026] -> g_wth [1024][512] fp16 (transposed) + fp32 tail cols
// ---------------------------------------------------------------------------
__global__ void __launch_bounds__(256)
prep_w_kernel(const float* __restrict__ W)
{
    int idx = blockIdx.x * 256 + threadIdx.x;       // over N_MAIN * K_DIM
    int n = idx >> 9;          // 0..1023
    int k = idx & 511;
    g_wth[idx] = __float2half_rn(W[(size_t)k * N_DIM + n]);
    // tail columns: block 0 extracts W[:,1024:1026] transposed, fp32
    if (blockIdx.x == 0) {
        int tid = threadIdx.x;
        for (int i = tid; i < 2 * K_DIM; i += 256) {
            int j  = i >> 9;           // 0/1
            int kk = i & 511;
            g_wtail[i] = W[(size_t)kk * N_DIM + 1024 + j];
        }
    }
}

// ---------------------------------------------------------------------------
// Prep 2 (MERGED): trig tables + window + envelope reciprocal + tail GEMV
// + x -> fp16 conversion (x is streamed anyway for the GEMV).
// Grid = 2052 blocks x 256 (2052*256 == OUT_FULL exactly).
// ---------------------------------------------------------------------------
__global__ void __launch_bounds__(256)
prep_tables_env_gemv_kernel(const float* __restrict__ x,
                            const float* __restrict__ bias)
{
    __shared__ float w0[K_DIM], w1[K_DIM];
    const int tid  = threadIdx.x;
    const int bid  = blockIdx.x;
    const int i    = bid * 256 + tid;
    const bool do_gemv = (bid < M_TOTAL / 8);

    // ---- stage tail weights (only blocks that run the GEMV) ----
    if (do_gemv) {
        for (int t = tid; t < K_DIM; t += 256) {
            w0[t] = g_wtail[t];
            w1[t] = g_wtail[K_DIM + t];
        }
        __syncthreads();
    }

    // ---- tables (first 1024 threads globally) ----
    float s, c;
    if (i < 512) {                               // e^{2*pi*i*j/512}
        sincospif((float)i * (1.0f / 256.0f), &s, &c);
        g_tw[i] = make_float2(c, s);
        sincospif((float)i * (1.0f / 512.0f), &s, &c);   // e^{2*pi*i*k/1024}
        g_pretw[i] = make_float2(c, s);
    }
    if (i < NFFT) {
        g_win[i] = 0.5f * (1.0f - cospif((float)i * (1.0f / 512.0f)));
    }

    // ---- tail GEMV + fp16 conversion: one warp per row, 8 rows per block ----
    if (do_gemv) {
        const int warp = tid >> 5;
        const int lane = tid & 31;
        const int m = (bid << 3) + warp;
        const float* __restrict__ xr = x + (size_t)m * K_DIM;
        __half* __restrict__ xh = g_xh + (size_t)m * K_DIM;
        float a0 = 0.0f, a1 = 0.0f;
#pragma unroll
        for (int p = 0; p < 4; p++) {
            int k = (p << 7) + (lane << 2);
            float4 v = *(const float4*)&xr[k];
            a0 += v.x * w0[k] + v.y * w0[k + 1] + v.z * w0[k + 2] + v.w * w0[k + 3];
            a1 += v.x * w1[k] + v.y * w1[k + 1] + v.z * w1[k + 2] + v.w * w1[k + 3];
            // emit fp16 copy (4 halves = 8B, coalesced)
            __half2 h01 = __floats2half2_rn(v.x, v.y);
            __half2 h23 = __floats2half2_rn(v.z, v.w);
            uint2 pk;
            pk.x = *reinterpret_cast<uint32_t*>(&h01);
            pk.y = *reinterpret_cast<uint32_t*>(&h23);
            *(uint2*)&xh[k] = pk;
        }
#pragma unroll
        for (int off = 16; off > 0; off >>= 1) {
            a0 += __shfl_down_sync(0xFFFFFFFFu, a0, off);
            a1 += __shfl_down_sync(0xFFFFFFFFu, a1, off);
        }
        if (lane == 0) {
            // cols 1024,1025 form a 4B-aligned half2 pair
            __half2 hv = __floats2half2_rn(a0 + bias[1024], a1 + bias[1025]);
            *(__half2*)&g_h[(size_t)m * N_DIM + 1024] = hv;
        }
    }

    // ---- envelope reciprocal (i covers exactly OUT_FULL) ----
    {
        int m = i;
        int t_hi = m >> 8;
        if (t_hi > T_FRAMES - 1) t_hi = T_FRAMES - 1;
        int t_lo = (m >= (NFFT - HOP)) ? ((m - (NFFT - HOP)) >> 8) : 0;
        float env = 0.0f;
        for (int t = t_lo; t <= t_hi; t++) {
            int n = m - (t << 8);
            float win = 0.5f * (1.0f - cospif((float)n * (1.0f / 512.0f)));
            env += win * win;
        }
        g_env_inv[m] = (env > 0.0f) ? (1.0f / env) : 0.0f;
    }
}

// ---------------------------------------------------------------------------
// Kernel 1: single-pass FP16 GEMM  h[:, :1024] = x @ W[:, :1024] + b.
// mma.sync.m16n8k16.f32.f16.f16.f32. CTA tile 128x128, BK=64 (128B rows,
// SW128 swizzle), 3-stage cp.async, 8 warps (64x32), 2 CTAs/SM.
// Epilogue stores fp16 h (half2 per column pair).
// ---------------------------------------------------------------------------
#define MAT_BYTES   16384                 // 128 rows x 128 B (64 fp16)
#define STAGE_BYTES (2 * MAT_BYTES)       // 32768 (A, B)
#define N_STAGES    3
#define GEMM_SMEM   (N_STAGES * STAGE_BYTES)   // 98304
#define N_CHUNKS_K  (K_DIM / 64)          // 8
#define OFF_A 0
#define OFF_B MAT_BYTES

// byte offset of (row, 16B-granule g in 0..7) within a 128B-row tile
#define SWZ(row, g) (((row) << 7) + ((((g) ^ ((row) & 7))) << 4))

__device__ __forceinline__ void load_stage(uint32_t sdst,
                                           const __half* pA, const __half* pB,
                                           int k0, int tid)
{
    // each matrix: 128 rows x 8 granules = 1024 transfers (4 iters of 256)
#pragma unroll
    for (int t = 0; t < 4; t++) {
        int idx = tid + (t << 8);
        int row = idx >> 3;
        int g   = idx & 7;
        uint32_t soff = SWZ(row, g);
        size_t goff = (size_t)row * K_DIM + k0 + (g << 3);
        cp_async16(sdst + OFF_A + soff, pA + goff);
        cp_async16(sdst + OFF_B + soff, pB + goff);
    }
}

__global__ void __launch_bounds__(256, 2)
gemm_mma_kernel(const float* __restrict__ bias)
{
    extern __shared__ __align__(128) char smem[];
    const int tid  = threadIdx.x;
    const int lane = tid & 31;
    const int warp = tid >> 5;
    const int wm   = (warp >> 2) << 6;   // 0 / 64
    const int wn   = (warp & 3) << 5;    // 0,32,64,96
    const int bm   = blockIdx.y << 7;    // 128-row tiles
    const int bn   = blockIdx.x << 7;    // 128-col tiles
    const uint32_t sbase = smem_u32(smem);

    const __half* pA = g_xh  + (size_t)bm * K_DIM;
    const __half* pB = g_wth + (size_t)bn * K_DIM;

    float acc[4][4][4];
#pragma unroll
    for (int i = 0; i < 4; i++)
#pragma unroll
        for (int j = 0; j < 4; j++)
#pragma unroll
            for (int r = 0; r < 4; r++) acc[i][j][r] = 0.0f;

    const int a_row  = wm + (lane & 15);
    const int a_gadd = (lane >> 4);          // 0/1
    const int b_row  = wn + (lane & 7) + ((lane >> 4) << 3);
    const int b_gadd = ((lane >> 3) & 1);

    // prologue: 2 stages in flight
    load_stage(sbase + 0 * STAGE_BYTES, pA, pB,  0, tid); CP_COMMIT();
    load_stage(sbase + 1 * STAGE_BYTES, pA, pB, 64, tid); CP_COMMIT();

    int buf = 0;
    for (int ck = 0; ck < N_CHUNKS_K; ck++) {
        CP_WAIT1();                        // stage ck landed (1 still flying)
        __syncthreads();
        if (ck + 2 < N_CHUNKS_K) {
            int nb = buf + 2; if (nb >= N_STAGES) nb -= N_STAGES;
            load_stage(sbase + nb * STAGE_BYTES, pA, pB, (ck + 2) << 6, tid);
        }
        CP_COMMIT();                       // commit (possibly empty) group

        const uint32_t stg = sbase + buf * STAGE_BYTES;
        if (++buf == N_STAGES) buf = 0;

#pragma unroll
        for (int s16 = 0; s16 < 4; s16++) {
            const int g0 = (s16 << 1);
            uint32_t a[4][4], b[2][4];

            // A: 4 ldmatrix.x4 (64 rows x 16 k)
#pragma unroll
            for (int i = 0; i < 4; i++) {
                int row = a_row + (i << 4);
                int g   = g0 + a_gadd;
                uint32_t addr = stg + OFF_A + SWZ(row, g);
                LDSM_X4(a[i][0], a[i][1], a[i][2], a[i][3], addr);
            }
            // B: 2 ldmatrix.x4 (32 cols x 16 k)
#pragma unroll
            for (int j2 = 0; j2 < 2; j2++) {
                int row = b_row + (j2 << 4);
                int g   = g0 + b_gadd;
                uint32_t addr = stg + OFF_B + SWZ(row, g);
                LDSM_X4(b[j2][0], b[j2][1], b[j2][2], b[j2][3], addr);
            }
            // 16 MMAs
#pragma unroll
            for (int i = 0; i < 4; i++)
#pragma unroll
                for (int j = 0; j < 4; j++)
                    MMAF16(acc[i][j], a[i][0], a[i][1], a[i][2], a[i][3],
                           b[j >> 1][(j & 1) << 1], b[j >> 1][((j & 1) << 1) + 1]);
        }
    }

    // epilogue: bias + fp16 half2 stores (all cols < 1024 < N_DIM)
    const int r0 = bm + wm + (lane >> 2);
    const int c0 = bn + wn + ((lane & 3) << 1);
#pragma unroll
    for (int j = 0; j < 4; j++) {
        int col = c0 + (j << 3);
        float bx = bias[col];
        float by = bias[col + 1];
#pragma unroll
        for (int i = 0; i < 4; i++) {
            int row = r0 + (i << 4);
            __half2 h0 = __floats2half2_rn(acc[i][j][0] + bx, acc[i][j][1] + by);
            __half2 h1 = __floats2half2_rn(acc[i][j][2] + bx, acc[i][j][3] + by);
            *(__half2*)&g_h[(size_t)row * N_DIM + col] = h0;
            *(__half2*)&g_h[(size_t)(row + 8) * N_DIM + col] = h1;
        }
    }
}

// ---------------------------------------------------------------------------
// Kernel 2: fp16 spectrum -> 512-pt inverse FFT as 3x radix-8 register passes
// (2 smem transposes, 64 threads/frame, 4 frames/block) -> window ->
// fp16 frames (half2 stores).
// ---------------------------------------------------------------------------
__global__ void __launch_bounds__(256)
ifft_kernel()
{
    __shared__ float2 s_spec[4][513];   // packed spectrum per frame
    __shared__ float2 s_buf[4][540];    // transpose buffer per frame
    __shared__ float2 s_tw[512];        // e^{2*pi*i*j/512}

    const int tid = threadIdx.x;
    const int fid = tid >> 6;                      // frame within block
    const int t   = tid & 63;                      // thread within frame
    const int f   = (blockIdx.x << 2) + fid;       // global frame id
    const __half* __restrict__ h = g_h + (size_t)f * N_DIM;

    s_tw[tid]       = g_tw[tid];
    s_tw[tid + 256] = g_tw[tid + 256];

    // spectrum: S_k = min(exp(h_k),100) * (cos p_k + i sin p_k)
    for (int k = t; k <= 512; k += 64) {
        float mag = fminf(__expf(__half2float(h[k])), 100.0f);
        float s, c;
        __sincosf(__half2float(h[NBINS + k]), &s, &c);
        if (k == 0 || k == 512) s = 0.0f;          // irfft ignores Im of DC/Nyquist
        s_spec[fid][k] = make_float2(mag * c, mag * s);
    }
    __syncthreads();

    // ---- pass A: pack + IFFT8 over k1 (k2 = t) ----
    {
        float2 c[8];
#pragma unroll
        for (int k1 = 0; k1 < 8; k1++) {
            int k = (k1 << 6) + t;
            float2 Xk = s_spec[fid][k];
            float2 Xr = s_spec[fid][512 - k];
            float Ex = 0.5f * (Xk.x + Xr.x);
            float Ey = 0.5f * (Xk.y - Xr.y);
            float Dx = 0.5f * (Xk.x - Xr.x);
            float Dy = 0.5f * (Xk.y + Xr.y);
            float2 w = g_pretw[k];
            c[k1] = make_float2(Ex - (w.x * Dy + w.y * Dx),
                                Ey + (w.x * Dx - w.y * Dy));
        }
        float2 X[8];
        ifft8(c, X);
#pragma unroll
        for (int n1 = 1; n1 < 8; n1++) X[n1] = cmul(X[n1], s_tw[t * n1]);
        const int base = (t >> 3) * 68 + (t & 7);
#pragma unroll
        for (int n1 = 0; n1 < 8; n1++) s_buf[fid][base + (n1 << 3)] = X[n1];
    }
    __syncthreads();

    // ---- pass B: IFFT8 over j1, thread = (n1, j2) ----
    {
        const int n1 = t >> 3, j2 = t & 7;
        float2 y[8];
#pragma unroll
        for (int j1 = 0; j1 < 8; j1++) y[j1] = s_buf[fid][j1 * 68 + (n1 << 3) + j2];
        __syncthreads();                          // reads done before in-place writes
        float2 V[8];
        ifft8(y, V);
#pragma unroll
        for (int m1 = 1; m1 < 8; m1++) V[m1] = cmul(V[m1], s_tw[((j2 * m1) << 3)]);
        const int base = j2 * 66 + (n1 << 3);
#pragma unroll
        for (int m1 = 0; m1 < 8; m1++) s_buf[fid][base + m1] = V[m1];
    }
    __syncthreads();

    // ---- pass C: IFFT8 over j2; scale + window; store fp16 pairs ----
    {
        const int n1 = t >> 3, m1 = t & 7;
        float2 d[8];
#pragma unroll
        for (int j2 = 0; j2 < 8; j2++) d[j2] = s_buf[fid][j2 * 66 + (n1 << 3) + m1];
        float2 X[8];
        ifft8(d, X);
        const float inv = 1.0f / 512.0f;
        __half* __restrict__ fr = g_frames + (size_t)f * NFFT;
        const int nb = n1 + (m1 << 3);
#pragma unroll
        for (int m2 = 0; m2 < 8; m2++) {
            int n = nb + (m2 << 6);
            float2 w2 = *(const float2*)&g_win[2 * n];
            __half2 hv = __floats2half2_rn(X[m2].x * inv * w2.x,
                                           X[m2].y * inv * w2.y);
            *(__half2*)&fr[2 * n] = hv;
        }
    }
}

// ---------------------------------------------------------------------------
// Kernel 3: overlap-add, 4 outputs/thread, fp16 frame loads (uint2 = 4 halves),
// precomputed 1/env. Interior fast path: exactly 4 taps.
// ---------------------------------------------------------------------------
__device__ __forceinline__ float4 load_tap_h4(const __half* p) {
    uint2 raw = *(const uint2*)p;                 // 4 halves, 8B aligned
    __half2 h01 = *reinterpret_cast<__half2*>(&raw.x);
    __half2 h23 = *reinterpret_cast<__half2*>(&raw.y);
    float2 f01 = __half22float2(h01);
    float2 f23 = __half22float2(h23);
    return make_float4(f01.x, f01.y, f23.x, f23.y);
}

__global__ void __launch_bounds__(256)
ola_kernel(float* __restrict__ out)
{
    int g = blockIdx.x * blockDim.x + threadIdx.x;       // group id
    if (g >= (BATCH * OUT_LEN) / 4) return;
    int b   = g / (OUT_LEN / 4);
    int mo0 = (g - b * (OUT_LEN / 4)) << 2;
    int m0  = mo0 + PAD;

    int t_hi = m0 >> 8;
    if (t_hi > T_FRAMES - 1) t_hi = T_FRAMES - 1;
    int t_lo = (m0 >= (NFFT - HOP)) ? ((m0 - (NFFT - HOP)) >> 8) : 0;

    float4 acc = make_float4(0.0f, 0.0f, 0.0f, 0.0f);
    const __half* __restrict__ base = g_frames + (size_t)b * T_FRAMES * NFFT;
    if (t_hi - t_lo == 3) {
#pragma unroll
        for (int d = 0; d < 4; d++) {
            int t = t_lo + d;
            float4 v = load_tap_h4(base + (size_t)t * NFFT + (m0 - (t << 8)));
            acc.x += v.x; acc.y += v.y; acc.z += v.z; acc.w += v.w;
        }
    } else {
        for (int t = t_lo; t <= t_hi; t++) {
            float4 v = load_tap_h4(base + (size_t)t * NFFT + (m0 - (t << 8)));
            acc.x += v.x; acc.y += v.y; acc.z += v.z; acc.w += v.w;
        }
    }
    float4 e = *(const float4*)&g_env_inv[m0];
    *(float4*)&out[(size_t)b * OUT_LEN + mo0] =
        make_float4(acc.x * e.x, acc.y * e.y, acc.z * e.z, acc.w * e.w);
}

// ---------------------------------------------------------------------------
// Launch
// ---------------------------------------------------------------------------
extern "C" void kernel_launch(void* const* d_in, const int* in_sizes, int n_in,
                              void* d_out, int out_size)
{
    const float* x    = (const float*)d_in[0];   // [8, 2048, 512]
    const float* W    = (const float*)d_in[1];   // [512, 1026]
    const float* bias = (const float*)d_in[2];   // [1026]
    float* out = (float*)d_out;                  // [8, 524544]

    cudaFuncSetAttribute(gemm_mma_kernel,
                         cudaFuncAttributeMaxDynamicSharedMemorySize,
                         GEMM_SMEM);

    // 0) prep: W -> fp16 W^T + tail extraction
    prep_w_kernel<<<(N_MAIN * K_DIM) / 256, 256>>>(W);

    // 0b) merged: tables + window + env + tail GEMV + x->fp16
    prep_tables_env_gemv_kernel<<<OUT_FULL / 256, 256>>>(x, bias);

    // 1) single-pass FP16 tensor-core GEMM over N=1024 -> fp16 g_h  (2 CTAs/SM)
    dim3 g1(N_MAIN / 128, M_TOTAL / 128);   // (8, 128)
    gemm_mma_kernel<<<g1, 256, GEMM_SMEM>>>(bias);

    // 2) fp16 spectrum -> radix-8 register irfft -> window -> fp16 g_frames
    ifft_kernel<<<M_TOTAL / 4, 256>>>();

    // 3) overlap-add * 1/env -> out (4 outputs per thread)
    int groups = (BATCH * OUT_LEN) / 4;
    ola_kernel<<<(groups + 255) / 256, 256>>>(out);
}